// round 5
// baseline (speedup 1.0000x reference)
#include <cuda_runtime.h>
#include <math.h>

// ---------------------------------------------------------------------------
// G_OracleAD: enc-LSTM(+attn pool) -> spatial attention -> dec-LSTM(+readouts)
// B=32 N=64 L=128 H=128  BN=2048  4H=512
// d_out layout (fp32): recon[2048*128] | pred[2048] | c_star[2048*128] | A[32*64*64]
// R5: fma.rn.f32x2 packed FMA in LSTM mainloops; encoder 2 syncs/step via
//     per-thread replicated online-softmax state.
// ---------------------------------------------------------------------------

#define BN_   2048
#define L_    128
#define H_    128
#define G4_   512          // 4*H
#define R_    16           // rows per CTA
#define NCTA_ (BN_ / R_)   // 128
#define THR_  512

typedef unsigned long long u64_t;

// device scratch (no allocation allowed)
__device__ float4 g_encWhhP[32 * G4_];   // packed transposed enc_W_hh
__device__ float4 g_decWhhP[32 * G4_];
__device__ float4 g_decWihP[32 * G4_];
__device__ float  g_c[BN_ * H_];         // pooled encoder context
__device__ float  g_cstar[BN_ * H_];     // spatial-attention output

__device__ __forceinline__ float sig_(float x) {
    return __fdividef(1.f, 1.f + __expf(-x));
}
__device__ __forceinline__ float tanh_(float x) {
    return 1.f - __fdividef(2.f, __expf(2.f * x) + 1.f);
}
__device__ __forceinline__ float warp_sum(float v) {
    #pragma unroll
    for (int o = 16; o; o >>= 1) v += __shfl_xor_sync(0xffffffffu, v, o);
    return v;
}

// ---- packed fp32x2 helpers (Blackwell FFMA2) ----
__device__ __forceinline__ u64_t ffma2_(u64_t a, u64_t b, u64_t c) {
    u64_t d;
    asm("fma.rn.f32x2 %0, %1, %2, %3;" : "=l"(d) : "l"(a), "l"(b), "l"(c));
    return d;
}
__device__ __forceinline__ u64_t packf2_(float lo, float hi) {
    u64_t d;
    asm("mov.b64 %0, {%1, %2};" : "=l"(d) : "f"(lo), "f"(hi));
    return d;
}
__device__ __forceinline__ float sumf2_(u64_t v) {
    float x, y;
    asm("mov.b64 {%0, %1}, %2;" : "=f"(x), "=f"(y) : "l"(v));
    return x + y;
}
union F4U2_ { float4 f4; ulonglong2 u2; };

// pack W[512,128] row-major -> P[kb*512 + t] = float4(W[t][4kb..4kb+3])
__global__ void pack_kernel(const float* __restrict__ encWhh,
                            const float* __restrict__ decWhh,
                            const float* __restrict__ decWih) {
    int idx = blockIdx.x * blockDim.x + threadIdx.x;
    if (idx >= 32 * G4_) return;
    int kb = idx >> 9;
    int t  = idx & 511;
    int s  = t * 128 + kb * 4;
    g_encWhhP[idx] = make_float4(encWhh[s], encWhh[s+1], encWhh[s+2], encWhh[s+3]);
    g_decWhhP[idx] = make_float4(decWhh[s], decWhh[s+1], decWhh[s+2], decWhh[s+3]);
    g_decWihP[idx] = make_float4(decWih[s], decWih[s+1], decWih[s+2], decWih[s+3]);
}

// ---------------------------------------------------------------------------
// Encoder: univariate LSTM over L steps + fused online-softmax attention pool
// smem: gsm[16*512] | hs[16*128] | xs[16*128] | red[64]
// 2 syncs/step: (m,z,accj) softmax state replicated per-thread.
// ---------------------------------------------------------------------------
#define ENC_SMEM ((8192 + 2048 + 2048 + 64) * 4)

__global__ __launch_bounds__(THR_, 1)
void encoder_kernel(const float* __restrict__ x,
                    const float* __restrict__ enc_Wih,
                    const float* __restrict__ enc_bih,
                    const float* __restrict__ enc_bhh,
                    const float* __restrict__ pool_w,
                    const float* __restrict__ pool_b) {
    extern __shared__ float sm[];
    float* gsm = sm;                    // [R][512]
    float* hs  = sm + 8192;             // [R][128]
    float* xs  = hs + 2048;             // [R][128]
    float* red = xs + 2048;             // [R][4]

    const int tid = threadIdx.x;
    const int rowbase = blockIdx.x * R_;

    for (int i = tid; i < R_ * 128; i += THR_) {
        xs[i] = x[rowbase * 128 + i];
        hs[i] = 0.f;
    }

    // gate-thread constants (thread == gate-row t)
    const float bt  = enc_bih[tid] + enc_bhh[tid];
    const float wih = enc_Wih[tid];
    const float pb  = pool_b[0];

    // elementwise-thread mapping
    const int j  = tid & 127;
    const int rb = tid >> 7;            // 0..3
    const float pwj = pool_w[j];
    float cst[4]  = {0.f, 0.f, 0.f, 0.f};
    float accj[4] = {0.f, 0.f, 0.f, 0.f};
    float msx[4]  = {-INFINITY, -INFINITY, -INFINITY, -INFINITY};
    float zsx[4]  = {0.f, 0.f, 0.f, 0.f};

    __syncthreads();

    for (int l = 0; l < L_; l++) {
        // ---- phase 1: gate pre-activations (thread = gate-row), FFMA2 ----
        u64_t accP[R_];
        #pragma unroll
        for (int r = 0; r < R_; r++)
            accP[r] = packf2_(fmaf(xs[r * 128 + l], wih, bt), 0.f);
        #pragma unroll 2
        for (int kb = 0; kb < 32; kb++) {
            F4U2_ w; w.f4 = g_encWhhP[kb * G4_ + tid];
            #pragma unroll
            for (int r = 0; r < R_; r++) {
                F4U2_ h; h.f4 = *reinterpret_cast<const float4*>(&hs[r * 128 + kb * 4]);
                accP[r] = ffma2_(w.u2.x, h.u2.x, accP[r]);
                accP[r] = ffma2_(w.u2.y, h.u2.y, accP[r]);
            }
        }
        #pragma unroll
        for (int r = 0; r < R_; r++) gsm[r * G4_ + tid] = sumf2_(accP[r]);
        __syncthreads();

        // ---- phase 2: elementwise LSTM cell + pool partial sums ----
        float hval[4];
        #pragma unroll
        for (int p = 0; p < 4; p++) {
            int r = p * 4 + rb;
            float gi = gsm[r * G4_ + j];
            float gf = gsm[r * G4_ + 128 + j];
            float gg = gsm[r * G4_ + 256 + j];
            float go = gsm[r * G4_ + 384 + j];
            float si = sig_(gi), sf = sig_(gf), so = sig_(go);
            float tg = tanh_(gg);
            cst[p] = fmaf(sf, cst[p], si * tg);
            float h = so * tanh_(cst[p]);
            hval[p] = h;
            hs[r * 128 + j] = h;
            float contrib = warp_sum(h * pwj);
            if ((tid & 31) == 0) red[r * 4 + ((tid >> 5) & 3)] = contrib;
        }
        __syncthreads();

        // ---- phase 3: replicated online-softmax update (no extra sync) ----
        #pragma unroll
        for (int p = 0; p < 4; p++) {
            int r = p * 4 + rb;
            float s = red[r * 4] + red[r * 4 + 1] + red[r * 4 + 2] + red[r * 4 + 3] + pb;
            float mn = fmaxf(msx[p], s);
            float f  = __expf(msx[p] - mn);
            float wg = __expf(s - mn);
            zsx[p]  = zsx[p] * f + wg;
            msx[p]  = mn;
            accj[p] = fmaf(accj[p], f, wg * hval[p]);
        }
        // red is rewritten only after next phase-1's __syncthreads -> safe
    }

    #pragma unroll
    for (int p = 0; p < 4; p++) {
        int r = p * 4 + rb;
        g_c[(rowbase + r) * 128 + j] = __fdividef(accj[p], zsx[p]);
    }
}

// ---------------------------------------------------------------------------
// Spatial self-attention per batch: Q/K/V proj, scores, softmax->A, c_star
// ---------------------------------------------------------------------------
#define ATT_SMEM ((8192 * 4 + 4096) * 4)

__global__ __launch_bounds__(256, 1)
void attn_kernel(const float* __restrict__ Wq, const float* __restrict__ bq,
                 const float* __restrict__ Wk, const float* __restrict__ bk,
                 const float* __restrict__ Wv, const float* __restrict__ bv,
                 float* __restrict__ out_cstar, float* __restrict__ out_A) {
    extern __shared__ float sm[];
    float* c_s = sm;            // [64][128]
    float* q_s = sm + 8192;
    float* k_s = sm + 16384;
    float* v_s = sm + 24576;
    float* sc  = sm + 32768;    // [64][64]
    const int b = blockIdx.x, tid = threadIdx.x;

    for (int i = tid; i < 8192; i += 256) c_s[i] = g_c[b * 8192 + i];
    __syncthreads();

    for (int o = tid; o < 8192; o += 256) {
        int n = o >> 7, d = o & 127;
        float aq = bq[d], ak = bk[d], av = bv[d];
        const float* cr = &c_s[n * 128];
        #pragma unroll 8
        for (int kk = 0; kk < 128; kk++) {
            float cv = cr[kk];
            aq = fmaf(cv, __ldg(&Wq[d * 128 + kk]), aq);
            ak = fmaf(cv, __ldg(&Wk[d * 128 + kk]), ak);
            av = fmaf(cv, __ldg(&Wv[d * 128 + kk]), av);
        }
        q_s[o] = aq; k_s[o] = ak; v_s[o] = av;
    }
    __syncthreads();

    const float scale = 0.08838834764831845f;   // 1/sqrt(128)
    for (int o = tid; o < 4096; o += 256) {
        int n = o >> 6, m = o & 63;
        float s = 0.f;
        #pragma unroll 8
        for (int d = 0; d < 128; d++) s = fmaf(q_s[n * 128 + d], k_s[m * 128 + d], s);
        sc[o] = s * scale;
    }
    __syncthreads();

    // softmax rows (warp per row)
    const int warp = tid >> 5, lane = tid & 31;
    for (int n = warp; n < 64; n += 8) {
        float v0 = sc[n * 64 + lane], v1 = sc[n * 64 + 32 + lane];
        float mx = fmaxf(v0, v1);
        #pragma unroll
        for (int o = 16; o; o >>= 1) mx = fmaxf(mx, __shfl_xor_sync(0xffffffffu, mx, o));
        float e0 = __expf(v0 - mx), e1 = __expf(v1 - mx);
        float ss = warp_sum(e0 + e1);
        float inv = 1.f / ss;
        float a0 = e0 * inv, a1 = e1 * inv;
        sc[n * 64 + lane] = a0;
        sc[n * 64 + 32 + lane] = a1;
        out_A[b * 4096 + n * 64 + lane] = a0;
        out_A[b * 4096 + n * 64 + 32 + lane] = a1;
    }
    __syncthreads();

    for (int o = tid; o < 8192; o += 256) {
        int n = o >> 7, d = o & 127;
        float s = 0.f;
        #pragma unroll 8
        for (int m = 0; m < 64; m++) s = fmaf(sc[n * 64 + m], v_s[m * 128 + d], s);
        out_cstar[b * 8192 + o] = s;
        g_cstar[b * 8192 + o]   = s;
    }
}

// ---------------------------------------------------------------------------
// Decoder: constant-input LSTM + fused recon/pred readouts (FFMA2 mainloop)
// smem: gsm[16*512] | hs[16*128] | cs[16*128] | red[64] | red2[64]
// ---------------------------------------------------------------------------
#define DEC_SMEM ((8192 + 2048 + 2048 + 64 + 64) * 4)

__global__ __launch_bounds__(THR_, 1)
void decoder_kernel(const float* __restrict__ dec_bih,
                    const float* __restrict__ dec_bhh,
                    const float* __restrict__ rec_w,  const float* __restrict__ rec_b,
                    const float* __restrict__ pred_w, const float* __restrict__ pred_b,
                    float* __restrict__ out_recon, float* __restrict__ out_pred) {
    extern __shared__ float sm[];
    float* gsm  = sm;                   // [R][512]
    float* hs   = sm + 8192;            // [R][128]
    float* cs   = hs + 2048;            // [R][128]
    float* red  = cs + 2048;            // [R][4]
    float* red2 = red + 64;             // [R][4]

    const int tid = threadIdx.x;
    const int rowbase = blockIdx.x * R_;

    for (int i = tid; i < R_ * 128; i += THR_) {
        cs[i] = g_cstar[rowbase * 128 + i];
        hs[i] = 0.f;
    }
    const float bt = dec_bih[tid] + dec_bhh[tid];
    const float rbv = rec_b[0], pbv = pred_b[0];

    const int j  = tid & 127;
    const int rb = tid >> 7;
    const float rwj = rec_w[j];
    const float pwj = pred_w[j];
    float cst[4] = {0.f, 0.f, 0.f, 0.f};
    __syncthreads();

    // constant input projection: dproj[r] = dec_W_ih[t,:]·c_star[row_r,:] + bt
    float dpr[R_];
    {
        u64_t dP[R_];
        #pragma unroll
        for (int r = 0; r < R_; r++) dP[r] = packf2_(bt, 0.f);
        #pragma unroll 2
        for (int kb = 0; kb < 32; kb++) {
            F4U2_ w; w.f4 = g_decWihP[kb * G4_ + tid];
            #pragma unroll
            for (int r = 0; r < R_; r++) {
                F4U2_ h; h.f4 = *reinterpret_cast<const float4*>(&cs[r * 128 + kb * 4]);
                dP[r] = ffma2_(w.u2.x, h.u2.x, dP[r]);
                dP[r] = ffma2_(w.u2.y, h.u2.y, dP[r]);
            }
        }
        #pragma unroll
        for (int r = 0; r < R_; r++) dpr[r] = sumf2_(dP[r]);
    }

    for (int l = 0; l < L_; l++) {
        // ---- phase 1: gates (FFMA2) ----
        u64_t accP[R_];
        #pragma unroll
        for (int r = 0; r < R_; r++) accP[r] = packf2_(dpr[r], 0.f);
        #pragma unroll 2
        for (int kb = 0; kb < 32; kb++) {
            F4U2_ w; w.f4 = g_decWhhP[kb * G4_ + tid];
            #pragma unroll
            for (int r = 0; r < R_; r++) {
                F4U2_ h; h.f4 = *reinterpret_cast<const float4*>(&hs[r * 128 + kb * 4]);
                accP[r] = ffma2_(w.u2.x, h.u2.x, accP[r]);
                accP[r] = ffma2_(w.u2.y, h.u2.y, accP[r]);
            }
        }
        #pragma unroll
        for (int r = 0; r < R_; r++) gsm[r * G4_ + tid] = sumf2_(accP[r]);
        __syncthreads();

        // ---- phase 2: cell + readout partials ----
        #pragma unroll
        for (int p = 0; p < 4; p++) {
            int r = p * 4 + rb;
            float gi = gsm[r * G4_ + j];
            float gf = gsm[r * G4_ + 128 + j];
            float gg = gsm[r * G4_ + 256 + j];
            float go = gsm[r * G4_ + 384 + j];
            float si = sig_(gi), sf = sig_(gf), so = sig_(go);
            float tg = tanh_(gg);
            cst[p] = fmaf(sf, cst[p], si * tg);
            float h = so * tanh_(cst[p]);
            hs[r * 128 + j] = h;
            float contrib = warp_sum(h * rwj);
            if ((tid & 31) == 0) red[r * 4 + ((tid >> 5) & 3)] = contrib;
            if (l == L_ - 1) {
                float c2 = warp_sum(h * pwj);
                if ((tid & 31) == 0) red2[r * 4 + ((tid >> 5) & 3)] = c2;
            }
        }
        __syncthreads();

        // ---- phase 3: leaders write recon (and pred on last step) ----
        if (tid < 16) {
            float s = red[tid * 4] + red[tid * 4 + 1] + red[tid * 4 + 2] + red[tid * 4 + 3] + rbv;
            out_recon[(rowbase + tid) * 128 + l] = s;
            if (l == L_ - 1) {
                float p2 = red2[tid * 4] + red2[tid * 4 + 1] + red2[tid * 4 + 2] + red2[tid * 4 + 3] + pbv;
                out_pred[rowbase + tid] = p2;
            }
        }
        // next phase-1's __syncthreads orders red reuse
    }
}

// ---------------------------------------------------------------------------
extern "C" void kernel_launch(void* const* d_in, const int* in_sizes, int n_in,
                              void* d_out, int out_size) {
    const float* x        = (const float*)d_in[0];
    const float* enc_Wih  = (const float*)d_in[1];
    const float* enc_Whh  = (const float*)d_in[2];
    const float* enc_bih  = (const float*)d_in[3];
    const float* enc_bhh  = (const float*)d_in[4];
    const float* pool_w   = (const float*)d_in[5];
    const float* pool_b   = (const float*)d_in[6];
    const float* Wq       = (const float*)d_in[7];
    const float* bq       = (const float*)d_in[8];
    const float* Wk       = (const float*)d_in[9];
    const float* bk       = (const float*)d_in[10];
    const float* Wv       = (const float*)d_in[11];
    const float* bv       = (const float*)d_in[12];
    const float* dec_Wih  = (const float*)d_in[13];
    const float* dec_Whh  = (const float*)d_in[14];
    const float* dec_bih  = (const float*)d_in[15];
    const float* dec_bhh  = (const float*)d_in[16];
    const float* rec_w    = (const float*)d_in[17];
    const float* rec_b    = (const float*)d_in[18];
    const float* pred_w   = (const float*)d_in[19];
    const float* pred_b   = (const float*)d_in[20];

    float* out = (float*)d_out;
    float* out_recon = out;                       // 2048*128
    float* out_pred  = out + 262144;              // 2048
    float* out_cstar = out + 264192;              // 2048*128
    float* out_A     = out + 526336;              // 32*64*64

    cudaFuncSetAttribute(encoder_kernel, cudaFuncAttributeMaxDynamicSharedMemorySize, ENC_SMEM);
    cudaFuncSetAttribute(decoder_kernel, cudaFuncAttributeMaxDynamicSharedMemorySize, DEC_SMEM);
    cudaFuncSetAttribute(attn_kernel,    cudaFuncAttributeMaxDynamicSharedMemorySize, ATT_SMEM);

    pack_kernel<<<64, 256>>>(enc_Whh, dec_Whh, dec_Wih);
    encoder_kernel<<<NCTA_, THR_, ENC_SMEM>>>(x, enc_Wih, enc_bih, enc_bhh, pool_w, pool_b);
    attn_kernel<<<32, 256, ATT_SMEM>>>(Wq, bq, Wk, bk, Wv, bv, out_cstar, out_A);
    decoder_kernel<<<NCTA_, THR_, DEC_SMEM>>>(dec_bih, dec_bhh, rec_w, rec_b,
                                              pred_w, pred_b, out_recon, out_pred);
}

// round 6
// speedup vs baseline: 1.4902x; 1.4902x over previous
#include <cuda_runtime.h>
#include <math.h>

// ---------------------------------------------------------------------------
// G_OracleAD: enc-LSTM(+attn pool) -> spatial attention -> dec-LSTM(+readouts)
// B=32 N=64 L=128 H=128  BN=2048  4H=512
// d_out layout (fp32): recon[2048*128] | pred[2048] | c_star[2048*128] | A[32*64*64]
// R6: coalesced/conflict-free attn (transposed W + padded kT smem);
//     scalar FFMA LSTM mainloops (FFMA2 reverted: measured neutral + alu cost).
// ---------------------------------------------------------------------------

#define BN_   2048
#define L_    128
#define H_    128
#define G4_   512          // 4*H
#define R_    16           // rows per CTA
#define NCTA_ (BN_ / R_)   // 128
#define THR_  512

// device scratch (no allocation allowed)
__device__ float4 g_encWhhP[32 * G4_];   // packed transposed enc_W_hh
__device__ float4 g_decWhhP[32 * G4_];
__device__ float4 g_decWihP[32 * G4_];
__device__ float  g_WqT[H_ * H_];        // WT[kk*128 + d] = W[d*128 + kk]
__device__ float  g_WkT[H_ * H_];
__device__ float  g_WvT[H_ * H_];
__device__ float  g_c[BN_ * H_];         // pooled encoder context
__device__ float  g_cstar[BN_ * H_];     // spatial-attention output

__device__ __forceinline__ float sig_(float x) {
    return __fdividef(1.f, 1.f + __expf(-x));
}
__device__ __forceinline__ float tanh_(float x) {
    return 1.f - __fdividef(2.f, __expf(2.f * x) + 1.f);
}
__device__ __forceinline__ float warp_sum(float v) {
    #pragma unroll
    for (int o = 16; o; o >>= 1) v += __shfl_xor_sync(0xffffffffu, v, o);
    return v;
}

// pack W[512,128] -> P[kb*512+t] float4; transpose Wq/Wk/Wv -> WT[kk*128+d]
__global__ void pack_kernel(const float* __restrict__ encWhh,
                            const float* __restrict__ decWhh,
                            const float* __restrict__ decWih,
                            const float* __restrict__ Wq,
                            const float* __restrict__ Wk,
                            const float* __restrict__ Wv) {
    int idx = blockIdx.x * blockDim.x + threadIdx.x;   // 0..16383
    if (idx < 32 * G4_) {
        int kb = idx >> 9;
        int t  = idx & 511;
        int s  = t * 128 + kb * 4;
        g_encWhhP[idx] = make_float4(encWhh[s], encWhh[s+1], encWhh[s+2], encWhh[s+3]);
        g_decWhhP[idx] = make_float4(decWhh[s], decWhh[s+1], decWhh[s+2], decWhh[s+3]);
        g_decWihP[idx] = make_float4(decWih[s], decWih[s+1], decWih[s+2], decWih[s+3]);
    }
    {   // transpose: idx -> (kk, d)
        int kk = idx >> 7;
        int d  = idx & 127;
        g_WqT[idx] = Wq[d * 128 + kk];
        g_WkT[idx] = Wk[d * 128 + kk];
        g_WvT[idx] = Wv[d * 128 + kk];
    }
}

// ---------------------------------------------------------------------------
// Encoder: univariate LSTM over L steps + fused online-softmax attention pool
// smem: gsm[16*512] | hs[16*128] | xs[16*128] | red[64]
// ---------------------------------------------------------------------------
#define ENC_SMEM ((8192 + 2048 + 2048 + 64) * 4)

__global__ __launch_bounds__(THR_, 1)
void encoder_kernel(const float* __restrict__ x,
                    const float* __restrict__ enc_Wih,
                    const float* __restrict__ enc_bih,
                    const float* __restrict__ enc_bhh,
                    const float* __restrict__ pool_w,
                    const float* __restrict__ pool_b) {
    extern __shared__ float sm[];
    float* gsm = sm;                    // [R][512]
    float* hs  = sm + 8192;             // [R][128]
    float* xs  = hs + 2048;             // [R][128]
    float* red = xs + 2048;             // [R][4]

    const int tid = threadIdx.x;
    const int rowbase = blockIdx.x * R_;

    for (int i = tid; i < R_ * 128; i += THR_) {
        xs[i] = x[rowbase * 128 + i];
        hs[i] = 0.f;
    }

    const float bt  = enc_bih[tid] + enc_bhh[tid];
    const float wih = enc_Wih[tid];
    const float pb  = pool_b[0];

    const int j  = tid & 127;
    const int rb = tid >> 7;            // 0..3
    const float pwj = pool_w[j];
    float cst[4]  = {0.f, 0.f, 0.f, 0.f};
    float accj[4] = {0.f, 0.f, 0.f, 0.f};
    float msx[4]  = {-INFINITY, -INFINITY, -INFINITY, -INFINITY};
    float zsx[4]  = {0.f, 0.f, 0.f, 0.f};

    __syncthreads();

    for (int l = 0; l < L_; l++) {
        // ---- phase 1: gate pre-activations (thread = gate-row) ----
        float acc[R_];
        #pragma unroll
        for (int r = 0; r < R_; r++) acc[r] = fmaf(xs[r * 128 + l], wih, bt);
        #pragma unroll 4
        for (int kb = 0; kb < 32; kb++) {
            float4 w = g_encWhhP[kb * G4_ + tid];
            #pragma unroll
            for (int r = 0; r < R_; r++) {
                float4 h4 = *reinterpret_cast<const float4*>(&hs[r * 128 + kb * 4]);
                acc[r] = fmaf(w.x, h4.x, acc[r]);
                acc[r] = fmaf(w.y, h4.y, acc[r]);
                acc[r] = fmaf(w.z, h4.z, acc[r]);
                acc[r] = fmaf(w.w, h4.w, acc[r]);
            }
        }
        #pragma unroll
        for (int r = 0; r < R_; r++) gsm[r * G4_ + tid] = acc[r];
        __syncthreads();

        // ---- phase 2: elementwise LSTM cell + pool partial sums ----
        #pragma unroll
        for (int p = 0; p < 4; p++) {
            int r = p * 4 + rb;
            float gi = gsm[r * G4_ + j];
            float gf = gsm[r * G4_ + 128 + j];
            float gg = gsm[r * G4_ + 256 + j];
            float go = gsm[r * G4_ + 384 + j];
            float si = sig_(gi), sf = sig_(gf), so = sig_(go);
            float tg = tanh_(gg);
            cst[p] = fmaf(sf, cst[p], si * tg);
            float h = so * tanh_(cst[p]);
            hs[r * 128 + j] = h;
            float contrib = warp_sum(h * pwj);
            if ((tid & 31) == 0) red[r * 4 + ((tid >> 5) & 3)] = contrib;
        }
        __syncthreads();

        // ---- phase 3: replicated online-softmax update (no extra sync) ----
        #pragma unroll
        for (int p = 0; p < 4; p++) {
            int r = p * 4 + rb;
            float s = red[r * 4] + red[r * 4 + 1] + red[r * 4 + 2] + red[r * 4 + 3] + pb;
            float hv = hs[r * 128 + j];
            float mn = fmaxf(msx[p], s);
            float f  = __expf(msx[p] - mn);
            float wg = __expf(s - mn);
            zsx[p]  = zsx[p] * f + wg;
            msx[p]  = mn;
            accj[p] = fmaf(accj[p], f, wg * hv);
        }
        // red rewritten only after next phase-1's __syncthreads -> safe
    }

    #pragma unroll
    for (int p = 0; p < 4; p++) {
        int r = p * 4 + rb;
        g_c[(rowbase + r) * 128 + j] = __fdividef(accj[p], zsx[p]);
    }
}

// ---------------------------------------------------------------------------
// Spatial self-attention per batch (coalesced + conflict-free):
//   Q/V in smem row-major [n][d]; K transposed padded kT[d][68] (bank-safe).
// smem floats: c_s 8192 | q_s 8192 | kT 128*68 | v_s 8192 | sc 4096
// ---------------------------------------------------------------------------
#define KTP_ 68
#define ATT_SMEM ((8192 + 8192 + 128 * KTP_ + 8192 + 4096) * 4)

__global__ __launch_bounds__(256, 1)
void attn_kernel(const float* __restrict__ bq,
                 const float* __restrict__ bk,
                 const float* __restrict__ bv,
                 float* __restrict__ out_cstar, float* __restrict__ out_A) {
    extern __shared__ float sm[];
    float* c_s = sm;                        // [64][128]
    float* q_s = c_s + 8192;                // [64][128]
    float* kT  = q_s + 8192;                // [128][68] padded
    float* v_s = kT + 128 * KTP_;           // [64][128]
    float* sc  = v_s + 8192;                // [64][64]
    const int b = blockIdx.x, tid = threadIdx.x;

    for (int i = tid; i < 8192; i += 256) c_s[i] = g_c[b * 8192 + i];
    __syncthreads();

    // ---- projections: thread handles (n, d4) -> 4 d's; WT loads coalesced ----
    const float4* WqT4 = reinterpret_cast<const float4*>(g_WqT);
    const float4* WkT4 = reinterpret_cast<const float4*>(g_WkT);
    const float4* WvT4 = reinterpret_cast<const float4*>(g_WvT);
    for (int o2 = tid; o2 < 64 * 32; o2 += 256) {
        int n = o2 >> 5, d4 = o2 & 31;
        const float* bq4 = bq + d4 * 4;
        const float* bk4 = bk + d4 * 4;
        const float* bv4 = bv + d4 * 4;
        float4 aq = make_float4(bq4[0], bq4[1], bq4[2], bq4[3]);
        float4 ak = make_float4(bk4[0], bk4[1], bk4[2], bk4[3]);
        float4 av = make_float4(bv4[0], bv4[1], bv4[2], bv4[3]);
        const float* cr = &c_s[n * 128];
        #pragma unroll 4
        for (int kk = 0; kk < 128; kk++) {
            float cv = cr[kk];
            float4 wq = WqT4[kk * 32 + d4];
            float4 wk = WkT4[kk * 32 + d4];
            float4 wv = WvT4[kk * 32 + d4];
            aq.x = fmaf(cv, wq.x, aq.x); aq.y = fmaf(cv, wq.y, aq.y);
            aq.z = fmaf(cv, wq.z, aq.z); aq.w = fmaf(cv, wq.w, aq.w);
            ak.x = fmaf(cv, wk.x, ak.x); ak.y = fmaf(cv, wk.y, ak.y);
            ak.z = fmaf(cv, wk.z, ak.z); ak.w = fmaf(cv, wk.w, ak.w);
            av.x = fmaf(cv, wv.x, av.x); av.y = fmaf(cv, wv.y, av.y);
            av.z = fmaf(cv, wv.z, av.z); av.w = fmaf(cv, wv.w, av.w);
        }
        *reinterpret_cast<float4*>(&q_s[n * 128 + d4 * 4]) = aq;
        *reinterpret_cast<float4*>(&v_s[n * 128 + d4 * 4]) = av;
        int dd = d4 * 4;
        kT[(dd + 0) * KTP_ + n] = ak.x;
        kT[(dd + 1) * KTP_ + n] = ak.y;
        kT[(dd + 2) * KTP_ + n] = ak.z;
        kT[(dd + 3) * KTP_ + n] = ak.w;
    }
    __syncthreads();

    // ---- scores: thread (n, m); q broadcast, kT[d][m] conflict-free ----
    const float scale = 0.08838834764831845f;   // 1/sqrt(128)
    for (int o = tid; o < 4096; o += 256) {
        int n = o >> 6, m = o & 63;
        float s = 0.f;
        const float* qr = &q_s[n * 128];
        #pragma unroll 8
        for (int d = 0; d < 128; d++) s = fmaf(qr[d], kT[d * KTP_ + m], s);
        sc[o] = s * scale;
    }
    __syncthreads();

    // ---- softmax rows (warp per row) ----
    const int warp = tid >> 5, lane = tid & 31;
    for (int n = warp; n < 64; n += 8) {
        float v0 = sc[n * 64 + lane], v1 = sc[n * 64 + 32 + lane];
        float mx = fmaxf(v0, v1);
        #pragma unroll
        for (int o = 16; o; o >>= 1) mx = fmaxf(mx, __shfl_xor_sync(0xffffffffu, mx, o));
        float e0 = __expf(v0 - mx), e1 = __expf(v1 - mx);
        float ss = warp_sum(e0 + e1);
        float inv = 1.f / ss;
        float a0 = e0 * inv, a1 = e1 * inv;
        sc[n * 64 + lane] = a0;
        sc[n * 64 + 32 + lane] = a1;
        out_A[b * 4096 + n * 64 + lane] = a0;
        out_A[b * 4096 + n * 64 + 32 + lane] = a1;
    }
    __syncthreads();

    // ---- c_star = A @ V: lane = d (coalesced v_s, broadcast sc) ----
    for (int o = tid; o < 8192; o += 256) {
        int n = o >> 7, d = o & 127;
        float s = 0.f;
        const float* ar = &sc[n * 64];
        #pragma unroll 8
        for (int m = 0; m < 64; m++) s = fmaf(ar[m], v_s[m * 128 + d], s);
        out_cstar[b * 8192 + o] = s;
        g_cstar[b * 8192 + o]   = s;
    }
}

// ---------------------------------------------------------------------------
// Decoder: constant-input LSTM + fused recon/pred readouts
// smem: gsm[16*512] | hs[16*128] | cs[16*128] | red[64] | red2[64]
// ---------------------------------------------------------------------------
#define DEC_SMEM ((8192 + 2048 + 2048 + 64 + 64) * 4)

__global__ __launch_bounds__(THR_, 1)
void decoder_kernel(const float* __restrict__ dec_bih,
                    const float* __restrict__ dec_bhh,
                    const float* __restrict__ rec_w,  const float* __restrict__ rec_b,
                    const float* __restrict__ pred_w, const float* __restrict__ pred_b,
                    float* __restrict__ out_recon, float* __restrict__ out_pred) {
    extern __shared__ float sm[];
    float* gsm  = sm;                   // [R][512]
    float* hs   = sm + 8192;            // [R][128]
    float* cs   = hs + 2048;            // [R][128]
    float* red  = cs + 2048;            // [R][4]
    float* red2 = red + 64;             // [R][4]

    const int tid = threadIdx.x;
    const int rowbase = blockIdx.x * R_;

    for (int i = tid; i < R_ * 128; i += THR_) {
        cs[i] = g_cstar[rowbase * 128 + i];
        hs[i] = 0.f;
    }
    const float bt = dec_bih[tid] + dec_bhh[tid];
    const float rbv = rec_b[0], pbv = pred_b[0];

    const int j  = tid & 127;
    const int rb = tid >> 7;
    const float rwj = rec_w[j];
    const float pwj = pred_w[j];
    float cst[4] = {0.f, 0.f, 0.f, 0.f};
    __syncthreads();

    // constant input projection: dproj[r] = dec_W_ih[t,:]·c_star[row_r,:] + bt
    float dpr[R_];
    #pragma unroll
    for (int r = 0; r < R_; r++) dpr[r] = bt;
    #pragma unroll 4
    for (int kb = 0; kb < 32; kb++) {
        float4 w = g_decWihP[kb * G4_ + tid];
        #pragma unroll
        for (int r = 0; r < R_; r++) {
            float4 h4 = *reinterpret_cast<const float4*>(&cs[r * 128 + kb * 4]);
            dpr[r] = fmaf(w.x, h4.x, dpr[r]);
            dpr[r] = fmaf(w.y, h4.y, dpr[r]);
            dpr[r] = fmaf(w.z, h4.z, dpr[r]);
            dpr[r] = fmaf(w.w, h4.w, dpr[r]);
        }
    }

    for (int l = 0; l < L_; l++) {
        // ---- phase 1: gates ----
        float acc[R_];
        #pragma unroll
        for (int r = 0; r < R_; r++) acc[r] = dpr[r];
        #pragma unroll 4
        for (int kb = 0; kb < 32; kb++) {
            float4 w = g_decWhhP[kb * G4_ + tid];
            #pragma unroll
            for (int r = 0; r < R_; r++) {
                float4 h4 = *reinterpret_cast<const float4*>(&hs[r * 128 + kb * 4]);
                acc[r] = fmaf(w.x, h4.x, acc[r]);
                acc[r] = fmaf(w.y, h4.y, acc[r]);
                acc[r] = fmaf(w.z, h4.z, acc[r]);
                acc[r] = fmaf(w.w, h4.w, acc[r]);
            }
        }
        #pragma unroll
        for (int r = 0; r < R_; r++) gsm[r * G4_ + tid] = acc[r];
        __syncthreads();

        // ---- phase 2: cell + readout partials ----
        #pragma unroll
        for (int p = 0; p < 4; p++) {
            int r = p * 4 + rb;
            float gi = gsm[r * G4_ + j];
            float gf = gsm[r * G4_ + 128 + j];
            float gg = gsm[r * G4_ + 256 + j];
            float go = gsm[r * G4_ + 384 + j];
            float si = sig_(gi), sf = sig_(gf), so = sig_(go);
            float tg = tanh_(gg);
            cst[p] = fmaf(sf, cst[p], si * tg);
            float h = so * tanh_(cst[p]);
            hs[r * 128 + j] = h;
            float contrib = warp_sum(h * rwj);
            if ((tid & 31) == 0) red[r * 4 + ((tid >> 5) & 3)] = contrib;
            if (l == L_ - 1) {
                float c2 = warp_sum(h * pwj);
                if ((tid & 31) == 0) red2[r * 4 + ((tid >> 5) & 3)] = c2;
            }
        }
        __syncthreads();

        // ---- phase 3: leaders write recon (and pred on last step) ----
        if (tid < 16) {
            float s = red[tid * 4] + red[tid * 4 + 1] + red[tid * 4 + 2] + red[tid * 4 + 3] + rbv;
            out_recon[(rowbase + tid) * 128 + l] = s;
            if (l == L_ - 1) {
                float p2 = red2[tid * 4] + red2[tid * 4 + 1] + red2[tid * 4 + 2] + red2[tid * 4 + 3] + pbv;
                out_pred[rowbase + tid] = p2;
            }
        }
        // next phase-1's __syncthreads orders red reuse
    }
}

// ---------------------------------------------------------------------------
extern "C" void kernel_launch(void* const* d_in, const int* in_sizes, int n_in,
                              void* d_out, int out_size) {
    const float* x        = (const float*)d_in[0];
    const float* enc_Wih  = (const float*)d_in[1];
    const float* enc_Whh  = (const float*)d_in[2];
    const float* enc_bih  = (const float*)d_in[3];
    const float* enc_bhh  = (const float*)d_in[4];
    const float* pool_w   = (const float*)d_in[5];
    const float* pool_b   = (const float*)d_in[6];
    const float* Wq       = (const float*)d_in[7];
    const float* bq       = (const float*)d_in[8];
    const float* Wk       = (const float*)d_in[9];
    const float* bk       = (const float*)d_in[10];
    const float* Wv       = (const float*)d_in[11];
    const float* bv       = (const float*)d_in[12];
    const float* dec_Wih  = (const float*)d_in[13];
    const float* dec_Whh  = (const float*)d_in[14];
    const float* dec_bih  = (const float*)d_in[15];
    const float* dec_bhh  = (const float*)d_in[16];
    const float* rec_w    = (const float*)d_in[17];
    const float* rec_b    = (const float*)d_in[18];
    const float* pred_w   = (const float*)d_in[19];
    const float* pred_b   = (const float*)d_in[20];

    float* out = (float*)d_out;
    float* out_recon = out;                       // 2048*128
    float* out_pred  = out + 262144;              // 2048
    float* out_cstar = out + 264192;              // 2048*128
    float* out_A     = out + 526336;              // 32*64*64

    cudaFuncSetAttribute(encoder_kernel, cudaFuncAttributeMaxDynamicSharedMemorySize, ENC_SMEM);
    cudaFuncSetAttribute(decoder_kernel, cudaFuncAttributeMaxDynamicSharedMemorySize, DEC_SMEM);
    cudaFuncSetAttribute(attn_kernel,    cudaFuncAttributeMaxDynamicSharedMemorySize, ATT_SMEM);

    pack_kernel<<<64, 256>>>(enc_Whh, dec_Whh, dec_Wih, Wq, Wk, Wv);
    encoder_kernel<<<NCTA_, THR_, ENC_SMEM>>>(x, enc_Wih, enc_bih, enc_bhh, pool_w, pool_b);
    attn_kernel<<<32, 256, ATT_SMEM>>>(bq, bk, bv, out_cstar, out_A);
    decoder_kernel<<<NCTA_, THR_, DEC_SMEM>>>(dec_bih, dec_bhh, rec_w, rec_b,
                                              pred_w, pred_b, out_recon, out_pred);
}

// round 7
// speedup vs baseline: 4.7154x; 3.1642x over previous
#include <cuda_runtime.h>
#include <cuda_bf16.h>
#include <math.h>

// ---------------------------------------------------------------------------
// G_OracleAD: enc-LSTM(+attn pool) -> spatial attention -> dec-LSTM(+readouts)
// B=32 N=64 L=128 H=128  BN=2048  4H=512
// d_out (fp32): recon[262144] | pred[2048] | c_star[262144] | A[131072]
// R7: LSTM recurrent GEMM on tensor cores (mma.sync m16n8k16 bf16, 3-term
//     error-free split W_hi*h_hi + W_hi*h_lo + W_lo*h_hi, f32 accum).
// ---------------------------------------------------------------------------

#define BN_   2048
#define L_    128
#define H_    128
#define G4_   512
#define R_    16
#define NCTA_ (BN_ / R_)   // 128
#define THR_  512
#define GS_   516          // padded gsm row stride (floats)

// device scratch
__device__ uint2  g_encWF_hi[16384];   // frag-order bf16x2 pairs: [(nt*8+kt)*32+lane]
__device__ uint2  g_encWF_lo[16384];
__device__ uint2  g_decWF_hi[16384];
__device__ uint2  g_decWF_lo[16384];
__device__ float4 g_decWihP[32 * G4_]; // for dpr GEMM (scalar, once)
__device__ float  g_WqT[H_ * H_];
__device__ float  g_WkT[H_ * H_];
__device__ float  g_WvT[H_ * H_];
__device__ float  g_c[BN_ * H_];
__device__ float  g_cstar[BN_ * H_];

__device__ __forceinline__ float sig_(float x) {
    return __fdividef(1.f, 1.f + __expf(-x));
}
__device__ __forceinline__ float tanh_(float x) {
    return 1.f - __fdividef(2.f, __expf(2.f * x) + 1.f);
}
__device__ __forceinline__ float warp_sum(float v) {
    #pragma unroll
    for (int o = 16; o; o >>= 1) v += __shfl_xor_sync(0xffffffffu, v, o);
    return v;
}
__device__ __forceinline__ void mma16816(float* c, unsigned a0, unsigned a1,
                                         unsigned a2, unsigned a3,
                                         unsigned b0, unsigned b1) {
    asm("mma.sync.aligned.m16n8k16.row.col.f32.bf16.bf16.f32 "
        "{%0,%1,%2,%3}, {%4,%5,%6,%7}, {%8,%9}, {%0,%1,%2,%3};"
        : "+f"(c[0]), "+f"(c[1]), "+f"(c[2]), "+f"(c[3])
        : "r"(a0), "r"(a1), "r"(a2), "r"(a3), "r"(b0), "r"(b1));
}
__device__ __forceinline__ void split_bf16(float w, unsigned short& hi, unsigned short& lo) {
    __nv_bfloat16 bh = __float2bfloat16_rn(w);
    hi = *reinterpret_cast<unsigned short*>(&bh);
    float r = w - __bfloat162float(bh);
    __nv_bfloat16 bl = __float2bfloat16_rn(r);
    lo = *reinterpret_cast<unsigned short*>(&bl);
}

// ---------------------------------------------------------------------------
// pack: fragment-order W splits for enc/dec W_hh, decWih float4, Wq/k/v^T
// frag (nt,kt,lane): n = nt*8 + lane/4 ; k0 = kt*16 + (lane&3)*2 (+8 for .y)
// value = W[n*128 + k]; u32 = bf16(k) | bf16(k+1)<<16
// ---------------------------------------------------------------------------
__global__ void pack_kernel(const float* __restrict__ encWhh,
                            const float* __restrict__ decWhh,
                            const float* __restrict__ decWih,
                            const float* __restrict__ Wq,
                            const float* __restrict__ Wk,
                            const float* __restrict__ Wv) {
    int idx = blockIdx.x * blockDim.x + threadIdx.x;   // 0..16383
    {   // decWih float4 pack
        int kb = idx >> 9, t = idx & 511;
        int s  = t * 128 + kb * 4;
        g_decWihP[idx] = make_float4(decWih[s], decWih[s+1], decWih[s+2], decWih[s+3]);
    }
    {   // fragment splits
        int nt = idx >> 8, kt = (idx >> 5) & 7, l = idx & 31;
        int n  = nt * 8 + (l >> 2);
        int k0 = kt * 16 + (l & 3) * 2;
        unsigned short h0, l0, h1, l1, h2, l2, h3, l3;
        split_bf16(encWhh[n * 128 + k0],     h0, l0);
        split_bf16(encWhh[n * 128 + k0 + 1], h1, l1);
        split_bf16(encWhh[n * 128 + k0 + 8], h2, l2);
        split_bf16(encWhh[n * 128 + k0 + 9], h3, l3);
        g_encWF_hi[idx] = make_uint2((unsigned)h0 | ((unsigned)h1 << 16),
                                     (unsigned)h2 | ((unsigned)h3 << 16));
        g_encWF_lo[idx] = make_uint2((unsigned)l0 | ((unsigned)l1 << 16),
                                     (unsigned)l2 | ((unsigned)l3 << 16));
        split_bf16(decWhh[n * 128 + k0],     h0, l0);
        split_bf16(decWhh[n * 128 + k0 + 1], h1, l1);
        split_bf16(decWhh[n * 128 + k0 + 8], h2, l2);
        split_bf16(decWhh[n * 128 + k0 + 9], h3, l3);
        g_decWF_hi[idx] = make_uint2((unsigned)h0 | ((unsigned)h1 << 16),
                                     (unsigned)h2 | ((unsigned)h3 << 16));
        g_decWF_lo[idx] = make_uint2((unsigned)l0 | ((unsigned)l1 << 16),
                                     (unsigned)l2 | ((unsigned)l3 << 16));
    }
    {   // transpose q/k/v
        int kk = idx >> 7, d = idx & 127;
        g_WqT[idx] = Wq[d * 128 + kk];
        g_WkT[idx] = Wk[d * 128 + kk];
        g_WvT[idx] = Wv[d * 128 + kk];
    }
}

// ---------------------------------------------------------------------------
// Encoder: tensor-core LSTM + fused online-softmax pool
// smem: wloS uint2[16384] | gsm f[16*516] | xs f[16*132] | red f[64] | abuf u32[2048]
// ---------------------------------------------------------------------------
#define ENC_SMEM ((32768 + 8256 + 2112 + 64 + 2048) * 4)

__global__ __launch_bounds__(THR_, 1)
void encoder_kernel(const float* __restrict__ x,
                    const float* __restrict__ enc_Wih,
                    const float* __restrict__ enc_bih,
                    const float* __restrict__ enc_bhh,
                    const float* __restrict__ pool_w,
                    const float* __restrict__ pool_b) {
    extern __shared__ float smf[];
    uint2*    wloS = (uint2*)smf;            // 131072 B
    float*    gsm  = smf + 32768;            // [16][516]
    float*    xs   = gsm + 8256;             // [16][132]
    float*    red  = xs + 2112;              // [16][4]
    unsigned* abuf = (unsigned*)(red + 64);  // 2048 u32 (hi: 0..1023, lo: 1024..2047)

    const int tid = threadIdx.x;
    const int w   = tid >> 5, lane = tid & 31;
    const int rowbase = blockIdx.x * R_;

    for (int i = tid; i < 16384; i += THR_) wloS[i] = g_encWF_lo[i];
    for (int i = tid; i < 2048;  i += THR_) abuf[i] = 0u;
    for (int i = tid; i < R_ * 128; i += THR_)
        xs[(i >> 7) * 132 + (i & 127)] = x[rowbase * 128 + i];

    // preload W_hi fragments (this warp's 4 N-tiles)
    uint2 whi[4][8];
    #pragma unroll
    for (int a = 0; a < 4; a++)
        #pragma unroll
        for (int kt = 0; kt < 8; kt++)
            whi[a][kt] = g_encWF_hi[((w * 4 + a) * 8 + kt) * 32 + lane];

    const int row0 = lane >> 2;
    const int colq = (lane & 3) * 2;
    float wihr[8], btr[8];
    #pragma unroll
    for (int a = 0; a < 4; a++)
        #pragma unroll
        for (int hh = 0; hh < 2; hh++) {
            int col = (w * 4 + a) * 8 + colq + hh;
            wihr[a * 2 + hh] = enc_Wih[col];
            btr[a * 2 + hh]  = enc_bih[col] + enc_bhh[col];
        }

    // elementwise mapping + abuf write indices
    const int j  = tid & 127;
    const int rb = tid >> 7;
    const float pwj = pool_w[j];
    const float pb  = pool_b[0];
    const int kt_j = j >> 4, kl = j & 15;
    int idxhi[4];
    #pragma unroll
    for (int p = 0; p < 4; p++) {
        int r = p * 4 + rb;
        int lane_w = ((r & 7) << 2) | ((kl >> 1) & 3);
        int reg    = ((kl >> 3) << 1) | (r >> 3);
        idxhi[p]   = (((kt_j * 32 + lane_w) * 4 + reg) << 1) | (kl & 1);
    }
    unsigned short* ab16 = (unsigned short*)abuf;

    float cst[4]  = {0.f, 0.f, 0.f, 0.f};
    float accj[4] = {0.f, 0.f, 0.f, 0.f};
    float msx[4]  = {-INFINITY, -INFINITY, -INFINITY, -INFINITY};
    float zsx[4]  = {0.f, 0.f, 0.f, 0.f};

    __syncthreads();

    for (int l = 0; l < L_; l++) {
        // ---- phase 1: gates on tensor cores ----
        float acc[4][4];
        float xr0 = xs[row0 * 132 + l];
        float xr8 = xs[(row0 + 8) * 132 + l];
        #pragma unroll
        for (int a = 0; a < 4; a++) {
            acc[a][0] = fmaf(xr0, wihr[a*2],   btr[a*2]);
            acc[a][1] = fmaf(xr0, wihr[a*2+1], btr[a*2+1]);
            acc[a][2] = fmaf(xr8, wihr[a*2],   btr[a*2]);
            acc[a][3] = fmaf(xr8, wihr[a*2+1], btr[a*2+1]);
        }
        #pragma unroll
        for (int kt = 0; kt < 8; kt++) {
            uint4 ah = *(const uint4*)&abuf[(kt * 32 + lane) * 4];
            uint4 al = *(const uint4*)&abuf[((8 + kt) * 32 + lane) * 4];
            #pragma unroll
            for (int a = 0; a < 4; a++) {
                uint2 bl = wloS[((w * 4 + a) * 8 + kt) * 32 + lane];
                mma16816(acc[a], ah.x, ah.y, ah.z, ah.w, whi[a][kt].x, whi[a][kt].y);
                mma16816(acc[a], al.x, al.y, al.z, al.w, whi[a][kt].x, whi[a][kt].y);
                mma16816(acc[a], ah.x, ah.y, ah.z, ah.w, bl.x, bl.y);
            }
        }
        #pragma unroll
        for (int a = 0; a < 4; a++) {
            int cb = (w * 4 + a) * 8 + colq;
            *(float2*)&gsm[row0 * GS_ + cb]       = make_float2(acc[a][0], acc[a][1]);
            *(float2*)&gsm[(row0 + 8) * GS_ + cb] = make_float2(acc[a][2], acc[a][3]);
        }
        __syncthreads();

        // ---- phase 2: cell + h split into abuf + pool partials ----
        float hval[4];
        #pragma unroll
        for (int p = 0; p < 4; p++) {
            int r = p * 4 + rb;
            float gi = gsm[r * GS_ + j];
            float gf = gsm[r * GS_ + 128 + j];
            float gg = gsm[r * GS_ + 256 + j];
            float go = gsm[r * GS_ + 384 + j];
            float si = sig_(gi), sf = sig_(gf), so = sig_(go);
            float tg = tanh_(gg);
            cst[p] = fmaf(sf, cst[p], si * tg);
            float h = so * tanh_(cst[p]);
            hval[p] = h;
            unsigned short hb, lb;
            split_bf16(h, hb, lb);
            ab16[idxhi[p]]        = hb;
            ab16[idxhi[p] + 2048] = lb;
            float contrib = warp_sum(h * pwj);
            if ((tid & 31) == 0) red[r * 4 + ((tid >> 5) & 3)] = contrib;
        }
        __syncthreads();

        // ---- phase 3: replicated online softmax ----
        #pragma unroll
        for (int p = 0; p < 4; p++) {
            int r = p * 4 + rb;
            float s = red[r*4] + red[r*4+1] + red[r*4+2] + red[r*4+3] + pb;
            float mn = fmaxf(msx[p], s);
            float f  = __expf(msx[p] - mn);
            float wg = __expf(s - mn);
            zsx[p]  = zsx[p] * f + wg;
            msx[p]  = mn;
            accj[p] = fmaf(accj[p], f, wg * hval[p]);
        }
    }

    #pragma unroll
    for (int p = 0; p < 4; p++) {
        int r = p * 4 + rb;
        g_c[(rowbase + r) * 128 + j] = __fdividef(accj[p], zsx[p]);
    }
}

// ---------------------------------------------------------------------------
// Spatial self-attention (unchanged from R6)
// ---------------------------------------------------------------------------
#define KTP_ 68
#define ATT_SMEM ((8192 + 8192 + 128 * KTP_ + 8192 + 4096) * 4)

__global__ __launch_bounds__(256, 1)
void attn_kernel(const float* __restrict__ bq,
                 const float* __restrict__ bk,
                 const float* __restrict__ bv,
                 float* __restrict__ out_cstar, float* __restrict__ out_A) {
    extern __shared__ float sm[];
    float* c_s = sm;
    float* q_s = c_s + 8192;
    float* kT  = q_s + 8192;
    float* v_s = kT + 128 * KTP_;
    float* sc  = v_s + 8192;
    const int b = blockIdx.x, tid = threadIdx.x;

    for (int i = tid; i < 8192; i += 256) c_s[i] = g_c[b * 8192 + i];
    __syncthreads();

    const float4* WqT4 = reinterpret_cast<const float4*>(g_WqT);
    const float4* WkT4 = reinterpret_cast<const float4*>(g_WkT);
    const float4* WvT4 = reinterpret_cast<const float4*>(g_WvT);
    for (int o2 = tid; o2 < 64 * 32; o2 += 256) {
        int n = o2 >> 5, d4 = o2 & 31;
        const float* bq4 = bq + d4 * 4;
        const float* bk4 = bk + d4 * 4;
        const float* bv4 = bv + d4 * 4;
        float4 aq = make_float4(bq4[0], bq4[1], bq4[2], bq4[3]);
        float4 ak = make_float4(bk4[0], bk4[1], bk4[2], bk4[3]);
        float4 av = make_float4(bv4[0], bv4[1], bv4[2], bv4[3]);
        const float* cr = &c_s[n * 128];
        #pragma unroll 4
        for (int kk = 0; kk < 128; kk++) {
            float cv = cr[kk];
            float4 wq = WqT4[kk * 32 + d4];
            float4 wk = WkT4[kk * 32 + d4];
            float4 wv = WvT4[kk * 32 + d4];
            aq.x = fmaf(cv, wq.x, aq.x); aq.y = fmaf(cv, wq.y, aq.y);
            aq.z = fmaf(cv, wq.z, aq.z); aq.w = fmaf(cv, wq.w, aq.w);
            ak.x = fmaf(cv, wk.x, ak.x); ak.y = fmaf(cv, wk.y, ak.y);
            ak.z = fmaf(cv, wk.z, ak.z); ak.w = fmaf(cv, wk.w, ak.w);
            av.x = fmaf(cv, wv.x, av.x); av.y = fmaf(cv, wv.y, av.y);
            av.z = fmaf(cv, wv.z, av.z); av.w = fmaf(cv, wv.w, av.w);
        }
        *reinterpret_cast<float4*>(&q_s[n * 128 + d4 * 4]) = aq;
        *reinterpret_cast<float4*>(&v_s[n * 128 + d4 * 4]) = av;
        int dd = d4 * 4;
        kT[(dd + 0) * KTP_ + n] = ak.x;
        kT[(dd + 1) * KTP_ + n] = ak.y;
        kT[(dd + 2) * KTP_ + n] = ak.z;
        kT[(dd + 3) * KTP_ + n] = ak.w;
    }
    __syncthreads();

    const float scale = 0.08838834764831845f;
    for (int o = tid; o < 4096; o += 256) {
        int n = o >> 6, m = o & 63;
        float s = 0.f;
        const float* qr = &q_s[n * 128];
        #pragma unroll 8
        for (int d = 0; d < 128; d++) s = fmaf(qr[d], kT[d * KTP_ + m], s);
        sc[o] = s * scale;
    }
    __syncthreads();

    const int warp = tid >> 5, lane = tid & 31;
    for (int n = warp; n < 64; n += 8) {
        float v0 = sc[n * 64 + lane], v1 = sc[n * 64 + 32 + lane];
        float mx = fmaxf(v0, v1);
        #pragma unroll
        for (int o = 16; o; o >>= 1) mx = fmaxf(mx, __shfl_xor_sync(0xffffffffu, mx, o));
        float e0 = __expf(v0 - mx), e1 = __expf(v1 - mx);
        float ss = warp_sum(e0 + e1);
        float inv = 1.f / ss;
        float a0 = e0 * inv, a1 = e1 * inv;
        sc[n * 64 + lane] = a0;
        sc[n * 64 + 32 + lane] = a1;
        out_A[b * 4096 + n * 64 + lane] = a0;
        out_A[b * 4096 + n * 64 + 32 + lane] = a1;
    }
    __syncthreads();

    for (int o = tid; o < 8192; o += 256) {
        int n = o >> 7, d = o & 127;
        float s = 0.f;
        const float* ar = &sc[n * 64];
        #pragma unroll 8
        for (int m = 0; m < 64; m++) s = fmaf(ar[m], v_s[m * 128 + d], s);
        out_cstar[b * 8192 + o] = s;
        g_cstar[b * 8192 + o]   = s;
    }
}

// ---------------------------------------------------------------------------
// Decoder: tensor-core LSTM + fused readouts
// smem: wloS uint2[16384] | gsm[16*516] | dprsm[16*516] | cs[2048] | red[64] |
//       red2[64] | abuf u32[2048]
// ---------------------------------------------------------------------------
#define DEC_SMEM ((32768 + 8256 + 8256 + 2048 + 64 + 64 + 2048) * 4)

__global__ __launch_bounds__(THR_, 1)
void decoder_kernel(const float* __restrict__ dec_bih,
                    const float* __restrict__ dec_bhh,
                    const float* __restrict__ rec_w,  const float* __restrict__ rec_b,
                    const float* __restrict__ pred_w, const float* __restrict__ pred_b,
                    float* __restrict__ out_recon, float* __restrict__ out_pred) {
    extern __shared__ float smf[];
    uint2*    wloS  = (uint2*)smf;
    float*    gsm   = smf + 32768;
    float*    dprsm = gsm + 8256;
    float*    cs    = dprsm + 8256;           // [16][128]
    float*    red   = cs + 2048;
    float*    red2  = red + 64;
    unsigned* abuf  = (unsigned*)(red2 + 64);

    const int tid = threadIdx.x;
    const int w   = tid >> 5, lane = tid & 31;
    const int rowbase = blockIdx.x * R_;

    for (int i = tid; i < 16384; i += THR_) wloS[i] = g_decWF_lo[i];
    for (int i = tid; i < 2048;  i += THR_) abuf[i] = 0u;
    for (int i = tid; i < R_ * 128; i += THR_) cs[i] = g_cstar[rowbase * 128 + i];

    uint2 whi[4][8];
    #pragma unroll
    for (int a = 0; a < 4; a++)
        #pragma unroll
        for (int kt = 0; kt < 8; kt++)
            whi[a][kt] = g_decWF_hi[((w * 4 + a) * 8 + kt) * 32 + lane];

    const int row0 = lane >> 2;
    const int colq = (lane & 3) * 2;

    const int j  = tid & 127;
    const int rb = tid >> 7;
    const float rwj = rec_w[j];
    const float pwj = pred_w[j];
    const float rbv = rec_b[0], pbv = pred_b[0];
    const int kt_j = j >> 4, kl = j & 15;
    int idxhi[4];
    #pragma unroll
    for (int p = 0; p < 4; p++) {
        int r = p * 4 + rb;
        int lane_w = ((r & 7) << 2) | ((kl >> 1) & 3);
        int reg    = ((kl >> 3) << 1) | (r >> 3);
        idxhi[p]   = (((kt_j * 32 + lane_w) * 4 + reg) << 1) | (kl & 1);
    }
    unsigned short* ab16 = (unsigned short*)abuf;

    float cst[4] = {0.f, 0.f, 0.f, 0.f};
    __syncthreads();

    // ---- dpr (constant input projection), scalar once: thread = gate t ----
    {
        const float bt = dec_bih[tid] + dec_bhh[tid];
        float dpr[R_];
        #pragma unroll
        for (int r = 0; r < R_; r++) dpr[r] = bt;
        #pragma unroll 4
        for (int kb = 0; kb < 32; kb++) {
            float4 wv = g_decWihP[kb * G4_ + tid];
            #pragma unroll
            for (int r = 0; r < R_; r++) {
                float4 h4 = *reinterpret_cast<const float4*>(&cs[r * 128 + kb * 4]);
                dpr[r] = fmaf(wv.x, h4.x, dpr[r]);
                dpr[r] = fmaf(wv.y, h4.y, dpr[r]);
                dpr[r] = fmaf(wv.z, h4.z, dpr[r]);
                dpr[r] = fmaf(wv.w, h4.w, dpr[r]);
            }
        }
        #pragma unroll
        for (int r = 0; r < R_; r++) dprsm[r * GS_ + tid] = dpr[r];
    }
    __syncthreads();

    for (int l = 0; l < L_; l++) {
        // ---- phase 1: gates on tensor cores ----
        float acc[4][4];
        #pragma unroll
        for (int a = 0; a < 4; a++) {
            int cb = (w * 4 + a) * 8 + colq;
            float2 d0 = *(const float2*)&dprsm[row0 * GS_ + cb];
            float2 d8 = *(const float2*)&dprsm[(row0 + 8) * GS_ + cb];
            acc[a][0] = d0.x; acc[a][1] = d0.y;
            acc[a][2] = d8.x; acc[a][3] = d8.y;
        }
        #pragma unroll
        for (int kt = 0; kt < 8; kt++) {
            uint4 ah = *(const uint4*)&abuf[(kt * 32 + lane) * 4];
            uint4 al = *(const uint4*)&abuf[((8 + kt) * 32 + lane) * 4];
            #pragma unroll
            for (int a = 0; a < 4; a++) {
                uint2 bl = wloS[((w * 4 + a) * 8 + kt) * 32 + lane];
                mma16816(acc[a], ah.x, ah.y, ah.z, ah.w, whi[a][kt].x, whi[a][kt].y);
                mma16816(acc[a], al.x, al.y, al.z, al.w, whi[a][kt].x, whi[a][kt].y);
                mma16816(acc[a], ah.x, ah.y, ah.z, ah.w, bl.x, bl.y);
            }
        }
        #pragma unroll
        for (int a = 0; a < 4; a++) {
            int cb = (w * 4 + a) * 8 + colq;
            *(float2*)&gsm[row0 * GS_ + cb]       = make_float2(acc[a][0], acc[a][1]);
            *(float2*)&gsm[(row0 + 8) * GS_ + cb] = make_float2(acc[a][2], acc[a][3]);
        }
        __syncthreads();

        // ---- phase 2: cell + h split + readout partials ----
        #pragma unroll
        for (int p = 0; p < 4; p++) {
            int r = p * 4 + rb;
            float gi = gsm[r * GS_ + j];
            float gf = gsm[r * GS_ + 128 + j];
            float gg = gsm[r * GS_ + 256 + j];
            float go = gsm[r * GS_ + 384 + j];
            float si = sig_(gi), sf = sig_(gf), so = sig_(go);
            float tg = tanh_(gg);
            cst[p] = fmaf(sf, cst[p], si * tg);
            float h = so * tanh_(cst[p]);
            unsigned short hb, lb;
            split_bf16(h, hb, lb);
            ab16[idxhi[p]]        = hb;
            ab16[idxhi[p] + 2048] = lb;
            float contrib = warp_sum(h * rwj);
            if ((tid & 31) == 0) red[r * 4 + ((tid >> 5) & 3)] = contrib;
            if (l == L_ - 1) {
                float c2 = warp_sum(h * pwj);
                if ((tid & 31) == 0) red2[r * 4 + ((tid >> 5) & 3)] = c2;
            }
        }
        __syncthreads();

        // ---- phase 3: leaders write recon (and pred last step) ----
        if (tid < 16) {
            float s = red[tid*4] + red[tid*4+1] + red[tid*4+2] + red[tid*4+3] + rbv;
            out_recon[(rowbase + tid) * 128 + l] = s;
            if (l == L_ - 1) {
                float p2 = red2[tid*4] + red2[tid*4+1] + red2[tid*4+2] + red2[tid*4+3] + pbv;
                out_pred[rowbase + tid] = p2;
            }
        }
    }
}

// ---------------------------------------------------------------------------
extern "C" void kernel_launch(void* const* d_in, const int* in_sizes, int n_in,
                              void* d_out, int out_size) {
    const float* x        = (const float*)d_in[0];
    const float* enc_Wih  = (const float*)d_in[1];
    const float* enc_Whh  = (const float*)d_in[2];
    const float* enc_bih  = (const float*)d_in[3];
    const float* enc_bhh  = (const float*)d_in[4];
    const float* pool_w   = (const float*)d_in[5];
    const float* pool_b   = (const float*)d_in[6];
    const float* Wq       = (const float*)d_in[7];
    const float* bq       = (const float*)d_in[8];
    const float* Wk       = (const float*)d_in[9];
    const float* bk       = (const float*)d_in[10];
    const float* Wv       = (const float*)d_in[11];
    const float* bv       = (const float*)d_in[12];
    const float* dec_Wih  = (const float*)d_in[13];
    const float* dec_Whh  = (const float*)d_in[14];
    const float* dec_bih  = (const float*)d_in[15];
    const float* dec_bhh  = (const float*)d_in[16];
    const float* rec_w    = (const float*)d_in[17];
    const float* rec_b    = (const float*)d_in[18];
    const float* pred_w   = (const float*)d_in[19];
    const float* pred_b   = (const float*)d_in[20];

    float* out = (float*)d_out;
    float* out_recon = out;
    float* out_pred  = out + 262144;
    float* out_cstar = out + 264192;
    float* out_A     = out + 526336;

    cudaFuncSetAttribute(encoder_kernel, cudaFuncAttributeMaxDynamicSharedMemorySize, ENC_SMEM);
    cudaFuncSetAttribute(decoder_kernel, cudaFuncAttributeMaxDynamicSharedMemorySize, DEC_SMEM);
    cudaFuncSetAttribute(attn_kernel,    cudaFuncAttributeMaxDynamicSharedMemorySize, ATT_SMEM);

    pack_kernel<<<64, 256>>>(enc_Whh, dec_Whh, dec_Wih, Wq, Wk, Wv);
    encoder_kernel<<<NCTA_, THR_, ENC_SMEM>>>(x, enc_Wih, enc_bih, enc_bhh, pool_w, pool_b);
    attn_kernel<<<32, 256, ATT_SMEM>>>(bq, bk, bv, out_cstar, out_A);
    decoder_kernel<<<NCTA_, THR_, DEC_SMEM>>>(dec_bih, dec_bhh, rec_w, rec_b,
                                              pred_w, pred_b, out_recon, out_pred);
}

// round 8
// speedup vs baseline: 5.1449x; 1.0911x over previous
#include <cuda_runtime.h>
#include <cuda_bf16.h>
#include <math.h>

// ---------------------------------------------------------------------------
// G_OracleAD: enc-LSTM(+attn pool) -> spatial attention -> dec-LSTM(+readouts)
// B=32 N=64 L=128 H=128  BN=2048  4H=512
// d_out (fp32): recon[262144] | pred[2048] | c_star[262144] | A[131072]
// R8: gate-interleaved N-permutation (c = j*4+gate) -> one LDS.128 per
//     (row,j) gate fetch; tanh.approx.f32 activations (MUFU.TANH).
//     Tensor-core 3-term bf16 split GEMM unchanged from R7.
// ---------------------------------------------------------------------------

#define BN_   2048
#define L_    128
#define H_    128
#define G4_   512
#define R_    16
#define NCTA_ (BN_ / R_)   // 128
#define THR_  512
#define GS_   516          // padded gsm row stride (floats)

// device scratch
__device__ uint2  g_encWF_hi[16384];   // frag-order bf16x2 pairs (permuted cols)
__device__ uint2  g_encWF_lo[16384];
__device__ uint2  g_decWF_hi[16384];
__device__ uint2  g_decWF_lo[16384];
__device__ float4 g_decWihP[32 * G4_]; // permuted-col float4 pack
__device__ float  g_WqT[H_ * H_];
__device__ float  g_WkT[H_ * H_];
__device__ float  g_WvT[H_ * H_];
__device__ float  g_c[BN_ * H_];
__device__ float  g_cstar[BN_ * H_];

// permuted col c -> original gate-major row: (c&3)*128 + (c>>2)
__device__ __forceinline__ int colorig_(int c) { return (c & 3) * 128 + (c >> 2); }

__device__ __forceinline__ float tanh_(float x) {
    float y;
    asm("tanh.approx.f32 %0, %1;" : "=f"(y) : "f"(x));
    return y;
}
__device__ __forceinline__ float sig_(float x) {
    return fmaf(tanh_(0.5f * x), 0.5f, 0.5f);
}
__device__ __forceinline__ float warp_sum(float v) {
    #pragma unroll
    for (int o = 16; o; o >>= 1) v += __shfl_xor_sync(0xffffffffu, v, o);
    return v;
}
__device__ __forceinline__ void mma16816(float* c, unsigned a0, unsigned a1,
                                         unsigned a2, unsigned a3,
                                         unsigned b0, unsigned b1) {
    asm("mma.sync.aligned.m16n8k16.row.col.f32.bf16.bf16.f32 "
        "{%0,%1,%2,%3}, {%4,%5,%6,%7}, {%8,%9}, {%0,%1,%2,%3};"
        : "+f"(c[0]), "+f"(c[1]), "+f"(c[2]), "+f"(c[3])
        : "r"(a0), "r"(a1), "r"(a2), "r"(a3), "r"(b0), "r"(b1));
}
__device__ __forceinline__ void split_bf16(float w, unsigned short& hi, unsigned short& lo) {
    __nv_bfloat16 bh = __float2bfloat16_rn(w);
    hi = *reinterpret_cast<unsigned short*>(&bh);
    float r = w - __bfloat162float(bh);
    __nv_bfloat16 bl = __float2bfloat16_rn(r);
    lo = *reinterpret_cast<unsigned short*>(&bl);
}

// ---------------------------------------------------------------------------
// pack: fragment-order W splits with permuted N-columns, decWih float4
// (permuted), Wq/k/v transposes.
// frag (nt,kt,lane): c = nt*8 + lane/4 (permuted col); k0 = kt*16+(lane&3)*2
// ---------------------------------------------------------------------------
__global__ void pack_kernel(const float* __restrict__ encWhh,
                            const float* __restrict__ decWhh,
                            const float* __restrict__ decWih,
                            const float* __restrict__ Wq,
                            const float* __restrict__ Wk,
                            const float* __restrict__ Wv) {
    int idx = blockIdx.x * blockDim.x + threadIdx.x;   // 0..16383
    {   // decWih float4 pack (permuted cols)
        int kb = idx >> 9, c = idx & 511;
        int orig = (c & 3) * 128 + (c >> 2);
        int s  = orig * 128 + kb * 4;
        g_decWihP[idx] = make_float4(decWih[s], decWih[s+1], decWih[s+2], decWih[s+3]);
    }
    {   // fragment splits (permuted cols)
        int nt = idx >> 8, kt = (idx >> 5) & 7, l = idx & 31;
        int c  = nt * 8 + (l >> 2);
        int n  = (c & 3) * 128 + (c >> 2);    // original W row
        int k0 = kt * 16 + (l & 3) * 2;
        unsigned short h0, l0, h1, l1, h2, l2, h3, l3;
        split_bf16(encWhh[n * 128 + k0],     h0, l0);
        split_bf16(encWhh[n * 128 + k0 + 1], h1, l1);
        split_bf16(encWhh[n * 128 + k0 + 8], h2, l2);
        split_bf16(encWhh[n * 128 + k0 + 9], h3, l3);
        g_encWF_hi[idx] = make_uint2((unsigned)h0 | ((unsigned)h1 << 16),
                                     (unsigned)h2 | ((unsigned)h3 << 16));
        g_encWF_lo[idx] = make_uint2((unsigned)l0 | ((unsigned)l1 << 16),
                                     (unsigned)l2 | ((unsigned)l3 << 16));
        split_bf16(decWhh[n * 128 + k0],     h0, l0);
        split_bf16(decWhh[n * 128 + k0 + 1], h1, l1);
        split_bf16(decWhh[n * 128 + k0 + 8], h2, l2);
        split_bf16(decWhh[n * 128 + k0 + 9], h3, l3);
        g_decWF_hi[idx] = make_uint2((unsigned)h0 | ((unsigned)h1 << 16),
                                     (unsigned)h2 | ((unsigned)h3 << 16));
        g_decWF_lo[idx] = make_uint2((unsigned)l0 | ((unsigned)l1 << 16),
                                     (unsigned)l2 | ((unsigned)l3 << 16));
    }
    {   // transpose q/k/v
        int kk = idx >> 7, d = idx & 127;
        g_WqT[idx] = Wq[d * 128 + kk];
        g_WkT[idx] = Wk[d * 128 + kk];
        g_WvT[idx] = Wv[d * 128 + kk];
    }
}

// ---------------------------------------------------------------------------
// Encoder: tensor-core LSTM + fused online-softmax pool
// smem: wloS uint2[16384] | gsm f[16*516] | xs f[16*132] | red f[64] | abuf u32[2048]
// ---------------------------------------------------------------------------
#define ENC_SMEM ((32768 + 8256 + 2112 + 64 + 2048) * 4)

__global__ __launch_bounds__(THR_, 1)
void encoder_kernel(const float* __restrict__ x,
                    const float* __restrict__ enc_Wih,
                    const float* __restrict__ enc_bih,
                    const float* __restrict__ enc_bhh,
                    const float* __restrict__ pool_w,
                    const float* __restrict__ pool_b) {
    extern __shared__ float smf[];
    uint2*    wloS = (uint2*)smf;
    float*    gsm  = smf + 32768;
    float*    xs   = gsm + 8256;
    float*    red  = xs + 2112;
    unsigned* abuf = (unsigned*)(red + 64);

    const int tid = threadIdx.x;
    const int w   = tid >> 5, lane = tid & 31;
    const int rowbase = blockIdx.x * R_;

    for (int i = tid; i < 16384; i += THR_) wloS[i] = g_encWF_lo[i];
    for (int i = tid; i < 2048;  i += THR_) abuf[i] = 0u;
    for (int i = tid; i < R_ * 128; i += THR_)
        xs[(i >> 7) * 132 + (i & 127)] = x[rowbase * 128 + i];

    uint2 whi[4][8];
    #pragma unroll
    for (int a = 0; a < 4; a++)
        #pragma unroll
        for (int kt = 0; kt < 8; kt++)
            whi[a][kt] = g_encWF_hi[((w * 4 + a) * 8 + kt) * 32 + lane];

    const int row0 = lane >> 2;
    const int colq = (lane & 3) * 2;
    float wihr[8], btr[8];
    #pragma unroll
    for (int a = 0; a < 4; a++)
        #pragma unroll
        for (int hh = 0; hh < 2; hh++) {
            int col  = (w * 4 + a) * 8 + colq + hh;   // permuted
            int orig = colorig_(col);
            wihr[a * 2 + hh] = enc_Wih[orig];
            btr[a * 2 + hh]  = enc_bih[orig] + enc_bhh[orig];
        }

    const int j  = tid & 127;
    const int rb = tid >> 7;
    const float pwj = pool_w[j];
    const float pb  = pool_b[0];
    const int kt_j = j >> 4, kl = j & 15;
    int idxhi[4];
    #pragma unroll
    for (int p = 0; p < 4; p++) {
        int r = p * 4 + rb;
        int lane_w = ((r & 7) << 2) | ((kl >> 1) & 3);
        int reg    = ((kl >> 3) << 1) | (r >> 3);
        idxhi[p]   = (((kt_j * 32 + lane_w) * 4 + reg) << 1) | (kl & 1);
    }
    unsigned short* ab16 = (unsigned short*)abuf;

    float cst[4]  = {0.f, 0.f, 0.f, 0.f};
    float accj[4] = {0.f, 0.f, 0.f, 0.f};
    float msx[4]  = {-INFINITY, -INFINITY, -INFINITY, -INFINITY};
    float zsx[4]  = {0.f, 0.f, 0.f, 0.f};

    __syncthreads();

    for (int l = 0; l < L_; l++) {
        // ---- phase 1: gates on tensor cores ----
        float acc[4][4];
        float xr0 = xs[row0 * 132 + l];
        float xr8 = xs[(row0 + 8) * 132 + l];
        #pragma unroll
        for (int a = 0; a < 4; a++) {
            acc[a][0] = fmaf(xr0, wihr[a*2],   btr[a*2]);
            acc[a][1] = fmaf(xr0, wihr[a*2+1], btr[a*2+1]);
            acc[a][2] = fmaf(xr8, wihr[a*2],   btr[a*2]);
            acc[a][3] = fmaf(xr8, wihr[a*2+1], btr[a*2+1]);
        }
        #pragma unroll
        for (int kt = 0; kt < 8; kt++) {
            uint4 ah = *(const uint4*)&abuf[(kt * 32 + lane) * 4];
            uint4 al = *(const uint4*)&abuf[((8 + kt) * 32 + lane) * 4];
            #pragma unroll
            for (int a = 0; a < 4; a++) {
                uint2 bl = wloS[((w * 4 + a) * 8 + kt) * 32 + lane];
                mma16816(acc[a], ah.x, ah.y, ah.z, ah.w, whi[a][kt].x, whi[a][kt].y);
                mma16816(acc[a], al.x, al.y, al.z, al.w, whi[a][kt].x, whi[a][kt].y);
                mma16816(acc[a], ah.x, ah.y, ah.z, ah.w, bl.x, bl.y);
            }
        }
        #pragma unroll
        for (int a = 0; a < 4; a++) {
            int cb = (w * 4 + a) * 8 + colq;
            *(float2*)&gsm[row0 * GS_ + cb]       = make_float2(acc[a][0], acc[a][1]);
            *(float2*)&gsm[(row0 + 8) * GS_ + cb] = make_float2(acc[a][2], acc[a][3]);
        }
        __syncthreads();

        // ---- phase 2: cell (vector gate load) + h split + pool partials ----
        float hval[4];
        #pragma unroll
        for (int p = 0; p < 4; p++) {
            int r = p * 4 + rb;
            float4 g4 = *(const float4*)&gsm[r * GS_ + 4 * j];  // i,f,g,o
            float si = sig_(g4.x), sf = sig_(g4.y), so = sig_(g4.w);
            float tg = tanh_(g4.z);
            cst[p] = fmaf(sf, cst[p], si * tg);
            float h = so * tanh_(cst[p]);
            hval[p] = h;
            unsigned short hb, lb;
            split_bf16(h, hb, lb);
            ab16[idxhi[p]]        = hb;
            ab16[idxhi[p] + 2048] = lb;
            float contrib = warp_sum(h * pwj);
            if ((tid & 31) == 0) red[r * 4 + ((tid >> 5) & 3)] = contrib;
        }
        __syncthreads();

        // ---- phase 3: replicated online softmax ----
        #pragma unroll
        for (int p = 0; p < 4; p++) {
            int r = p * 4 + rb;
            float s = red[r*4] + red[r*4+1] + red[r*4+2] + red[r*4+3] + pb;
            float mn = fmaxf(msx[p], s);
            float f  = __expf(msx[p] - mn);
            float wg = __expf(s - mn);
            zsx[p]  = zsx[p] * f + wg;
            msx[p]  = mn;
            accj[p] = fmaf(accj[p], f, wg * hval[p]);
        }
    }

    #pragma unroll
    for (int p = 0; p < 4; p++) {
        int r = p * 4 + rb;
        g_c[(rowbase + r) * 128 + j] = __fdividef(accj[p], zsx[p]);
    }
}

// ---------------------------------------------------------------------------
// Spatial self-attention (unchanged from R6)
// ---------------------------------------------------------------------------
#define KTP_ 68
#define ATT_SMEM ((8192 + 8192 + 128 * KTP_ + 8192 + 4096) * 4)

__global__ __launch_bounds__(256, 1)
void attn_kernel(const float* __restrict__ bq,
                 const float* __restrict__ bk,
                 const float* __restrict__ bv,
                 float* __restrict__ out_cstar, float* __restrict__ out_A) {
    extern __shared__ float sm[];
    float* c_s = sm;
    float* q_s = c_s + 8192;
    float* kT  = q_s + 8192;
    float* v_s = kT + 128 * KTP_;
    float* sc  = v_s + 8192;
    const int b = blockIdx.x, tid = threadIdx.x;

    for (int i = tid; i < 8192; i += 256) c_s[i] = g_c[b * 8192 + i];
    __syncthreads();

    const float4* WqT4 = reinterpret_cast<const float4*>(g_WqT);
    const float4* WkT4 = reinterpret_cast<const float4*>(g_WkT);
    const float4* WvT4 = reinterpret_cast<const float4*>(g_WvT);
    for (int o2 = tid; o2 < 64 * 32; o2 += 256) {
        int n = o2 >> 5, d4 = o2 & 31;
        const float* bq4 = bq + d4 * 4;
        const float* bk4 = bk + d4 * 4;
        const float* bv4 = bv + d4 * 4;
        float4 aq = make_float4(bq4[0], bq4[1], bq4[2], bq4[3]);
        float4 ak = make_float4(bk4[0], bk4[1], bk4[2], bk4[3]);
        float4 av = make_float4(bv4[0], bv4[1], bv4[2], bv4[3]);
        const float* cr = &c_s[n * 128];
        #pragma unroll 4
        for (int kk = 0; kk < 128; kk++) {
            float cv = cr[kk];
            float4 wq = WqT4[kk * 32 + d4];
            float4 wk = WkT4[kk * 32 + d4];
            float4 wv = WvT4[kk * 32 + d4];
            aq.x = fmaf(cv, wq.x, aq.x); aq.y = fmaf(cv, wq.y, aq.y);
            aq.z = fmaf(cv, wq.z, aq.z); aq.w = fmaf(cv, wq.w, aq.w);
            ak.x = fmaf(cv, wk.x, ak.x); ak.y = fmaf(cv, wk.y, ak.y);
            ak.z = fmaf(cv, wk.z, ak.z); ak.w = fmaf(cv, wk.w, ak.w);
            av.x = fmaf(cv, wv.x, av.x); av.y = fmaf(cv, wv.y, av.y);
            av.z = fmaf(cv, wv.z, av.z); av.w = fmaf(cv, wv.w, av.w);
        }
        *reinterpret_cast<float4*>(&q_s[n * 128 + d4 * 4]) = aq;
        *reinterpret_cast<float4*>(&v_s[n * 128 + d4 * 4]) = av;
        int dd = d4 * 4;
        kT[(dd + 0) * KTP_ + n] = ak.x;
        kT[(dd + 1) * KTP_ + n] = ak.y;
        kT[(dd + 2) * KTP_ + n] = ak.z;
        kT[(dd + 3) * KTP_ + n] = ak.w;
    }
    __syncthreads();

    const float scale = 0.08838834764831845f;
    for (int o = tid; o < 4096; o += 256) {
        int n = o >> 6, m = o & 63;
        float s = 0.f;
        const float* qr = &q_s[n * 128];
        #pragma unroll 8
        for (int d = 0; d < 128; d++) s = fmaf(qr[d], kT[d * KTP_ + m], s);
        sc[o] = s * scale;
    }
    __syncthreads();

    const int warp = tid >> 5, lane = tid & 31;
    for (int n = warp; n < 64; n += 8) {
        float v0 = sc[n * 64 + lane], v1 = sc[n * 64 + 32 + lane];
        float mx = fmaxf(v0, v1);
        #pragma unroll
        for (int o = 16; o; o >>= 1) mx = fmaxf(mx, __shfl_xor_sync(0xffffffffu, mx, o));
        float e0 = __expf(v0 - mx), e1 = __expf(v1 - mx);
        float ss = warp_sum(e0 + e1);
        float inv = 1.f / ss;
        float a0 = e0 * inv, a1 = e1 * inv;
        sc[n * 64 + lane] = a0;
        sc[n * 64 + 32 + lane] = a1;
        out_A[b * 4096 + n * 64 + lane] = a0;
        out_A[b * 4096 + n * 64 + 32 + lane] = a1;
    }
    __syncthreads();

    for (int o = tid; o < 8192; o += 256) {
        int n = o >> 7, d = o & 127;
        float s = 0.f;
        const float* ar = &sc[n * 64];
        #pragma unroll 8
        for (int m = 0; m < 64; m++) s = fmaf(ar[m], v_s[m * 128 + d], s);
        out_cstar[b * 8192 + o] = s;
        g_cstar[b * 8192 + o]   = s;
    }
}

// ---------------------------------------------------------------------------
// Decoder: tensor-core LSTM + fused readouts
// ---------------------------------------------------------------------------
#define DEC_SMEM ((32768 + 8256 + 8256 + 2048 + 64 + 64 + 2048) * 4)

__global__ __launch_bounds__(THR_, 1)
void decoder_kernel(const float* __restrict__ dec_bih,
                    const float* __restrict__ dec_bhh,
                    const float* __restrict__ rec_w,  const float* __restrict__ rec_b,
                    const float* __restrict__ pred_w, const float* __restrict__ pred_b,
                    float* __restrict__ out_recon, float* __restrict__ out_pred) {
    extern __shared__ float smf[];
    uint2*    wloS  = (uint2*)smf;
    float*    gsm   = smf + 32768;
    float*    dprsm = gsm + 8256;
    float*    cs    = dprsm + 8256;
    float*    red   = cs + 2048;
    float*    red2  = red + 64;
    unsigned* abuf  = (unsigned*)(red2 + 64);

    const int tid = threadIdx.x;
    const int w   = tid >> 5, lane = tid & 31;
    const int rowbase = blockIdx.x * R_;

    for (int i = tid; i < 16384; i += THR_) wloS[i] = g_decWF_lo[i];
    for (int i = tid; i < 2048;  i += THR_) abuf[i] = 0u;
    for (int i = tid; i < R_ * 128; i += THR_) cs[i] = g_cstar[rowbase * 128 + i];

    uint2 whi[4][8];
    #pragma unroll
    for (int a = 0; a < 4; a++)
        #pragma unroll
        for (int kt = 0; kt < 8; kt++)
            whi[a][kt] = g_decWF_hi[((w * 4 + a) * 8 + kt) * 32 + lane];

    const int row0 = lane >> 2;
    const int colq = (lane & 3) * 2;

    const int j  = tid & 127;
    const int rb = tid >> 7;
    const float rwj = rec_w[j];
    const float pwj = pred_w[j];
    const float rbv = rec_b[0], pbv = pred_b[0];
    const int kt_j = j >> 4, kl = j & 15;
    int idxhi[4];
    #pragma unroll
    for (int p = 0; p < 4; p++) {
        int r = p * 4 + rb;
        int lane_w = ((r & 7) << 2) | ((kl >> 1) & 3);
        int reg    = ((kl >> 3) << 1) | (r >> 3);
        idxhi[p]   = (((kt_j * 32 + lane_w) * 4 + reg) << 1) | (kl & 1);
    }
    unsigned short* ab16 = (unsigned short*)abuf;

    float cst[4] = {0.f, 0.f, 0.f, 0.f};
    __syncthreads();

    // ---- dpr (constant input projection), scalar once: thread = permuted col ----
    {
        const int orig = colorig_(tid);
        const float bt = dec_bih[orig] + dec_bhh[orig];
        float dpr[R_];
        #pragma unroll
        for (int r = 0; r < R_; r++) dpr[r] = bt;
        #pragma unroll 4
        for (int kb = 0; kb < 32; kb++) {
            float4 wv = g_decWihP[kb * G4_ + tid];
            #pragma unroll
            for (int r = 0; r < R_; r++) {
                float4 h4 = *reinterpret_cast<const float4*>(&cs[r * 128 + kb * 4]);
                dpr[r] = fmaf(wv.x, h4.x, dpr[r]);
                dpr[r] = fmaf(wv.y, h4.y, dpr[r]);
                dpr[r] = fmaf(wv.z, h4.z, dpr[r]);
                dpr[r] = fmaf(wv.w, h4.w, dpr[r]);
            }
        }
        #pragma unroll
        for (int r = 0; r < R_; r++) dprsm[r * GS_ + tid] = dpr[r];
    }
    __syncthreads();

    for (int l = 0; l < L_; l++) {
        // ---- phase 1: gates on tensor cores ----
        float acc[4][4];
        #pragma unroll
        for (int a = 0; a < 4; a++) {
            int cb = (w * 4 + a) * 8 + colq;
            float2 d0 = *(const float2*)&dprsm[row0 * GS_ + cb];
            float2 d8 = *(const float2*)&dprsm[(row0 + 8) * GS_ + cb];
            acc[a][0] = d0.x; acc[a][1] = d0.y;
            acc[a][2] = d8.x; acc[a][3] = d8.y;
        }
        #pragma unroll
        for (int kt = 0; kt < 8; kt++) {
            uint4 ah = *(const uint4*)&abuf[(kt * 32 + lane) * 4];
            uint4 al = *(const uint4*)&abuf[((8 + kt) * 32 + lane) * 4];
            #pragma unroll
            for (int a = 0; a < 4; a++) {
                uint2 bl = wloS[((w * 4 + a) * 8 + kt) * 32 + lane];
                mma16816(acc[a], ah.x, ah.y, ah.z, ah.w, whi[a][kt].x, whi[a][kt].y);
                mma16816(acc[a], al.x, al.y, al.z, al.w, whi[a][kt].x, whi[a][kt].y);
                mma16816(acc[a], ah.x, ah.y, ah.z, ah.w, bl.x, bl.y);
            }
        }
        #pragma unroll
        for (int a = 0; a < 4; a++) {
            int cb = (w * 4 + a) * 8 + colq;
            *(float2*)&gsm[row0 * GS_ + cb]       = make_float2(acc[a][0], acc[a][1]);
            *(float2*)&gsm[(row0 + 8) * GS_ + cb] = make_float2(acc[a][2], acc[a][3]);
        }
        __syncthreads();

        // ---- phase 2: cell (vector gate load) + h split + readout partials ----
        #pragma unroll
        for (int p = 0; p < 4; p++) {
            int r = p * 4 + rb;
            float4 g4 = *(const float4*)&gsm[r * GS_ + 4 * j];  // i,f,g,o
            float si = sig_(g4.x), sf = sig_(g4.y), so = sig_(g4.w);
            float tg = tanh_(g4.z);
            cst[p] = fmaf(sf, cst[p], si * tg);
            float h = so * tanh_(cst[p]);
            unsigned short hb, lb;
            split_bf16(h, hb, lb);
            ab16[idxhi[p]]        = hb;
            ab16[idxhi[p] + 2048] = lb;
            float contrib = warp_sum(h * rwj);
            if ((tid & 31) == 0) red[r * 4 + ((tid >> 5) & 3)] = contrib;
            if (l == L_ - 1) {
                float c2 = warp_sum(h * pwj);
                if ((tid & 31) == 0) red2[r * 4 + ((tid >> 5) & 3)] = c2;
            }
        }
        __syncthreads();

        // ---- phase 3: leaders write recon (and pred last step) ----
        if (tid < 16) {
            float s = red[tid*4] + red[tid*4+1] + red[tid*4+2] + red[tid*4+3] + rbv;
            out_recon[(rowbase + tid) * 128 + l] = s;
            if (l == L_ - 1) {
                float p2 = red2[tid*4] + red2[tid*4+1] + red2[tid*4+2] + red2[tid*4+3] + pbv;
                out_pred[rowbase + tid] = p2;
            }
        }
    }
}

// ---------------------------------------------------------------------------
extern "C" void kernel_launch(void* const* d_in, const int* in_sizes, int n_in,
                              void* d_out, int out_size) {
    const float* x        = (const float*)d_in[0];
    const float* enc_Wih  = (const float*)d_in[1];
    const float* enc_Whh  = (const float*)d_in[2];
    const float* enc_bih  = (const float*)d_in[3];
    const float* enc_bhh  = (const float*)d_in[4];
    const float* pool_w   = (const float*)d_in[5];
    const float* pool_b   = (const float*)d_in[6];
    const float* Wq       = (const float*)d_in[7];
    const float* bq       = (const float*)d_in[8];
    const float* Wk       = (const float*)d_in[9];
    const float* bk       = (const float*)d_in[10];
    const float* Wv       = (const float*)d_in[11];
    const float* bv       = (const float*)d_in[12];
    const float* dec_Wih  = (const float*)d_in[13];
    const float* dec_Whh  = (const float*)d_in[14];
    const float* dec_bih  = (const float*)d_in[15];
    const float* dec_bhh  = (const float*)d_in[16];
    const float* rec_w    = (const float*)d_in[17];
    const float* rec_b    = (const float*)d_in[18];
    const float* pred_w   = (const float*)d_in[19];
    const float* pred_b   = (const float*)d_in[20];

    float* out = (float*)d_out;
    float* out_recon = out;
    float* out_pred  = out + 262144;
    float* out_cstar = out + 264192;
    float* out_A     = out + 526336;

    cudaFuncSetAttribute(encoder_kernel, cudaFuncAttributeMaxDynamicSharedMemorySize, ENC_SMEM);
    cudaFuncSetAttribute(decoder_kernel, cudaFuncAttributeMaxDynamicSharedMemorySize, DEC_SMEM);
    cudaFuncSetAttribute(attn_kernel,    cudaFuncAttributeMaxDynamicSharedMemorySize, ATT_SMEM);

    pack_kernel<<<64, 256>>>(enc_Whh, dec_Whh, dec_Wih, Wq, Wk, Wv);
    encoder_kernel<<<NCTA_, THR_, ENC_SMEM>>>(x, enc_Wih, enc_bih, enc_bhh, pool_w, pool_b);
    attn_kernel<<<32, 256, ATT_SMEM>>>(bq, bk, bv, out_cstar, out_A);
    decoder_kernel<<<NCTA_, THR_, DEC_SMEM>>>(dec_bih, dec_bhh, rec_w, rec_b,
                                              pred_w, pred_b, out_recon, out_pred);
}

// round 9
// speedup vs baseline: 5.4610x; 1.0614x over previous
#include <cuda_runtime.h>
#include <cuda_bf16.h>
#include <math.h>

// ---------------------------------------------------------------------------
// G_OracleAD: enc-LSTM(+attn pool) -> spatial attention -> dec-LSTM(+readouts)
// B=32 N=64 L=128 H=128  BN=2048  4H=512
// d_out (fp32): recon[262144] | pred[2048] | c_star[262144] | A[131072]
// R9: ownership-aligned warps (gate cols j in [w*8,(w+1)*8) processed by warp
//     w) -> phase1->phase2 is warp-local (__syncwarp); ONE __syncthreads per
//     step; abuf/red double-buffered by parity; decoder dpr in registers.
// ---------------------------------------------------------------------------

#define BN_   2048
#define L_    128
#define H_    128
#define G4_   512
#define R_    16
#define NCTA_ (BN_ / R_)   // 128
#define THR_  512
#define GS_   516          // padded gsm row stride (floats)

// device scratch
__device__ uint2  g_encWF_hi[16384];
__device__ uint2  g_encWF_lo[16384];
__device__ uint2  g_decWF_hi[16384];
__device__ uint2  g_decWF_lo[16384];
__device__ float4 g_decWihP[32 * G4_];
__device__ float  g_WqT[H_ * H_];
__device__ float  g_WkT[H_ * H_];
__device__ float  g_WvT[H_ * H_];
__device__ float  g_c[BN_ * H_];
__device__ float  g_cstar[BN_ * H_];

__device__ __forceinline__ int colorig_(int c) { return (c & 3) * 128 + (c >> 2); }

__device__ __forceinline__ float tanh_(float x) {
    float y;
    asm("tanh.approx.f32 %0, %1;" : "=f"(y) : "f"(x));
    return y;
}
__device__ __forceinline__ float sig_(float x) {
    return fmaf(tanh_(0.5f * x), 0.5f, 0.5f);
}
__device__ __forceinline__ void mma16816(float* c, unsigned a0, unsigned a1,
                                         unsigned a2, unsigned a3,
                                         unsigned b0, unsigned b1) {
    asm("mma.sync.aligned.m16n8k16.row.col.f32.bf16.bf16.f32 "
        "{%0,%1,%2,%3}, {%4,%5,%6,%7}, {%8,%9}, {%0,%1,%2,%3};"
        : "+f"(c[0]), "+f"(c[1]), "+f"(c[2]), "+f"(c[3])
        : "r"(a0), "r"(a1), "r"(a2), "r"(a3), "r"(b0), "r"(b1));
}
__device__ __forceinline__ void split_bf16(float w, unsigned short& hi, unsigned short& lo) {
    __nv_bfloat16 bh = __float2bfloat16_rn(w);
    hi = *reinterpret_cast<unsigned short*>(&bh);
    float r = w - __bfloat162float(bh);
    __nv_bfloat16 bl = __float2bfloat16_rn(r);
    lo = *reinterpret_cast<unsigned short*>(&bl);
}
// A-fragment halfword index for (row r, k=j) within step buffer (2048 shorts hi region)
__device__ __forceinline__ int fragidx_(int r, int j) {
    int kt = j >> 4, kl = j & 15;
    int lane_w = ((r & 7) << 2) | ((kl >> 1) & 3);
    int reg    = ((kl >> 3) << 1) | (r >> 3);
    return (((kt * 32 + lane_w) * 4 + reg) << 1) | (kl & 1);
}

// ---------------------------------------------------------------------------
__global__ void pack_kernel(const float* __restrict__ encWhh,
                            const float* __restrict__ decWhh,
                            const float* __restrict__ decWih,
                            const float* __restrict__ Wq,
                            const float* __restrict__ Wk,
                            const float* __restrict__ Wv) {
    int idx = blockIdx.x * blockDim.x + threadIdx.x;   // 0..16383
    {   // decWih float4 pack (permuted cols)
        int kb = idx >> 9, c = idx & 511;
        int orig = (c & 3) * 128 + (c >> 2);
        int s  = orig * 128 + kb * 4;
        g_decWihP[idx] = make_float4(decWih[s], decWih[s+1], decWih[s+2], decWih[s+3]);
    }
    {   // fragment splits (permuted cols)
        int nt = idx >> 8, kt = (idx >> 5) & 7, l = idx & 31;
        int c  = nt * 8 + (l >> 2);
        int n  = (c & 3) * 128 + (c >> 2);
        int k0 = kt * 16 + (l & 3) * 2;
        unsigned short h0, l0, h1, l1, h2, l2, h3, l3;
        split_bf16(encWhh[n * 128 + k0],     h0, l0);
        split_bf16(encWhh[n * 128 + k0 + 1], h1, l1);
        split_bf16(encWhh[n * 128 + k0 + 8], h2, l2);
        split_bf16(encWhh[n * 128 + k0 + 9], h3, l3);
        g_encWF_hi[idx] = make_uint2((unsigned)h0 | ((unsigned)h1 << 16),
                                     (unsigned)h2 | ((unsigned)h3 << 16));
        g_encWF_lo[idx] = make_uint2((unsigned)l0 | ((unsigned)l1 << 16),
                                     (unsigned)l2 | ((unsigned)l3 << 16));
        split_bf16(decWhh[n * 128 + k0],     h0, l0);
        split_bf16(decWhh[n * 128 + k0 + 1], h1, l1);
        split_bf16(decWhh[n * 128 + k0 + 8], h2, l2);
        split_bf16(decWhh[n * 128 + k0 + 9], h3, l3);
        g_decWF_hi[idx] = make_uint2((unsigned)h0 | ((unsigned)h1 << 16),
                                     (unsigned)h2 | ((unsigned)h3 << 16));
        g_decWF_lo[idx] = make_uint2((unsigned)l0 | ((unsigned)l1 << 16),
                                     (unsigned)l2 | ((unsigned)l3 << 16));
    }
    {   // transpose q/k/v
        int kk = idx >> 7, d = idx & 127;
        g_WqT[idx] = Wq[d * 128 + kk];
        g_WkT[idx] = Wk[d * 128 + kk];
        g_WvT[idx] = Wv[d * 128 + kk];
    }
}

// ---------------------------------------------------------------------------
// Encoder: tensor-core LSTM + fused online-softmax pool; ONE bar/step.
// smem f-words: wloS 32768 | gsm 8256 | xs 2112 | red 2*256 | abuf 2*2048
// ---------------------------------------------------------------------------
#define ENC_SMEM ((32768 + 8256 + 2112 + 512 + 4096) * 4)

__global__ __launch_bounds__(THR_, 1)
void encoder_kernel(const float* __restrict__ x,
                    const float* __restrict__ enc_Wih,
                    const float* __restrict__ enc_bih,
                    const float* __restrict__ enc_bhh,
                    const float* __restrict__ pool_w,
                    const float* __restrict__ pool_b) {
    extern __shared__ float smf[];
    uint2*    wloS = (uint2*)smf;              // 16384 uint2
    float*    gsm  = smf + 32768;              // [16][516]
    float*    xs   = gsm + 8256;               // [16][132]
    float*    red  = xs + 2112;                // [2][16][16]
    unsigned* abuf = (unsigned*)(red + 512);   // [2][2048] u32

    const int tid = threadIdx.x;
    const int w   = tid >> 5, lane = tid & 31;
    const int rowbase = blockIdx.x * R_;

    for (int i = tid; i < 16384; i += THR_) wloS[i] = g_encWF_lo[i];
    for (int i = tid; i < 2048;  i += THR_) abuf[i] = 0u;      // buffer 0 (h=0)
    for (int i = tid; i < R_ * 128; i += THR_)
        xs[(i >> 7) * 132 + (i & 127)] = x[rowbase * 128 + i];

    uint2 whi[4][8];
    #pragma unroll
    for (int a = 0; a < 4; a++)
        #pragma unroll
        for (int kt = 0; kt < 8; kt++)
            whi[a][kt] = g_encWF_hi[((w * 4 + a) * 8 + kt) * 32 + lane];

    const int row0 = lane >> 2;
    const int colq = (lane & 3) * 2;
    float wihr[8], btr[8];
    #pragma unroll
    for (int a = 0; a < 4; a++)
        #pragma unroll
        for (int hh = 0; hh < 2; hh++) {
            int col  = (w * 4 + a) * 8 + colq + hh;
            int orig = colorig_(col);
            wihr[a * 2 + hh] = enc_Wih[orig];
            btr[a * 2 + hh]  = enc_bih[orig] + enc_bhh[orig];
        }

    // ownership-aligned cell mapping: lane -> row rr, 4 cols j0..j0+3
    const int rr = lane & 15;
    const int j0 = w * 8 + (lane >> 4) * 4;
    const float pb = pool_b[0];
    float pw[4];
    int   idxf[4];
    #pragma unroll
    for (int m = 0; m < 4; m++) {
        pw[m]   = pool_w[j0 + m];
        idxf[m] = fragidx_(rr, j0 + m);
    }
    unsigned short* ab16 = (unsigned short*)abuf;

    float cst[4]  = {0.f, 0.f, 0.f, 0.f};
    float accj[4] = {0.f, 0.f, 0.f, 0.f};
    float msx = -INFINITY, zsx = 0.f;

    __syncthreads();

    for (int l = 0; l < L_; l++) {
        const int rp = l & 1;           // read abuf[rp], write abuf[rp^1]
        const int rbase = rp * 2048;    // u32
        const int wbase = (rp ^ 1) * 4096;  // shorts

        // ---- phase 1: gates on tensor cores (reads abuf[rp]) ----
        float acc[4][4];
        float xr0 = xs[row0 * 132 + l];
        float xr8 = xs[(row0 + 8) * 132 + l];
        #pragma unroll
        for (int a = 0; a < 4; a++) {
            acc[a][0] = fmaf(xr0, wihr[a*2],   btr[a*2]);
            acc[a][1] = fmaf(xr0, wihr[a*2+1], btr[a*2+1]);
            acc[a][2] = fmaf(xr8, wihr[a*2],   btr[a*2]);
            acc[a][3] = fmaf(xr8, wihr[a*2+1], btr[a*2+1]);
        }
        #pragma unroll
        for (int kt = 0; kt < 8; kt++) {
            uint4 ah = *(const uint4*)&abuf[rbase + (kt * 32 + lane) * 4];
            uint4 al = *(const uint4*)&abuf[rbase + 1024 + (kt * 32 + lane) * 4];
            #pragma unroll
            for (int a = 0; a < 4; a++) {
                uint2 bl = wloS[((w * 4 + a) * 8 + kt) * 32 + lane];
                mma16816(acc[a], ah.x, ah.y, ah.z, ah.w, whi[a][kt].x, whi[a][kt].y);
                mma16816(acc[a], al.x, al.y, al.z, al.w, whi[a][kt].x, whi[a][kt].y);
                mma16816(acc[a], ah.x, ah.y, ah.z, ah.w, bl.x, bl.y);
            }
        }
        #pragma unroll
        for (int a = 0; a < 4; a++) {
            int cb = (w * 4 + a) * 8 + colq;
            *(float2*)&gsm[row0 * GS_ + cb]       = make_float2(acc[a][0], acc[a][1]);
            *(float2*)&gsm[(row0 + 8) * GS_ + cb] = make_float2(acc[a][2], acc[a][3]);
        }
        __syncwarp();   // warp-local: this warp's cols -> this warp's cells

        // ---- phase 2: cell + h split -> abuf[rp^1] + pool partial ----
        float hv[4], partial = 0.f;
        #pragma unroll
        for (int m = 0; m < 4; m++) {
            float4 g4 = *(const float4*)&gsm[rr * GS_ + 4 * (j0 + m)];  // i,f,g,o
            float si = sig_(g4.x), sf = sig_(g4.y), so = sig_(g4.w);
            float tg = tanh_(g4.z);
            cst[m] = fmaf(sf, cst[m], si * tg);
            float h = so * tanh_(cst[m]);
            hv[m] = h;
            unsigned short hb, lb;
            split_bf16(h, hb, lb);
            ab16[wbase + idxf[m]]        = hb;
            ab16[wbase + idxf[m] + 2048] = lb;
            partial = fmaf(h, pw[m], partial);
        }
        partial += __shfl_xor_sync(0xffffffffu, partial, 16);
        if (lane < 16) red[rp * 256 + rr * 16 + w] = partial;
        __syncthreads();

        // ---- phase 3: replicated online softmax (reads red[rp]) ----
        {
            const float* rr16 = &red[rp * 256 + rr * 16];
            float4 v0 = *(const float4*)&rr16[0];
            float4 v1 = *(const float4*)&rr16[4];
            float4 v2 = *(const float4*)&rr16[8];
            float4 v3 = *(const float4*)&rr16[12];
            float s = ((v0.x+v0.y)+(v0.z+v0.w)) + ((v1.x+v1.y)+(v1.z+v1.w))
                    + ((v2.x+v2.y)+(v2.z+v2.w)) + ((v3.x+v3.y)+(v3.z+v3.w)) + pb;
            float mn = fmaxf(msx, s);
            float f  = __expf(msx - mn);
            float wg = __expf(s - mn);
            zsx = zsx * f + wg;
            msx = mn;
            #pragma unroll
            for (int m = 0; m < 4; m++) accj[m] = fmaf(accj[m], f, wg * hv[m]);
        }
    }

    #pragma unroll
    for (int m = 0; m < 4; m++)
        g_c[(rowbase + rr) * 128 + j0 + m] = __fdividef(accj[m], zsx);
}

// ---------------------------------------------------------------------------
// Spatial self-attention (unchanged from R6)
// ---------------------------------------------------------------------------
#define KTP_ 68
#define ATT_SMEM ((8192 + 8192 + 128 * KTP_ + 8192 + 4096) * 4)

__global__ __launch_bounds__(256, 1)
void attn_kernel(const float* __restrict__ bq,
                 const float* __restrict__ bk,
                 const float* __restrict__ bv,
                 float* __restrict__ out_cstar, float* __restrict__ out_A) {
    extern __shared__ float sm[];
    float* c_s = sm;
    float* q_s = c_s + 8192;
    float* kT  = q_s + 8192;
    float* v_s = kT + 128 * KTP_;
    float* sc  = v_s + 8192;
    const int b = blockIdx.x, tid = threadIdx.x;

    for (int i = tid; i < 8192; i += 256) c_s[i] = g_c[b * 8192 + i];
    __syncthreads();

    const float4* WqT4 = reinterpret_cast<const float4*>(g_WqT);
    const float4* WkT4 = reinterpret_cast<const float4*>(g_WkT);
    const float4* WvT4 = reinterpret_cast<const float4*>(g_WvT);
    for (int o2 = tid; o2 < 64 * 32; o2 += 256) {
        int n = o2 >> 5, d4 = o2 & 31;
        const float* bq4 = bq + d4 * 4;
        const float* bk4 = bk + d4 * 4;
        const float* bv4 = bv + d4 * 4;
        float4 aq = make_float4(bq4[0], bq4[1], bq4[2], bq4[3]);
        float4 ak = make_float4(bk4[0], bk4[1], bk4[2], bk4[3]);
        float4 av = make_float4(bv4[0], bv4[1], bv4[2], bv4[3]);
        const float* cr = &c_s[n * 128];
        #pragma unroll 4
        for (int kk = 0; kk < 128; kk++) {
            float cv = cr[kk];
            float4 wq = WqT4[kk * 32 + d4];
            float4 wk = WkT4[kk * 32 + d4];
            float4 wv = WvT4[kk * 32 + d4];
            aq.x = fmaf(cv, wq.x, aq.x); aq.y = fmaf(cv, wq.y, aq.y);
            aq.z = fmaf(cv, wq.z, aq.z); aq.w = fmaf(cv, wq.w, aq.w);
            ak.x = fmaf(cv, wk.x, ak.x); ak.y = fmaf(cv, wk.y, ak.y);
            ak.z = fmaf(cv, wk.z, ak.z); ak.w = fmaf(cv, wk.w, ak.w);
            av.x = fmaf(cv, wv.x, av.x); av.y = fmaf(cv, wv.y, av.y);
            av.z = fmaf(cv, wv.z, av.z); av.w = fmaf(cv, wv.w, av.w);
        }
        *reinterpret_cast<float4*>(&q_s[n * 128 + d4 * 4]) = aq;
        *reinterpret_cast<float4*>(&v_s[n * 128 + d4 * 4]) = av;
        int dd = d4 * 4;
        kT[(dd + 0) * KTP_ + n] = ak.x;
        kT[(dd + 1) * KTP_ + n] = ak.y;
        kT[(dd + 2) * KTP_ + n] = ak.z;
        kT[(dd + 3) * KTP_ + n] = ak.w;
    }
    __syncthreads();

    const float scale = 0.08838834764831845f;
    for (int o = tid; o < 4096; o += 256) {
        int n = o >> 6, m = o & 63;
        float s = 0.f;
        const float* qr = &q_s[n * 128];
        #pragma unroll 8
        for (int d = 0; d < 128; d++) s = fmaf(qr[d], kT[d * KTP_ + m], s);
        sc[o] = s * scale;
    }
    __syncthreads();

    const int warp = tid >> 5, lane = tid & 31;
    for (int n = warp; n < 64; n += 8) {
        float v0 = sc[n * 64 + lane], v1 = sc[n * 64 + 32 + lane];
        float mx = fmaxf(v0, v1);
        #pragma unroll
        for (int o = 16; o; o >>= 1) mx = fmaxf(mx, __shfl_xor_sync(0xffffffffu, mx, o));
        float e0 = __expf(v0 - mx), e1 = __expf(v1 - mx);
        float ss = e0 + e1;
        #pragma unroll
        for (int o = 16; o; o >>= 1) ss += __shfl_xor_sync(0xffffffffu, ss, o);
        float inv = 1.f / ss;
        float a0 = e0 * inv, a1 = e1 * inv;
        sc[n * 64 + lane] = a0;
        sc[n * 64 + 32 + lane] = a1;
        out_A[b * 4096 + n * 64 + lane] = a0;
        out_A[b * 4096 + n * 64 + 32 + lane] = a1;
    }
    __syncthreads();

    for (int o = tid; o < 8192; o += 256) {
        int n = o >> 7, d = o & 127;
        float s = 0.f;
        const float* ar = &sc[n * 64];
        #pragma unroll 8
        for (int m = 0; m < 64; m++) s = fmaf(ar[m], v_s[m * 128 + d], s);
        out_cstar[b * 8192 + o] = s;
        g_cstar[b * 8192 + o]   = s;
    }
}

// ---------------------------------------------------------------------------
// Decoder: tensor-core LSTM + fused readouts; ONE bar/step; dpr in regs.
// smem f-words: wloS 32768 | gsm 8256 | cs 2048 | red 512 | red2 256 | abuf 4096
// ---------------------------------------------------------------------------
#define DEC_SMEM ((32768 + 8256 + 2048 + 512 + 256 + 4096) * 4)

__global__ __launch_bounds__(THR_, 1)
void decoder_kernel(const float* __restrict__ dec_bih,
                    const float* __restrict__ dec_bhh,
                    const float* __restrict__ rec_w,  const float* __restrict__ rec_b,
                    const float* __restrict__ pred_w, const float* __restrict__ pred_b,
                    float* __restrict__ out_recon, float* __restrict__ out_pred) {
    extern __shared__ float smf[];
    uint2*    wloS = (uint2*)smf;
    float*    gsm  = smf + 32768;              // [16][516]
    float*    cs   = gsm + 8256;               // [16][128]
    float*    red  = cs + 2048;                // [2][16][16]
    float*    red2 = red + 512;                // [16][16]
    unsigned* abuf = (unsigned*)(red2 + 256);  // [2][2048] u32

    const int tid = threadIdx.x;
    const int w   = tid >> 5, lane = tid & 31;
    const int rowbase = blockIdx.x * R_;

    for (int i = tid; i < 16384; i += THR_) wloS[i] = g_decWF_lo[i];
    for (int i = tid; i < 2048;  i += THR_) abuf[i] = 0u;
    for (int i = tid; i < R_ * 128; i += THR_) cs[i] = g_cstar[rowbase * 128 + i];

    uint2 whi[4][8];
    #pragma unroll
    for (int a = 0; a < 4; a++)
        #pragma unroll
        for (int kt = 0; kt < 8; kt++)
            whi[a][kt] = g_decWF_hi[((w * 4 + a) * 8 + kt) * 32 + lane];

    const int row0 = lane >> 2;
    const int colq = (lane & 3) * 2;

    const int rr = lane & 15;
    const int j0 = w * 8 + (lane >> 4) * 4;
    const float rbv = rec_b[0], pbv = pred_b[0];
    float rw[4], pw2[4];
    int   idxf[4];
    #pragma unroll
    for (int m = 0; m < 4; m++) {
        rw[m]   = rec_w[j0 + m];
        pw2[m]  = pred_w[j0 + m];
        idxf[m] = fragidx_(rr, j0 + m);
    }
    unsigned short* ab16 = (unsigned short*)abuf;

    float cst[4] = {0.f, 0.f, 0.f, 0.f};
    __syncthreads();

    // ---- dpr GEMM (scalar, once): thread = permuted col tid; via gsm ----
    {
        const int orig = colorig_(tid);
        const float bt = dec_bih[orig] + dec_bhh[orig];
        float dpr[R_];
        #pragma unroll
        for (int r = 0; r < R_; r++) dpr[r] = bt;
        #pragma unroll 4
        for (int kb = 0; kb < 32; kb++) {
            float4 wv = g_decWihP[kb * G4_ + tid];
            #pragma unroll
            for (int r = 0; r < R_; r++) {
                float4 h4 = *reinterpret_cast<const float4*>(&cs[r * 128 + kb * 4]);
                dpr[r] = fmaf(wv.x, h4.x, dpr[r]);
                dpr[r] = fmaf(wv.y, h4.y, dpr[r]);
                dpr[r] = fmaf(wv.z, h4.z, dpr[r]);
                dpr[r] = fmaf(wv.w, h4.w, dpr[r]);
            }
        }
        #pragma unroll
        for (int r = 0; r < R_; r++) gsm[r * GS_ + tid] = dpr[r];
    }
    __syncwarp();   // col tid belongs to warp tid>>5's tile -> warp-local

    // hoist dpr fragment values to registers (constant across steps)
    float dfrag[4][4];
    #pragma unroll
    for (int a = 0; a < 4; a++) {
        int cb = (w * 4 + a) * 8 + colq;
        float2 d0 = *(const float2*)&gsm[row0 * GS_ + cb];
        float2 d8 = *(const float2*)&gsm[(row0 + 8) * GS_ + cb];
        dfrag[a][0] = d0.x; dfrag[a][1] = d0.y;
        dfrag[a][2] = d8.x; dfrag[a][3] = d8.y;
    }
    __syncwarp();

    for (int l = 0; l < L_; l++) {
        const int rp = l & 1;
        const int rbase = rp * 2048;
        const int wbase = (rp ^ 1) * 4096;

        // ---- phase 1: gates on tensor cores ----
        float acc[4][4];
        #pragma unroll
        for (int a = 0; a < 4; a++)
            #pragma unroll
            for (int q = 0; q < 4; q++) acc[a][q] = dfrag[a][q];
        #pragma unroll
        for (int kt = 0; kt < 8; kt++) {
            uint4 ah = *(const uint4*)&abuf[rbase + (kt * 32 + lane) * 4];
            uint4 al = *(const uint4*)&abuf[rbase + 1024 + (kt * 32 + lane) * 4];
            #pragma unroll
            for (int a = 0; a < 4; a++) {
                uint2 bl = wloS[((w * 4 + a) * 8 + kt) * 32 + lane];
                mma16816(acc[a], ah.x, ah.y, ah.z, ah.w, whi[a][kt].x, whi[a][kt].y);
                mma16816(acc[a], al.x, al.y, al.z, al.w, whi[a][kt].x, whi[a][kt].y);
                mma16816(acc[a], ah.x, ah.y, ah.z, ah.w, bl.x, bl.y);
            }
        }
        #pragma unroll
        for (int a = 0; a < 4; a++) {
            int cb = (w * 4 + a) * 8 + colq;
            *(float2*)&gsm[row0 * GS_ + cb]       = make_float2(acc[a][0], acc[a][1]);
            *(float2*)&gsm[(row0 + 8) * GS_ + cb] = make_float2(acc[a][2], acc[a][3]);
        }
        __syncwarp();

        // ---- phase 2: cell + h split + readout partials ----
        float partial = 0.f, partial2 = 0.f;
        #pragma unroll
        for (int m = 0; m < 4; m++) {
            float4 g4 = *(const float4*)&gsm[rr * GS_ + 4 * (j0 + m)];
            float si = sig_(g4.x), sf = sig_(g4.y), so = sig_(g4.w);
            float tg = tanh_(g4.z);
            cst[m] = fmaf(sf, cst[m], si * tg);
            float h = so * tanh_(cst[m]);
            unsigned short hb, lb;
            split_bf16(h, hb, lb);
            ab16[wbase + idxf[m]]        = hb;
            ab16[wbase + idxf[m] + 2048] = lb;
            partial = fmaf(h, rw[m], partial);
            if (l == L_ - 1) partial2 = fmaf(h, pw2[m], partial2);
        }
        partial += __shfl_xor_sync(0xffffffffu, partial, 16);
        if (lane < 16) red[rp * 256 + rr * 16 + w] = partial;
        if (l == L_ - 1) {
            partial2 += __shfl_xor_sync(0xffffffffu, partial2, 16);
            if (lane < 16) red2[rr * 16 + w] = partial2;
        }
        __syncthreads();

        // ---- phase 3: leaders write recon (and pred on last step) ----
        if (tid < 16) {
            const float* r16 = &red[rp * 256 + tid * 16];
            float4 v0 = *(const float4*)&r16[0];
            float4 v1 = *(const float4*)&r16[4];
            float4 v2 = *(const float4*)&r16[8];
            float4 v3 = *(const float4*)&r16[12];
            float s = ((v0.x+v0.y)+(v0.z+v0.w)) + ((v1.x+v1.y)+(v1.z+v1.w))
                    + ((v2.x+v2.y)+(v2.z+v2.w)) + ((v3.x+v3.y)+(v3.z+v3.w)) + rbv;
            out_recon[(rowbase + tid) * 128 + l] = s;
            if (l == L_ - 1) {
                const float* q16 = &red2[tid * 16];
                float4 u0 = *(const float4*)&q16[0];
                float4 u1 = *(const float4*)&q16[4];
                float4 u2 = *(const float4*)&q16[8];
                float4 u3 = *(const float4*)&q16[12];
                float p2 = ((u0.x+u0.y)+(u0.z+u0.w)) + ((u1.x+u1.y)+(u1.z+u1.w))
                         + ((u2.x+u2.y)+(u2.z+u2.w)) + ((u3.x+u3.y)+(u3.z+u3.w)) + pbv;
                out_pred[rowbase + tid] = p2;
            }
        }
    }
}

// ---------------------------------------------------------------------------
extern "C" void kernel_launch(void* const* d_in, const int* in_sizes, int n_in,
                              void* d_out, int out_size) {
    const float* x        = (const float*)d_in[0];
    const float* enc_Wih  = (const float*)d_in[1];
    const float* enc_Whh  = (const float*)d_in[2];
    const float* enc_bih  = (const float*)d_in[3];
    const float* enc_bhh  = (const float*)d_in[4];
    const float* pool_w   = (const float*)d_in[5];
    const float* pool_b   = (const float*)d_in[6];
    const float* Wq       = (const float*)d_in[7];
    const float* bq       = (const float*)d_in[8];
    const float* Wk       = (const float*)d_in[9];
    const float* bk       = (const float*)d_in[10];
    const float* Wv       = (const float*)d_in[11];
    const float* bv       = (const float*)d_in[12];
    const float* dec_Wih  = (const float*)d_in[13];
    const float* dec_Whh  = (const float*)d_in[14];
    const float* dec_bih  = (const float*)d_in[15];
    const float* dec_bhh  = (const float*)d_in[16];
    const float* rec_w    = (const float*)d_in[17];
    const float* rec_b    = (const float*)d_in[18];
    const float* pred_w   = (const float*)d_in[19];
    const float* pred_b   = (const float*)d_in[20];

    float* out = (float*)d_out;
    float* out_recon = out;
    float* out_pred  = out + 262144;
    float* out_cstar = out + 264192;
    float* out_A     = out + 526336;

    cudaFuncSetAttribute(encoder_kernel, cudaFuncAttributeMaxDynamicSharedMemorySize, ENC_SMEM);
    cudaFuncSetAttribute(decoder_kernel, cudaFuncAttributeMaxDynamicSharedMemorySize, DEC_SMEM);
    cudaFuncSetAttribute(attn_kernel,    cudaFuncAttributeMaxDynamicSharedMemorySize, ATT_SMEM);

    pack_kernel<<<64, 256>>>(enc_Whh, dec_Whh, dec_Wih, Wq, Wk, Wv);
    encoder_kernel<<<NCTA_, THR_, ENC_SMEM>>>(x, enc_Wih, enc_bih, enc_bhh, pool_w, pool_b);
    attn_kernel<<<32, 256, ATT_SMEM>>>(bq, bk, bv, out_cstar, out_A);
    decoder_kernel<<<NCTA_, THR_, DEC_SMEM>>>(dec_bih, dec_bhh, rec_w, rec_b,
                                              pred_w, pred_b, out_recon, out_pred);
}

// round 10
// speedup vs baseline: 6.6975x; 1.2264x over previous
#include <cuda_runtime.h>
#include <cuda_fp16.h>
#include <math.h>

// ---------------------------------------------------------------------------
// G_OracleAD: enc-LSTM(+attn pool) -> spatial attention -> dec-LSTM(+readouts)
// B=32 N=64 L=128 H=128  BN=2048  4H=512
// d_out (fp32): recon[262144] | pred[2048] | c_star[262144] | A[131072]
// R10: fp16 2-term weight split (W=Whi+Wlo fp16; h single fp16) -> 2 MMAs per
//      tile instead of 3; h store is one fp16 (no split). R9 structure kept:
//      ownership-aligned warps, one CTA barrier/step, parity double-buffer.
// ---------------------------------------------------------------------------

#define BN_   2048
#define L_    128
#define H_    128
#define G4_   512
#define R_    16
#define NCTA_ (BN_ / R_)   // 128
#define THR_  512
#define GS_   516          // padded gsm row stride (floats)

// device scratch
__device__ uint2  g_encWF_hi[16384];   // fp16x2 B-fragments (permuted cols)
__device__ uint2  g_encWF_lo[16384];
__device__ uint2  g_decWF_hi[16384];
__device__ uint2  g_decWF_lo[16384];
__device__ float4 g_decWihP[32 * G4_];
__device__ float  g_WqT[H_ * H_];
__device__ float  g_WkT[H_ * H_];
__device__ float  g_WvT[H_ * H_];
__device__ float  g_c[BN_ * H_];
__device__ float  g_cstar[BN_ * H_];

__device__ __forceinline__ int colorig_(int c) { return (c & 3) * 128 + (c >> 2); }

__device__ __forceinline__ float tanh_(float x) {
    float y;
    asm("tanh.approx.f32 %0, %1;" : "=f"(y) : "f"(x));
    return y;
}
__device__ __forceinline__ float sig_(float x) {
    return fmaf(tanh_(0.5f * x), 0.5f, 0.5f);
}
__device__ __forceinline__ void mma16816h(float* c, unsigned a0, unsigned a1,
                                          unsigned a2, unsigned a3,
                                          unsigned b0, unsigned b1) {
    asm("mma.sync.aligned.m16n8k16.row.col.f32.f16.f16.f32 "
        "{%0,%1,%2,%3}, {%4,%5,%6,%7}, {%8,%9}, {%0,%1,%2,%3};"
        : "+f"(c[0]), "+f"(c[1]), "+f"(c[2]), "+f"(c[3])
        : "r"(a0), "r"(a1), "r"(a2), "r"(a3), "r"(b0), "r"(b1));
}
__device__ __forceinline__ void split_fp16(float w, unsigned short& hi, unsigned short& lo) {
    __half bh = __float2half_rn(w);
    hi = *reinterpret_cast<unsigned short*>(&bh);
    float r = w - __half2float(bh);
    __half bl = __float2half_rn(r);
    lo = *reinterpret_cast<unsigned short*>(&bl);
}
// A-fragment halfword index for (row r, k=j): region = 1024 u32 = 2048 shorts
__device__ __forceinline__ int fragidx_(int r, int j) {
    int kt = j >> 4, kl = j & 15;
    int lane_w = ((r & 7) << 2) | ((kl >> 1) & 3);
    int reg    = ((kl >> 3) << 1) | (r >> 3);
    return (((kt * 32 + lane_w) * 4 + reg) << 1) | (kl & 1);
}

// ---------------------------------------------------------------------------
__global__ void pack_kernel(const float* __restrict__ encWhh,
                            const float* __restrict__ decWhh,
                            const float* __restrict__ decWih,
                            const float* __restrict__ Wq,
                            const float* __restrict__ Wk,
                            const float* __restrict__ Wv) {
    int idx = blockIdx.x * blockDim.x + threadIdx.x;   // 0..16383
    {   // decWih float4 pack (permuted cols)
        int kb = idx >> 9, c = idx & 511;
        int orig = (c & 3) * 128 + (c >> 2);
        int s  = orig * 128 + kb * 4;
        g_decWihP[idx] = make_float4(decWih[s], decWih[s+1], decWih[s+2], decWih[s+3]);
    }
    {   // fp16 fragment splits (permuted cols)
        int nt = idx >> 8, kt = (idx >> 5) & 7, l = idx & 31;
        int c  = nt * 8 + (l >> 2);
        int n  = (c & 3) * 128 + (c >> 2);
        int k0 = kt * 16 + (l & 3) * 2;
        unsigned short h0, l0, h1, l1, h2, l2, h3, l3;
        split_fp16(encWhh[n * 128 + k0],     h0, l0);
        split_fp16(encWhh[n * 128 + k0 + 1], h1, l1);
        split_fp16(encWhh[n * 128 + k0 + 8], h2, l2);
        split_fp16(encWhh[n * 128 + k0 + 9], h3, l3);
        g_encWF_hi[idx] = make_uint2((unsigned)h0 | ((unsigned)h1 << 16),
                                     (unsigned)h2 | ((unsigned)h3 << 16));
        g_encWF_lo[idx] = make_uint2((unsigned)l0 | ((unsigned)l1 << 16),
                                     (unsigned)l2 | ((unsigned)l3 << 16));
        split_fp16(decWhh[n * 128 + k0],     h0, l0);
        split_fp16(decWhh[n * 128 + k0 + 1], h1, l1);
        split_fp16(decWhh[n * 128 + k0 + 8], h2, l2);
        split_fp16(decWhh[n * 128 + k0 + 9], h3, l3);
        g_decWF_hi[idx] = make_uint2((unsigned)h0 | ((unsigned)h1 << 16),
                                     (unsigned)h2 | ((unsigned)h3 << 16));
        g_decWF_lo[idx] = make_uint2((unsigned)l0 | ((unsigned)l1 << 16),
                                     (unsigned)l2 | ((unsigned)l3 << 16));
    }
    {   // transpose q/k/v
        int kk = idx >> 7, d = idx & 127;
        g_WqT[idx] = Wq[d * 128 + kk];
        g_WkT[idx] = Wk[d * 128 + kk];
        g_WvT[idx] = Wv[d * 128 + kk];
    }
}

// ---------------------------------------------------------------------------
// Encoder: tensor-core LSTM + fused online-softmax pool; ONE bar/step.
// smem f-words: wloS 32768 | gsm 8256 | xs 2112 | red 512 | abuf 2048
// ---------------------------------------------------------------------------
#define ENC_SMEM ((32768 + 8256 + 2112 + 512 + 2048) * 4)

__global__ __launch_bounds__(THR_, 1)
void encoder_kernel(const float* __restrict__ x,
                    const float* __restrict__ enc_Wih,
                    const float* __restrict__ enc_bih,
                    const float* __restrict__ enc_bhh,
                    const float* __restrict__ pool_w,
                    const float* __restrict__ pool_b) {
    extern __shared__ float smf[];
    uint2*    wloS = (uint2*)smf;              // 16384 uint2
    float*    gsm  = smf + 32768;              // [16][516]
    float*    xs   = gsm + 8256;               // [16][132]
    float*    red  = xs + 2112;                // [2][16][16]
    unsigned* abuf = (unsigned*)(red + 512);   // [2][1024] u32 (fp16 A frags)

    const int tid = threadIdx.x;
    const int w   = tid >> 5, lane = tid & 31;
    const int rowbase = blockIdx.x * R_;

    for (int i = tid; i < 16384; i += THR_) wloS[i] = g_encWF_lo[i];
    for (int i = tid; i < 2048;  i += THR_) abuf[i] = 0u;      // both buffers
    for (int i = tid; i < R_ * 128; i += THR_)
        xs[(i >> 7) * 132 + (i & 127)] = x[rowbase * 128 + i];

    uint2 whi[4][8];
    #pragma unroll
    for (int a = 0; a < 4; a++)
        #pragma unroll
        for (int kt = 0; kt < 8; kt++)
            whi[a][kt] = g_encWF_hi[((w * 4 + a) * 8 + kt) * 32 + lane];

    const int row0 = lane >> 2;
    const int colq = (lane & 3) * 2;
    float wihr[8], btr[8];
    #pragma unroll
    for (int a = 0; a < 4; a++)
        #pragma unroll
        for (int hh = 0; hh < 2; hh++) {
            int col  = (w * 4 + a) * 8 + colq + hh;
            int orig = colorig_(col);
            wihr[a * 2 + hh] = enc_Wih[orig];
            btr[a * 2 + hh]  = enc_bih[orig] + enc_bhh[orig];
        }

    const int rr = lane & 15;
    const int j0 = w * 8 + (lane >> 4) * 4;
    const float pb = pool_b[0];
    float pw[4];
    int   idxf[4];
    #pragma unroll
    for (int m = 0; m < 4; m++) {
        pw[m]   = pool_w[j0 + m];
        idxf[m] = fragidx_(rr, j0 + m);
    }
    unsigned short* ab16 = (unsigned short*)abuf;

    float cst[4]  = {0.f, 0.f, 0.f, 0.f};
    float accj[4] = {0.f, 0.f, 0.f, 0.f};
    float msx = -INFINITY, zsx = 0.f;

    __syncthreads();

    for (int l = 0; l < L_; l++) {
        const int rp = l & 1;
        const int rbase = rp * 1024;        // u32
        const int wbase = (rp ^ 1) * 2048;  // shorts

        // ---- phase 1: gates on tensor cores (2 MMAs/tile) ----
        float acc[4][4];
        float xr0 = xs[row0 * 132 + l];
        float xr8 = xs[(row0 + 8) * 132 + l];
        #pragma unroll
        for (int a = 0; a < 4; a++) {
            acc[a][0] = fmaf(xr0, wihr[a*2],   btr[a*2]);
            acc[a][1] = fmaf(xr0, wihr[a*2+1], btr[a*2+1]);
            acc[a][2] = fmaf(xr8, wihr[a*2],   btr[a*2]);
            acc[a][3] = fmaf(xr8, wihr[a*2+1], btr[a*2+1]);
        }
        #pragma unroll
        for (int kt = 0; kt < 8; kt++) {
            uint4 ah = *(const uint4*)&abuf[rbase + (kt * 32 + lane) * 4];
            #pragma unroll
            for (int a = 0; a < 4; a++) {
                uint2 bl = wloS[((w * 4 + a) * 8 + kt) * 32 + lane];
                mma16816h(acc[a], ah.x, ah.y, ah.z, ah.w, whi[a][kt].x, whi[a][kt].y);
                mma16816h(acc[a], ah.x, ah.y, ah.z, ah.w, bl.x, bl.y);
            }
        }
        #pragma unroll
        for (int a = 0; a < 4; a++) {
            int cb = (w * 4 + a) * 8 + colq;
            *(float2*)&gsm[row0 * GS_ + cb]       = make_float2(acc[a][0], acc[a][1]);
            *(float2*)&gsm[(row0 + 8) * GS_ + cb] = make_float2(acc[a][2], acc[a][3]);
        }
        __syncwarp();

        // ---- phase 2: cell + fp16 h -> abuf[rp^1] + pool partial ----
        float hv[4], partial = 0.f;
        #pragma unroll
        for (int m = 0; m < 4; m++) {
            float4 g4 = *(const float4*)&gsm[rr * GS_ + 4 * (j0 + m)];  // i,f,g,o
            float si = sig_(g4.x), sf = sig_(g4.y), so = sig_(g4.w);
            float tg = tanh_(g4.z);
            cst[m] = fmaf(sf, cst[m], si * tg);
            float h = so * tanh_(cst[m]);
            hv[m] = h;
            __half hx = __float2half_rn(h);
            ab16[wbase + idxf[m]] = *reinterpret_cast<unsigned short*>(&hx);
            partial = fmaf(h, pw[m], partial);
        }
        partial += __shfl_xor_sync(0xffffffffu, partial, 16);
        if (lane < 16) red[rp * 256 + rr * 16 + w] = partial;
        __syncthreads();

        // ---- phase 3: replicated online softmax ----
        {
            const float* rr16 = &red[rp * 256 + rr * 16];
            float4 v0 = *(const float4*)&rr16[0];
            float4 v1 = *(const float4*)&rr16[4];
            float4 v2 = *(const float4*)&rr16[8];
            float4 v3 = *(const float4*)&rr16[12];
            float s = ((v0.x+v0.y)+(v0.z+v0.w)) + ((v1.x+v1.y)+(v1.z+v1.w))
                    + ((v2.x+v2.y)+(v2.z+v2.w)) + ((v3.x+v3.y)+(v3.z+v3.w)) + pb;
            float mn = fmaxf(msx, s);
            float f  = __expf(msx - mn);
            float wg = __expf(s - mn);
            zsx = zsx * f + wg;
            msx = mn;
            #pragma unroll
            for (int m = 0; m < 4; m++) accj[m] = fmaf(accj[m], f, wg * hv[m]);
        }
    }

    #pragma unroll
    for (int m = 0; m < 4; m++)
        g_c[(rowbase + rr) * 128 + j0 + m] = __fdividef(accj[m], zsx);
}

// ---------------------------------------------------------------------------
// Spatial self-attention (unchanged)
// ---------------------------------------------------------------------------
#define KTP_ 68
#define ATT_SMEM ((8192 + 8192 + 128 * KTP_ + 8192 + 4096) * 4)

__global__ __launch_bounds__(256, 1)
void attn_kernel(const float* __restrict__ bq,
                 const float* __restrict__ bk,
                 const float* __restrict__ bv,
                 float* __restrict__ out_cstar, float* __restrict__ out_A) {
    extern __shared__ float sm[];
    float* c_s = sm;
    float* q_s = c_s + 8192;
    float* kT  = q_s + 8192;
    float* v_s = kT + 128 * KTP_;
    float* sc  = v_s + 8192;
    const int b = blockIdx.x, tid = threadIdx.x;

    for (int i = tid; i < 8192; i += 256) c_s[i] = g_c[b * 8192 + i];
    __syncthreads();

    const float4* WqT4 = reinterpret_cast<const float4*>(g_WqT);
    const float4* WkT4 = reinterpret_cast<const float4*>(g_WkT);
    const float4* WvT4 = reinterpret_cast<const float4*>(g_WvT);
    for (int o2 = tid; o2 < 64 * 32; o2 += 256) {
        int n = o2 >> 5, d4 = o2 & 31;
        const float* bq4 = bq + d4 * 4;
        const float* bk4 = bk + d4 * 4;
        const float* bv4 = bv + d4 * 4;
        float4 aq = make_float4(bq4[0], bq4[1], bq4[2], bq4[3]);
        float4 ak = make_float4(bk4[0], bk4[1], bk4[2], bk4[3]);
        float4 av = make_float4(bv4[0], bv4[1], bv4[2], bv4[3]);
        const float* cr = &c_s[n * 128];
        #pragma unroll 4
        for (int kk = 0; kk < 128; kk++) {
            float cv = cr[kk];
            float4 wq = WqT4[kk * 32 + d4];
            float4 wk = WkT4[kk * 32 + d4];
            float4 wv = WvT4[kk * 32 + d4];
            aq.x = fmaf(cv, wq.x, aq.x); aq.y = fmaf(cv, wq.y, aq.y);
            aq.z = fmaf(cv, wq.z, aq.z); aq.w = fmaf(cv, wq.w, aq.w);
            ak.x = fmaf(cv, wk.x, ak.x); ak.y = fmaf(cv, wk.y, ak.y);
            ak.z = fmaf(cv, wk.z, ak.z); ak.w = fmaf(cv, wk.w, ak.w);
            av.x = fmaf(cv, wv.x, av.x); av.y = fmaf(cv, wv.y, av.y);
            av.z = fmaf(cv, wv.z, av.z); av.w = fmaf(cv, wv.w, av.w);
        }
        *reinterpret_cast<float4*>(&q_s[n * 128 + d4 * 4]) = aq;
        *reinterpret_cast<float4*>(&v_s[n * 128 + d4 * 4]) = av;
        int dd = d4 * 4;
        kT[(dd + 0) * KTP_ + n] = ak.x;
        kT[(dd + 1) * KTP_ + n] = ak.y;
        kT[(dd + 2) * KTP_ + n] = ak.z;
        kT[(dd + 3) * KTP_ + n] = ak.w;
    }
    __syncthreads();

    const float scale = 0.08838834764831845f;
    for (int o = tid; o < 4096; o += 256) {
        int n = o >> 6, m = o & 63;
        float s = 0.f;
        const float* qr = &q_s[n * 128];
        #pragma unroll 8
        for (int d = 0; d < 128; d++) s = fmaf(qr[d], kT[d * KTP_ + m], s);
        sc[o] = s * scale;
    }
    __syncthreads();

    const int warp = tid >> 5, lane = tid & 31;
    for (int n = warp; n < 64; n += 8) {
        float v0 = sc[n * 64 + lane], v1 = sc[n * 64 + 32 + lane];
        float mx = fmaxf(v0, v1);
        #pragma unroll
        for (int o = 16; o; o >>= 1) mx = fmaxf(mx, __shfl_xor_sync(0xffffffffu, mx, o));
        float e0 = __expf(v0 - mx), e1 = __expf(v1 - mx);
        float ss = e0 + e1;
        #pragma unroll
        for (int o = 16; o; o >>= 1) ss += __shfl_xor_sync(0xffffffffu, ss, o);
        float inv = 1.f / ss;
        float a0 = e0 * inv, a1 = e1 * inv;
        sc[n * 64 + lane] = a0;
        sc[n * 64 + 32 + lane] = a1;
        out_A[b * 4096 + n * 64 + lane] = a0;
        out_A[b * 4096 + n * 64 + 32 + lane] = a1;
    }
    __syncthreads();

    for (int o = tid; o < 8192; o += 256) {
        int n = o >> 7, d = o & 127;
        float s = 0.f;
        const float* ar = &sc[n * 64];
        #pragma unroll 8
        for (int m = 0; m < 64; m++) s = fmaf(ar[m], v_s[m * 128 + d], s);
        out_cstar[b * 8192 + o] = s;
        g_cstar[b * 8192 + o]   = s;
    }
}

// ---------------------------------------------------------------------------
// Decoder: tensor-core LSTM + fused readouts; ONE bar/step; dpr in regs.
// smem f-words: wloS 32768 | gsm 8256 | cs 2048 | red 512 | red2 256 | abuf 2048
// ---------------------------------------------------------------------------
#define DEC_SMEM ((32768 + 8256 + 2048 + 512 + 256 + 2048) * 4)

__global__ __launch_bounds__(THR_, 1)
void decoder_kernel(const float* __restrict__ dec_bih,
                    const float* __restrict__ dec_bhh,
                    const float* __restrict__ rec_w,  const float* __restrict__ rec_b,
                    const float* __restrict__ pred_w, const float* __restrict__ pred_b,
                    float* __restrict__ out_recon, float* __restrict__ out_pred) {
    extern __shared__ float smf[];
    uint2*    wloS = (uint2*)smf;
    float*    gsm  = smf + 32768;              // [16][516]
    float*    cs   = gsm + 8256;               // [16][128]
    float*    red  = cs + 2048;                // [2][16][16]
    float*    red2 = red + 512;                // [16][16]
    unsigned* abuf = (unsigned*)(red2 + 256);  // [2][1024] u32

    const int tid = threadIdx.x;
    const int w   = tid >> 5, lane = tid & 31;
    const int rowbase = blockIdx.x * R_;

    for (int i = tid; i < 16384; i += THR_) wloS[i] = g_decWF_lo[i];
    for (int i = tid; i < 2048;  i += THR_) abuf[i] = 0u;
    for (int i = tid; i < R_ * 128; i += THR_) cs[i] = g_cstar[rowbase * 128 + i];

    uint2 whi[4][8];
    #pragma unroll
    for (int a = 0; a < 4; a++)
        #pragma unroll
        for (int kt = 0; kt < 8; kt++)
            whi[a][kt] = g_decWF_hi[((w * 4 + a) * 8 + kt) * 32 + lane];

    const int row0 = lane >> 2;
    const int colq = (lane & 3) * 2;

    const int rr = lane & 15;
    const int j0 = w * 8 + (lane >> 4) * 4;
    const float rbv = rec_b[0], pbv = pred_b[0];
    float rw[4], pw2[4];
    int   idxf[4];
    #pragma unroll
    for (int m = 0; m < 4; m++) {
        rw[m]   = rec_w[j0 + m];
        pw2[m]  = pred_w[j0 + m];
        idxf[m] = fragidx_(rr, j0 + m);
    }
    unsigned short* ab16 = (unsigned short*)abuf;

    float cst[4] = {0.f, 0.f, 0.f, 0.f};
    __syncthreads();

    // ---- dpr GEMM (scalar, once): thread = permuted col tid; via gsm ----
    {
        const int orig = colorig_(tid);
        const float bt = dec_bih[orig] + dec_bhh[orig];
        float dpr[R_];
        #pragma unroll
        for (int r = 0; r < R_; r++) dpr[r] = bt;
        #pragma unroll 4
        for (int kb = 0; kb < 32; kb++) {
            float4 wv = g_decWihP[kb * G4_ + tid];
            #pragma unroll
            for (int r = 0; r < R_; r++) {
                float4 h4 = *reinterpret_cast<const float4*>(&cs[r * 128 + kb * 4]);
                dpr[r] = fmaf(wv.x, h4.x, dpr[r]);
                dpr[r] = fmaf(wv.y, h4.y, dpr[r]);
                dpr[r] = fmaf(wv.z, h4.z, dpr[r]);
                dpr[r] = fmaf(wv.w, h4.w, dpr[r]);
            }
        }
        #pragma unroll
        for (int r = 0; r < R_; r++) gsm[r * GS_ + tid] = dpr[r];
    }
    __syncwarp();

    float dfrag[4][4];
    #pragma unroll
    for (int a = 0; a < 4; a++) {
        int cb = (w * 4 + a) * 8 + colq;
        float2 d0 = *(const float2*)&gsm[row0 * GS_ + cb];
        float2 d8 = *(const float2*)&gsm[(row0 + 8) * GS_ + cb];
        dfrag[a][0] = d0.x; dfrag[a][1] = d0.y;
        dfrag[a][2] = d8.x; dfrag[a][3] = d8.y;
    }
    __syncwarp();

    for (int l = 0; l < L_; l++) {
        const int rp = l & 1;
        const int rbase = rp * 1024;
        const int wbase = (rp ^ 1) * 2048;

        // ---- phase 1: gates on tensor cores (2 MMAs/tile) ----
        float acc[4][4];
        #pragma unroll
        for (int a = 0; a < 4; a++)
            #pragma unroll
            for (int q = 0; q < 4; q++) acc[a][q] = dfrag[a][q];
        #pragma unroll
        for (int kt = 0; kt < 8; kt++) {
            uint4 ah = *(const uint4*)&abuf[rbase + (kt * 32 + lane) * 4];
            #pragma unroll
            for (int a = 0; a < 4; a++) {
                uint2 bl = wloS[((w * 4 + a) * 8 + kt) * 32 + lane];
                mma16816h(acc[a], ah.x, ah.y, ah.z, ah.w, whi[a][kt].x, whi[a][kt].y);
                mma16816h(acc[a], ah.x, ah.y, ah.z, ah.w, bl.x, bl.y);
            }
        }
        #pragma unroll
        for (int a = 0; a < 4; a++) {
            int cb = (w * 4 + a) * 8 + colq;
            *(float2*)&gsm[row0 * GS_ + cb]       = make_float2(acc[a][0], acc[a][1]);
            *(float2*)&gsm[(row0 + 8) * GS_ + cb] = make_float2(acc[a][2], acc[a][3]);
        }
        __syncwarp();

        // ---- phase 2: cell + fp16 h + readout partials ----
        float partial = 0.f, partial2 = 0.f;
        #pragma unroll
        for (int m = 0; m < 4; m++) {
            float4 g4 = *(const float4*)&gsm[rr * GS_ + 4 * (j0 + m)];
            float si = sig_(g4.x), sf = sig_(g4.y), so = sig_(g4.w);
            float tg = tanh_(g4.z);
            cst[m] = fmaf(sf, cst[m], si * tg);
            float h = so * tanh_(cst[m]);
            __half hx = __float2half_rn(h);
            ab16[wbase + idxf[m]] = *reinterpret_cast<unsigned short*>(&hx);
            partial = fmaf(h, rw[m], partial);
            if (l == L_ - 1) partial2 = fmaf(h, pw2[m], partial2);
        }
        partial += __shfl_xor_sync(0xffffffffu, partial, 16);
        if (lane < 16) red[rp * 256 + rr * 16 + w] = partial;
        if (l == L_ - 1) {
            partial2 += __shfl_xor_sync(0xffffffffu, partial2, 16);
            if (lane < 16) red2[rr * 16 + w] = partial2;
        }
        __syncthreads();

        // ---- phase 3: leaders write recon (and pred last step) ----
        if (tid < 16) {
            const float* r16 = &red[rp * 256 + tid * 16];
            float4 v0 = *(const float4*)&r16[0];
            float4 v1 = *(const float4*)&r16[4];
            float4 v2 = *(const float4*)&r16[8];
            float4 v3 = *(const float4*)&r16[12];
            float s = ((v0.x+v0.y)+(v0.z+v0.w)) + ((v1.x+v1.y)+(v1.z+v1.w))
                    + ((v2.x+v2.y)+(v2.z+v2.w)) + ((v3.x+v3.y)+(v3.z+v3.w)) + rbv;
            out_recon[(rowbase + tid) * 128 + l] = s;
            if (l == L_ - 1) {
                const float* q16 = &red2[tid * 16];
                float4 u0 = *(const float4*)&q16[0];
                float4 u1 = *(const float4*)&q16[4];
                float4 u2 = *(const float4*)&q16[8];
                float4 u3 = *(const float4*)&q16[12];
                float p2 = ((u0.x+u0.y)+(u0.z+u0.w)) + ((u1.x+u1.y)+(u1.z+u1.w))
                         + ((u2.x+u2.y)+(u2.z+u2.w)) + ((u3.x+u3.y)+(u3.z+u3.w)) + pbv;
                out_pred[rowbase + tid] = p2;
            }
        }
    }
}

// ---------------------------------------------------------------------------
extern "C" void kernel_launch(void* const* d_in, const int* in_sizes, int n_in,
                              void* d_out, int out_size) {
    const float* x        = (const float*)d_in[0];
    const float* enc_Wih  = (const float*)d_in[1];
    const float* enc_Whh  = (const float*)d_in[2];
    const float* enc_bih  = (const float*)d_in[3];
    const float* enc_bhh  = (const float*)d_in[4];
    const float* pool_w   = (const float*)d_in[5];
    const float* pool_b   = (const float*)d_in[6];
    const float* Wq       = (const float*)d_in[7];
    const float* bq       = (const float*)d_in[8];
    const float* Wk       = (const float*)d_in[9];
    const float* bk       = (const float*)d_in[10];
    const float* Wv       = (const float*)d_in[11];
    const float* bv       = (const float*)d_in[12];
    const float* dec_Wih  = (const float*)d_in[13];
    const float* dec_Whh  = (const float*)d_in[14];
    const float* dec_bih  = (const float*)d_in[15];
    const float* dec_bhh  = (const float*)d_in[16];
    const float* rec_w    = (const float*)d_in[17];
    const float* rec_b    = (const float*)d_in[18];
    const float* pred_w   = (const float*)d_in[19];
    const float* pred_b   = (const float*)d_in[20];

    float* out = (float*)d_out;
    float* out_recon = out;
    float* out_pred  = out + 262144;
    float* out_cstar = out + 264192;
    float* out_A     = out + 526336;

    cudaFuncSetAttribute(encoder_kernel, cudaFuncAttributeMaxDynamicSharedMemorySize, ENC_SMEM);
    cudaFuncSetAttribute(decoder_kernel, cudaFuncAttributeMaxDynamicSharedMemorySize, DEC_SMEM);
    cudaFuncSetAttribute(attn_kernel,    cudaFuncAttributeMaxDynamicSharedMemorySize, ATT_SMEM);

    pack_kernel<<<64, 256>>>(enc_Whh, dec_Whh, dec_Wih, Wq, Wk, Wv);
    encoder_kernel<<<NCTA_, THR_, ENC_SMEM>>>(x, enc_Wih, enc_bih, enc_bhh, pool_w, pool_b);
    attn_kernel<<<32, 256, ATT_SMEM>>>(bq, bk, bv, out_cstar, out_A);
    decoder_kernel<<<NCTA_, THR_, DEC_SMEM>>>(dec_bih, dec_bhh, rec_w, rec_b,
                                              pred_w, pred_b, out_recon, out_pred);
}

// round 12
// speedup vs baseline: 7.3640x; 1.0995x over previous
#include <cuda_runtime.h>
#include <cuda_fp16.h>
#include <math.h>

// ---------------------------------------------------------------------------
// G_OracleAD: enc-LSTM(+attn pool) -> spatial attention -> dec-LSTM(+readouts)
// B=32 N=64 L=128 H=128  BN=2048  4H=512
// d_out (fp32): recon[262144] | pred[2048] | c_star[262144] | A[131072]
// R12 = R11 resubmitted (infra failure, no measurement):
//      attention split into full-chip proj_kernel (Q,V + K-transposed to
//      gmem) + per-batch attn2_kernel. LSTM kernels unchanged from R10
//      (fp16 2-term W split, ownership-aligned warps, 1 barrier/step).
// ---------------------------------------------------------------------------

#define BN_   2048
#define L_    128
#define H_    128
#define G4_   512
#define R_    16
#define NCTA_ (BN_ / R_)   // 128
#define THR_  512
#define GS_   516          // padded gsm row stride (floats)

// device scratch
__device__ uint2  g_encWF_hi[16384];   // fp16x2 B-fragments (permuted cols)
__device__ uint2  g_encWF_lo[16384];
__device__ uint2  g_decWF_hi[16384];
__device__ uint2  g_decWF_lo[16384];
__device__ float4 g_decWihP[32 * G4_];
__device__ float  g_WqT[H_ * H_];
__device__ float  g_WkT[H_ * H_];
__device__ float  g_WvT[H_ * H_];
__device__ float  g_c[BN_ * H_];
__device__ float  g_cstar[BN_ * H_];
__device__ float  g_q[BN_ * H_];       // Q rows [bn][d]
__device__ float  g_v[BN_ * H_];       // V rows [bn][d]
__device__ float  g_kT[32 * H_ * 64];  // K transposed [b][d][n]

__device__ __forceinline__ int colorig_(int c) { return (c & 3) * 128 + (c >> 2); }

__device__ __forceinline__ float tanh_(float x) {
    float y;
    asm("tanh.approx.f32 %0, %1;" : "=f"(y) : "f"(x));
    return y;
}
__device__ __forceinline__ float sig_(float x) {
    return fmaf(tanh_(0.5f * x), 0.5f, 0.5f);
}
__device__ __forceinline__ void mma16816h(float* c, unsigned a0, unsigned a1,
                                          unsigned a2, unsigned a3,
                                          unsigned b0, unsigned b1) {
    asm("mma.sync.aligned.m16n8k16.row.col.f32.f16.f16.f32 "
        "{%0,%1,%2,%3}, {%4,%5,%6,%7}, {%8,%9}, {%0,%1,%2,%3};"
        : "+f"(c[0]), "+f"(c[1]), "+f"(c[2]), "+f"(c[3])
        : "r"(a0), "r"(a1), "r"(a2), "r"(a3), "r"(b0), "r"(b1));
}
__device__ __forceinline__ void split_fp16(float w, unsigned short& hi, unsigned short& lo) {
    __half bh = __float2half_rn(w);
    hi = *reinterpret_cast<unsigned short*>(&bh);
    float r = w - __half2float(bh);
    __half bl = __float2half_rn(r);
    lo = *reinterpret_cast<unsigned short*>(&bl);
}
__device__ __forceinline__ int fragidx_(int r, int j) {
    int kt = j >> 4, kl = j & 15;
    int lane_w = ((r & 7) << 2) | ((kl >> 1) & 3);
    int reg    = ((kl >> 3) << 1) | (r >> 3);
    return (((kt * 32 + lane_w) * 4 + reg) << 1) | (kl & 1);
}

// ---------------------------------------------------------------------------
__global__ void pack_kernel(const float* __restrict__ encWhh,
                            const float* __restrict__ decWhh,
                            const float* __restrict__ decWih,
                            const float* __restrict__ Wq,
                            const float* __restrict__ Wk,
                            const float* __restrict__ Wv) {
    int idx = blockIdx.x * blockDim.x + threadIdx.x;   // 0..16383
    {
        int kb = idx >> 9, c = idx & 511;
        int orig = (c & 3) * 128 + (c >> 2);
        int s  = orig * 128 + kb * 4;
        g_decWihP[idx] = make_float4(decWih[s], decWih[s+1], decWih[s+2], decWih[s+3]);
    }
    {
        int nt = idx >> 8, kt = (idx >> 5) & 7, l = idx & 31;
        int c  = nt * 8 + (l >> 2);
        int n  = (c & 3) * 128 + (c >> 2);
        int k0 = kt * 16 + (l & 3) * 2;
        unsigned short h0, l0, h1, l1, h2, l2, h3, l3;
        split_fp16(encWhh[n * 128 + k0],     h0, l0);
        split_fp16(encWhh[n * 128 + k0 + 1], h1, l1);
        split_fp16(encWhh[n * 128 + k0 + 8], h2, l2);
        split_fp16(encWhh[n * 128 + k0 + 9], h3, l3);
        g_encWF_hi[idx] = make_uint2((unsigned)h0 | ((unsigned)h1 << 16),
                                     (unsigned)h2 | ((unsigned)h3 << 16));
        g_encWF_lo[idx] = make_uint2((unsigned)l0 | ((unsigned)l1 << 16),
                                     (unsigned)l2 | ((unsigned)l3 << 16));
        split_fp16(decWhh[n * 128 + k0],     h0, l0);
        split_fp16(decWhh[n * 128 + k0 + 1], h1, l1);
        split_fp16(decWhh[n * 128 + k0 + 8], h2, l2);
        split_fp16(decWhh[n * 128 + k0 + 9], h3, l3);
        g_decWF_hi[idx] = make_uint2((unsigned)h0 | ((unsigned)h1 << 16),
                                     (unsigned)h2 | ((unsigned)h3 << 16));
        g_decWF_lo[idx] = make_uint2((unsigned)l0 | ((unsigned)l1 << 16),
                                     (unsigned)l2 | ((unsigned)l3 << 16));
    }
    {
        int kk = idx >> 7, d = idx & 127;
        g_WqT[idx] = Wq[d * 128 + kk];
        g_WkT[idx] = Wk[d * 128 + kk];
        g_WvT[idx] = Wv[d * 128 + kk];
    }
}

// ---------------------------------------------------------------------------
// Encoder: tensor-core LSTM + fused online-softmax pool; ONE bar/step.
// ---------------------------------------------------------------------------
#define ENC_SMEM ((32768 + 8256 + 2112 + 512 + 2048) * 4)

__global__ __launch_bounds__(THR_, 1)
void encoder_kernel(const float* __restrict__ x,
                    const float* __restrict__ enc_Wih,
                    const float* __restrict__ enc_bih,
                    const float* __restrict__ enc_bhh,
                    const float* __restrict__ pool_w,
                    const float* __restrict__ pool_b) {
    extern __shared__ float smf[];
    uint2*    wloS = (uint2*)smf;              // 16384 uint2
    float*    gsm  = smf + 32768;              // [16][516]
    float*    xs   = gsm + 8256;               // [16][132]
    float*    red  = xs + 2112;                // [2][16][16]
    unsigned* abuf = (unsigned*)(red + 512);   // [2][1024] u32 (fp16 A frags)

    const int tid = threadIdx.x;
    const int w   = tid >> 5, lane = tid & 31;
    const int rowbase = blockIdx.x * R_;

    for (int i = tid; i < 16384; i += THR_) wloS[i] = g_encWF_lo[i];
    for (int i = tid; i < 2048;  i += THR_) abuf[i] = 0u;
    for (int i = tid; i < R_ * 128; i += THR_)
        xs[(i >> 7) * 132 + (i & 127)] = x[rowbase * 128 + i];

    uint2 whi[4][8];
    #pragma unroll
    for (int a = 0; a < 4; a++)
        #pragma unroll
        for (int kt = 0; kt < 8; kt++)
            whi[a][kt] = g_encWF_hi[((w * 4 + a) * 8 + kt) * 32 + lane];

    const int row0 = lane >> 2;
    const int colq = (lane & 3) * 2;
    float wihr[8], btr[8];
    #pragma unroll
    for (int a = 0; a < 4; a++)
        #pragma unroll
        for (int hh = 0; hh < 2; hh++) {
            int col  = (w * 4 + a) * 8 + colq + hh;
            int orig = colorig_(col);
            wihr[a * 2 + hh] = enc_Wih[orig];
            btr[a * 2 + hh]  = enc_bih[orig] + enc_bhh[orig];
        }

    const int rr = lane & 15;
    const int j0 = w * 8 + (lane >> 4) * 4;
    const float pb = pool_b[0];
    float pw[4];
    int   idxf[4];
    #pragma unroll
    for (int m = 0; m < 4; m++) {
        pw[m]   = pool_w[j0 + m];
        idxf[m] = fragidx_(rr, j0 + m);
    }
    unsigned short* ab16 = (unsigned short*)abuf;

    float cst[4]  = {0.f, 0.f, 0.f, 0.f};
    float accj[4] = {0.f, 0.f, 0.f, 0.f};
    float msx = -INFINITY, zsx = 0.f;

    __syncthreads();

    for (int l = 0; l < L_; l++) {
        const int rp = l & 1;
        const int rbase = rp * 1024;        // u32
        const int wbase = (rp ^ 1) * 2048;  // shorts

        // ---- phase 1: gates on tensor cores (2 MMAs/tile) ----
        float acc[4][4];
        float xr0 = xs[row0 * 132 + l];
        float xr8 = xs[(row0 + 8) * 132 + l];
        #pragma unroll
        for (int a = 0; a < 4; a++) {
            acc[a][0] = fmaf(xr0, wihr[a*2],   btr[a*2]);
            acc[a][1] = fmaf(xr0, wihr[a*2+1], btr[a*2+1]);
            acc[a][2] = fmaf(xr8, wihr[a*2],   btr[a*2]);
            acc[a][3] = fmaf(xr8, wihr[a*2+1], btr[a*2+1]);
        }
        #pragma unroll
        for (int kt = 0; kt < 8; kt++) {
            uint4 ah = *(const uint4*)&abuf[rbase + (kt * 32 + lane) * 4];
            #pragma unroll
            for (int a = 0; a < 4; a++) {
                uint2 bl = wloS[((w * 4 + a) * 8 + kt) * 32 + lane];
                mma16816h(acc[a], ah.x, ah.y, ah.z, ah.w, whi[a][kt].x, whi[a][kt].y);
                mma16816h(acc[a], ah.x, ah.y, ah.z, ah.w, bl.x, bl.y);
            }
        }
        #pragma unroll
        for (int a = 0; a < 4; a++) {
            int cb = (w * 4 + a) * 8 + colq;
            *(float2*)&gsm[row0 * GS_ + cb]       = make_float2(acc[a][0], acc[a][1]);
            *(float2*)&gsm[(row0 + 8) * GS_ + cb] = make_float2(acc[a][2], acc[a][3]);
        }
        __syncwarp();

        // ---- phase 2: cell + fp16 h -> abuf[rp^1] + pool partial ----
        float hv[4], partial = 0.f;
        #pragma unroll
        for (int m = 0; m < 4; m++) {
            float4 g4 = *(const float4*)&gsm[rr * GS_ + 4 * (j0 + m)];  // i,f,g,o
            float si = sig_(g4.x), sf = sig_(g4.y), so = sig_(g4.w);
            float tg = tanh_(g4.z);
            cst[m] = fmaf(sf, cst[m], si * tg);
            float h = so * tanh_(cst[m]);
            hv[m] = h;
            __half hx = __float2half_rn(h);
            ab16[wbase + idxf[m]] = *reinterpret_cast<unsigned short*>(&hx);
            partial = fmaf(h, pw[m], partial);
        }
        partial += __shfl_xor_sync(0xffffffffu, partial, 16);
        if (lane < 16) red[rp * 256 + rr * 16 + w] = partial;
        __syncthreads();

        // ---- phase 3: replicated online softmax ----
        {
            const float* rr16 = &red[rp * 256 + rr * 16];
            float4 v0 = *(const float4*)&rr16[0];
            float4 v1 = *(const float4*)&rr16[4];
            float4 v2 = *(const float4*)&rr16[8];
            float4 v3 = *(const float4*)&rr16[12];
            float s = ((v0.x+v0.y)+(v0.z+v0.w)) + ((v1.x+v1.y)+(v1.z+v1.w))
                    + ((v2.x+v2.y)+(v2.z+v2.w)) + ((v3.x+v3.y)+(v3.z+v3.w)) + pb;
            float mn = fmaxf(msx, s);
            float f  = __expf(msx - mn);
            float wg = __expf(s - mn);
            zsx = zsx * f + wg;
            msx = mn;
            #pragma unroll
            for (int m = 0; m < 4; m++) accj[m] = fmaf(accj[m], f, wg * hv[m]);
        }
    }

    #pragma unroll
    for (int m = 0; m < 4; m++)
        g_c[(rowbase + rr) * 128 + j0 + m] = __fdividef(accj[m], zsx);
}

// ---------------------------------------------------------------------------
// proj_kernel: Q,K,V projections, full chip. grid 256 x 256 threads.
// thread -> (bn, d4): Q/V row-major float4; K transposed [b][d][n].
// ---------------------------------------------------------------------------
__global__ __launch_bounds__(256, 1)
void proj_kernel(const float* __restrict__ bq,
                 const float* __restrict__ bk,
                 const float* __restrict__ bv) {
    int idx = blockIdx.x * 256 + threadIdx.x;   // 0..65535
    int bn = idx >> 5;
    int d4 = idx & 31;
    const float* cr = g_c + bn * 128;

    const float4* WqT4 = reinterpret_cast<const float4*>(g_WqT);
    const float4* WkT4 = reinterpret_cast<const float4*>(g_WkT);
    const float4* WvT4 = reinterpret_cast<const float4*>(g_WvT);

    const float* bq4 = bq + d4 * 4;
    const float* bk4 = bk + d4 * 4;
    const float* bv4 = bv + d4 * 4;
    float4 aq = make_float4(bq4[0], bq4[1], bq4[2], bq4[3]);
    float4 ak = make_float4(bk4[0], bk4[1], bk4[2], bk4[3]);
    float4 av = make_float4(bv4[0], bv4[1], bv4[2], bv4[3]);

    #pragma unroll 4
    for (int kk = 0; kk < 128; kk++) {
        float cv = __ldg(&cr[kk]);
        float4 wq = WqT4[kk * 32 + d4];
        float4 wk = WkT4[kk * 32 + d4];
        float4 wv = WvT4[kk * 32 + d4];
        aq.x = fmaf(cv, wq.x, aq.x); aq.y = fmaf(cv, wq.y, aq.y);
        aq.z = fmaf(cv, wq.z, aq.z); aq.w = fmaf(cv, wq.w, aq.w);
        ak.x = fmaf(cv, wk.x, ak.x); ak.y = fmaf(cv, wk.y, ak.y);
        ak.z = fmaf(cv, wk.z, ak.z); ak.w = fmaf(cv, wk.w, ak.w);
        av.x = fmaf(cv, wv.x, av.x); av.y = fmaf(cv, wv.y, av.y);
        av.z = fmaf(cv, wv.z, av.z); av.w = fmaf(cv, wv.w, av.w);
    }
    *reinterpret_cast<float4*>(&g_q[bn * 128 + d4 * 4]) = aq;
    *reinterpret_cast<float4*>(&g_v[bn * 128 + d4 * 4]) = av;
    int b = bn >> 6, n = bn & 63;
    int dd = d4 * 4;
    g_kT[b * 8192 + (dd + 0) * 64 + n] = ak.x;
    g_kT[b * 8192 + (dd + 1) * 64 + n] = ak.y;
    g_kT[b * 8192 + (dd + 2) * 64 + n] = ak.z;
    g_kT[b * 8192 + (dd + 3) * 64 + n] = ak.w;
}

// ---------------------------------------------------------------------------
// attn2_kernel: per-batch scores + softmax + A@V. grid 32 x 512 threads.
// smem f-words: q_s 8192 | kTS 8192 | v_s 8192 | sc 4096
// ---------------------------------------------------------------------------
#define ATT_SMEM ((8192 * 3 + 4096) * 4)

__global__ __launch_bounds__(512, 1)
void attn2_kernel(float* __restrict__ out_cstar, float* __restrict__ out_A) {
    extern __shared__ float sm[];
    float* q_s = sm;              // [64][128]
    float* kTS = q_s + 8192;      // [128][64]
    float* v_s = kTS + 8192;      // [64][128]
    float* sc  = v_s + 8192;      // [64][64]
    const int b = blockIdx.x, tid = threadIdx.x;

    {
        const float4* q4 = reinterpret_cast<const float4*>(g_q + b * 8192);
        const float4* k4 = reinterpret_cast<const float4*>(g_kT + b * 8192);
        const float4* v4 = reinterpret_cast<const float4*>(g_v + b * 8192);
        for (int i = tid; i < 2048; i += 512) {
            *reinterpret_cast<float4*>(&q_s[i * 4]) = q4[i];
            *reinterpret_cast<float4*>(&kTS[i * 4]) = k4[i];
            *reinterpret_cast<float4*>(&v_s[i * 4]) = v4[i];
        }
    }
    __syncthreads();

    const float scale = 0.08838834764831845f;   // 1/sqrt(128)
    for (int o = tid; o < 4096; o += 512) {
        int n = o >> 6, m = o & 63;
        float s = 0.f;
        const float* qr = &q_s[n * 128];
        #pragma unroll 8
        for (int d = 0; d < 128; d++) s = fmaf(qr[d], kTS[d * 64 + m], s);
        sc[o] = s * scale;
    }
    __syncthreads();

    const int warp = tid >> 5, lane = tid & 31;
    for (int n = warp; n < 64; n += 16) {
        float v0 = sc[n * 64 + lane], v1 = sc[n * 64 + 32 + lane];
        float mx = fmaxf(v0, v1);
        #pragma unroll
        for (int o = 16; o; o >>= 1) mx = fmaxf(mx, __shfl_xor_sync(0xffffffffu, mx, o));
        float e0 = __expf(v0 - mx), e1 = __expf(v1 - mx);
        float ss = e0 + e1;
        #pragma unroll
        for (int o = 16; o; o >>= 1) ss += __shfl_xor_sync(0xffffffffu, ss, o);
        float inv = 1.f / ss;
        float a0 = e0 * inv, a1 = e1 * inv;
        sc[n * 64 + lane] = a0;
        sc[n * 64 + 32 + lane] = a1;
        out_A[b * 4096 + n * 64 + lane] = a0;
        out_A[b * 4096 + n * 64 + 32 + lane] = a1;
    }
    __syncthreads();

    for (int o = tid; o < 8192; o += 512) {
        int n = o >> 7, d = o & 127;
        float s = 0.f;
        const float* ar = &sc[n * 64];
        #pragma unroll 8
        for (int m = 0; m < 64; m++) s = fmaf(ar[m], v_s[m * 128 + d], s);
        out_cstar[b * 8192 + o] = s;
        g_cstar[b * 8192 + o]   = s;
    }
}

// ---------------------------------------------------------------------------
// Decoder: tensor-core LSTM + fused readouts; ONE bar/step; dpr in regs.
// ---------------------------------------------------------------------------
#define DEC_SMEM ((32768 + 8256 + 2048 + 512 + 256 + 2048) * 4)

__global__ __launch_bounds__(THR_, 1)
void decoder_kernel(const float* __restrict__ dec_bih,
                    const float* __restrict__ dec_bhh,
                    const float* __restrict__ rec_w,  const float* __restrict__ rec_b,
                    const float* __restrict__ pred_w, const float* __restrict__ pred_b,
                    float* __restrict__ out_recon, float* __restrict__ out_pred) {
    extern __shared__ float smf[];
    uint2*    wloS = (uint2*)smf;
    float*    gsm  = smf + 32768;              // [16][516]
    float*    cs   = gsm + 8256;               // [16][128]
    float*    red  = cs + 2048;                // [2][16][16]
    float*    red2 = red + 512;                // [16][16]
    unsigned* abuf = (unsigned*)(red2 + 256);  // [2][1024] u32

    const int tid = threadIdx.x;
    const int w   = tid >> 5, lane = tid & 31;
    const int rowbase = blockIdx.x * R_;

    for (int i = tid; i < 16384; i += THR_) wloS[i] = g_decWF_lo[i];
    for (int i = tid; i < 2048;  i += THR_) abuf[i] = 0u;
    for (int i = tid; i < R_ * 128; i += THR_) cs[i] = g_cstar[rowbase * 128 + i];

    uint2 whi[4][8];
    #pragma unroll
    for (int a = 0; a < 4; a++)
        #pragma unroll
        for (int kt = 0; kt < 8; kt++)
            whi[a][kt] = g_decWF_hi[((w * 4 + a) * 8 + kt) * 32 + lane];

    const int row0 = lane >> 2;
    const int colq = (lane & 3) * 2;

    const int rr = lane & 15;
    const int j0 = w * 8 + (lane >> 4) * 4;
    const float rbv = rec_b[0], pbv = pred_b[0];
    float rw[4], pw2[4];
    int   idxf[4];
    #pragma unroll
    for (int m = 0; m < 4; m++) {
        rw[m]   = rec_w[j0 + m];
        pw2[m]  = pred_w[j0 + m];
        idxf[m] = fragidx_(rr, j0 + m);
    }
    unsigned short* ab16 = (unsigned short*)abuf;

    float cst[4] = {0.f, 0.f, 0.f, 0.f};
    __syncthreads();

    // ---- dpr GEMM (scalar, once): thread = permuted col tid; via gsm ----
    {
        const int orig = colorig_(tid);
        const float bt = dec_bih[orig] + dec_bhh[orig];
        float dpr[R_];
        #pragma unroll
        for (int r = 0; r < R_; r++) dpr[r] = bt;
        #pragma unroll 4
        for (int kb = 0; kb < 32; kb++) {
            float4 wv = g_decWihP[kb * G4_ + tid];
            #pragma unroll
            for (int r = 0; r < R_; r++) {
                float4 h4 = *reinterpret_cast<const float4*>(&cs[r * 128 + kb * 4]);
                dpr[r] = fmaf(wv.x, h4.x, dpr[r]);
                dpr[r] = fmaf(wv.y, h4.y, dpr[r]);
                dpr[r] = fmaf(wv.z, h4.z, dpr[r]);
                dpr[r] = fmaf(wv.w, h4.w, dpr[r]);
            }
        }
        #pragma unroll
        for (int r = 0; r < R_; r++) gsm[r * GS_ + tid] = dpr[r];
    }
    __syncwarp();

    float dfrag[4][4];
    #pragma unroll
    for (int a = 0; a < 4; a++) {
        int cb = (w * 4 + a) * 8 + colq;
        float2 d0 = *(const float2*)&gsm[row0 * GS_ + cb];
        float2 d8 = *(const float2*)&gsm[(row0 + 8) * GS_ + cb];
        dfrag[a][0] = d0.x; dfrag[a][1] = d0.y;
        dfrag[a][2] = d8.x; dfrag[a][3] = d8.y;
    }
    __syncwarp();

    for (int l = 0; l < L_; l++) {
        const int rp = l & 1;
        const int rbase = rp * 1024;
        const int wbase = (rp ^ 1) * 2048;

        // ---- phase 1: gates on tensor cores (2 MMAs/tile) ----
        float acc[4][4];
        #pragma unroll
        for (int a = 0; a < 4; a++)
            #pragma unroll
            for (int q = 0; q < 4; q++) acc[a][q] = dfrag[a][q];
        #pragma unroll
        for (int kt = 0; kt < 8; kt++) {
            uint4 ah = *(const uint4*)&abuf[rbase + (kt * 32 + lane) * 4];
            #pragma unroll
            for (int a = 0; a < 4; a++) {
                uint2 bl = wloS[((w * 4 + a) * 8 + kt) * 32 + lane];
                mma16816h(acc[a], ah.x, ah.y, ah.z, ah.w, whi[a][kt].x, whi[a][kt].y);
                mma16816h(acc[a], ah.x, ah.y, ah.z, ah.w, bl.x, bl.y);
            }
        }
        #pragma unroll
        for (int a = 0; a < 4; a++) {
            int cb = (w * 4 + a) * 8 + colq;
            *(float2*)&gsm[row0 * GS_ + cb]       = make_float2(acc[a][0], acc[a][1]);
            *(float2*)&gsm[(row0 + 8) * GS_ + cb] = make_float2(acc[a][2], acc[a][3]);
        }
        __syncwarp();

        // ---- phase 2: cell + fp16 h + readout partials ----
        float partial = 0.f, partial2 = 0.f;
        #pragma unroll
        for (int m = 0; m < 4; m++) {
            float4 g4 = *(const float4*)&gsm[rr * GS_ + 4 * (j0 + m)];
            float si = sig_(g4.x), sf = sig_(g4.y), so = sig_(g4.w);
            float tg = tanh_(g4.z);
            cst[m] = fmaf(sf, cst[m], si * tg);
            float h = so * tanh_(cst[m]);
            __half hx = __float2half_rn(h);
            ab16[wbase + idxf[m]] = *reinterpret_cast<unsigned short*>(&hx);
            partial = fmaf(h, rw[m], partial);
            if (l == L_ - 1) partial2 = fmaf(h, pw2[m], partial2);
        }
        partial += __shfl_xor_sync(0xffffffffu, partial, 16);
        if (lane < 16) red[rp * 256 + rr * 16 + w] = partial;
        if (l == L_ - 1) {
            partial2 += __shfl_xor_sync(0xffffffffu, partial2, 16);
            if (lane < 16) red2[rr * 16 + w] = partial2;
        }
        __syncthreads();

        // ---- phase 3: leaders write recon (and pred last step) ----
        if (tid < 16) {
            const float* r16 = &red[rp * 256 + tid * 16];
            float4 v0 = *(const float4*)&r16[0];
            float4 v1 = *(const float4*)&r16[4];
            float4 v2 = *(const float4*)&r16[8];
            float4 v3 = *(const float4*)&r16[12];
            float s = ((v0.x+v0.y)+(v0.z+v0.w)) + ((v1.x+v1.y)+(v1.z+v1.w))
                    + ((v2.x+v2.y)+(v2.z+v2.w)) + ((v3.x+v3.y)+(v3.z+v3.w)) + rbv;
            out_recon[(rowbase + tid) * 128 + l] = s;
            if (l == L_ - 1) {
                const float* q16 = &red2[tid * 16];
                float4 u0 = *(const float4*)&q16[0];
                float4 u1 = *(const float4*)&q16[4];
                float4 u2 = *(const float4*)&q16[8];
                float4 u3 = *(const float4*)&q16[12];
                float p2 = ((u0.x+u0.y)+(u0.z+u0.w)) + ((u1.x+u1.y)+(u1.z+u1.w))
                         + ((u2.x+u2.y)+(u2.z+u2.w)) + ((u3.x+u3.y)+(u3.z+u3.w)) + pbv;
                out_pred[rowbase + tid] = p2;
            }
        }
    }
}

// ---------------------------------------------------------------------------
extern "C" void kernel_launch(void* const* d_in, const int* in_sizes, int n_in,
                              void* d_out, int out_size) {
    const float* x        = (const float*)d_in[0];
    const float* enc_Wih  = (const float*)d_in[1];
    const float* enc_Whh  = (const float*)d_in[2];
    const float* enc_bih  = (const float*)d_in[3];
    const float* enc_bhh  = (const float*)d_in[4];
    const float* pool_w   = (const float*)d_in[5];
    const float* pool_b   = (const float*)d_in[6];
    const float* Wq       = (const float*)d_in[7];
    const float* bq       = (const float*)d_in[8];
    const float* Wk       = (const float*)d_in[9];
    const float* bk       = (const float*)d_in[10];
    const float* Wv       = (const float*)d_in[11];
    const float* bv       = (const float*)d_in[12];
    const float* dec_Wih  = (const float*)d_in[13];
    const float* dec_Whh  = (const float*)d_in[14];
    const float* dec_bih  = (const float*)d_in[15];
    const float* dec_bhh  = (const float*)d_in[16];
    const float* rec_w    = (const float*)d_in[17];
    const float* rec_b    = (const float*)d_in[18];
    const float* pred_w   = (const float*)d_in[19];
    const float* pred_b   = (const float*)d_in[20];

    float* out = (float*)d_out;
    float* out_recon = out;
    float* out_pred  = out + 262144;
    float* out_cstar = out + 264192;
    float* out_A     = out + 526336;

    cudaFuncSetAttribute(encoder_kernel, cudaFuncAttributeMaxDynamicSharedMemorySize, ENC_SMEM);
    cudaFuncSetAttribute(decoder_kernel, cudaFuncAttributeMaxDynamicSharedMemorySize, DEC_SMEM);
    cudaFuncSetAttribute(attn2_kernel,   cudaFuncAttributeMaxDynamicSharedMemorySize, ATT_SMEM);

    pack_kernel<<<64, 256>>>(enc_Whh, dec_Whh, dec_Wih, Wq, Wk, Wv);
    encoder_kernel<<<NCTA_, THR_, ENC_SMEM>>>(x, enc_Wih, enc_bih, enc_bhh, pool_w, pool_b);
    proj_kernel<<<256, 256>>>(bq, bk, bv);
    attn2_kernel<<<32, 512, ATT_SMEM>>>(out_cstar, out_A);
    decoder_kernel<<<NCTA_, THR_, DEC_SMEM>>>(dec_bih, dec_bhh, rec_w, rec_b,
                                              pred_w, pred_b, out_recon, out_pred);
}

// round 13
// speedup vs baseline: 10.2895x; 1.3973x over previous
#include <cuda_runtime.h>
#include <cuda_fp16.h>
#include <math.h>

// ---------------------------------------------------------------------------
// G_OracleAD: enc-LSTM(+attn pool) -> spatial attention -> dec-LSTM(+readouts)
// B=32 N=64 L=128 H=128  BN=2048  4H=512
// d_out (fp32): recon[262144] | pred[2048] | c_star[262144] | A[131072]
// R13: single-fp16 W_hh (lo term dropped) -> 1 MMA per tile (tensor work
//      halved); attn2 spread over 128 CTAs (4 Q-tiles x 32 batches).
//      Everything else as R12.
// ---------------------------------------------------------------------------

#define BN_   2048
#define L_    128
#define H_    128
#define G4_   512
#define R_    16
#define NCTA_ (BN_ / R_)   // 128
#define THR_  512
#define GS_   516          // padded gsm row stride (floats)

// device scratch
__device__ uint2  g_encWF[16384];      // fp16x2 B-fragments (permuted cols)
__device__ uint2  g_decWF[16384];
__device__ float4 g_decWihP[32 * G4_];
__device__ float  g_WqT[H_ * H_];
__device__ float  g_WkT[H_ * H_];
__device__ float  g_WvT[H_ * H_];
__device__ float  g_c[BN_ * H_];
__device__ float  g_cstar[BN_ * H_];
__device__ float  g_q[BN_ * H_];       // Q rows [bn][d]
__device__ float  g_v[BN_ * H_];       // V rows [bn][d]
__device__ float  g_kT[32 * H_ * 64];  // K transposed [b][d][n]

__device__ __forceinline__ int colorig_(int c) { return (c & 3) * 128 + (c >> 2); }

__device__ __forceinline__ float tanh_(float x) {
    float y;
    asm("tanh.approx.f32 %0, %1;" : "=f"(y) : "f"(x));
    return y;
}
__device__ __forceinline__ float sig_(float x) {
    return fmaf(tanh_(0.5f * x), 0.5f, 0.5f);
}
__device__ __forceinline__ void mma16816h(float* c, unsigned a0, unsigned a1,
                                          unsigned a2, unsigned a3,
                                          unsigned b0, unsigned b1) {
    asm("mma.sync.aligned.m16n8k16.row.col.f32.f16.f16.f32 "
        "{%0,%1,%2,%3}, {%4,%5,%6,%7}, {%8,%9}, {%0,%1,%2,%3};"
        : "+f"(c[0]), "+f"(c[1]), "+f"(c[2]), "+f"(c[3])
        : "r"(a0), "r"(a1), "r"(a2), "r"(a3), "r"(b0), "r"(b1));
}
__device__ __forceinline__ unsigned short f2h_(float w) {
    __half b = __float2half_rn(w);
    return *reinterpret_cast<unsigned short*>(&b);
}
__device__ __forceinline__ int fragidx_(int r, int j) {
    int kt = j >> 4, kl = j & 15;
    int lane_w = ((r & 7) << 2) | ((kl >> 1) & 3);
    int reg    = ((kl >> 3) << 1) | (r >> 3);
    return (((kt * 32 + lane_w) * 4 + reg) << 1) | (kl & 1);
}

// ---------------------------------------------------------------------------
__global__ void pack_kernel(const float* __restrict__ encWhh,
                            const float* __restrict__ decWhh,
                            const float* __restrict__ decWih,
                            const float* __restrict__ Wq,
                            const float* __restrict__ Wk,
                            const float* __restrict__ Wv) {
    int idx = blockIdx.x * blockDim.x + threadIdx.x;   // 0..16383
    {
        int kb = idx >> 9, c = idx & 511;
        int orig = (c & 3) * 128 + (c >> 2);
        int s  = orig * 128 + kb * 4;
        g_decWihP[idx] = make_float4(decWih[s], decWih[s+1], decWih[s+2], decWih[s+3]);
    }
    {
        int nt = idx >> 8, kt = (idx >> 5) & 7, l = idx & 31;
        int c  = nt * 8 + (l >> 2);
        int n  = (c & 3) * 128 + (c >> 2);
        int k0 = kt * 16 + (l & 3) * 2;
        unsigned short h0 = f2h_(encWhh[n * 128 + k0]);
        unsigned short h1 = f2h_(encWhh[n * 128 + k0 + 1]);
        unsigned short h2 = f2h_(encWhh[n * 128 + k0 + 8]);
        unsigned short h3 = f2h_(encWhh[n * 128 + k0 + 9]);
        g_encWF[idx] = make_uint2((unsigned)h0 | ((unsigned)h1 << 16),
                                  (unsigned)h2 | ((unsigned)h3 << 16));
        h0 = f2h_(decWhh[n * 128 + k0]);
        h1 = f2h_(decWhh[n * 128 + k0 + 1]);
        h2 = f2h_(decWhh[n * 128 + k0 + 8]);
        h3 = f2h_(decWhh[n * 128 + k0 + 9]);
        g_decWF[idx] = make_uint2((unsigned)h0 | ((unsigned)h1 << 16),
                                  (unsigned)h2 | ((unsigned)h3 << 16));
    }
    {
        int kk = idx >> 7, d = idx & 127;
        g_WqT[idx] = Wq[d * 128 + kk];
        g_WkT[idx] = Wk[d * 128 + kk];
        g_WvT[idx] = Wv[d * 128 + kk];
    }
}

// ---------------------------------------------------------------------------
// Encoder: tensor-core LSTM + fused online-softmax pool; ONE bar/step.
// smem f-words: gsm 8256 | xs 2112 | red 512 | abuf 2048
// ---------------------------------------------------------------------------
#define ENC_SMEM ((8256 + 2112 + 512 + 2048) * 4)

__global__ __launch_bounds__(THR_, 1)
void encoder_kernel(const float* __restrict__ x,
                    const float* __restrict__ enc_Wih,
                    const float* __restrict__ enc_bih,
                    const float* __restrict__ enc_bhh,
                    const float* __restrict__ pool_w,
                    const float* __restrict__ pool_b) {
    extern __shared__ float smf[];
    float*    gsm  = smf;                      // [16][516]
    float*    xs   = gsm + 8256;               // [16][132]
    float*    red  = xs + 2112;                // [2][16][16]
    unsigned* abuf = (unsigned*)(red + 512);   // [2][1024] u32 (fp16 A frags)

    const int tid = threadIdx.x;
    const int w   = tid >> 5, lane = tid & 31;
    const int rowbase = blockIdx.x * R_;

    for (int i = tid; i < 2048;  i += THR_) abuf[i] = 0u;
    for (int i = tid; i < R_ * 128; i += THR_)
        xs[(i >> 7) * 132 + (i & 127)] = x[rowbase * 128 + i];

    uint2 whi[4][8];
    #pragma unroll
    for (int a = 0; a < 4; a++)
        #pragma unroll
        for (int kt = 0; kt < 8; kt++)
            whi[a][kt] = g_encWF[((w * 4 + a) * 8 + kt) * 32 + lane];

    const int row0 = lane >> 2;
    const int colq = (lane & 3) * 2;
    float wihr[8], btr[8];
    #pragma unroll
    for (int a = 0; a < 4; a++)
        #pragma unroll
        for (int hh = 0; hh < 2; hh++) {
            int col  = (w * 4 + a) * 8 + colq + hh;
            int orig = colorig_(col);
            wihr[a * 2 + hh] = enc_Wih[orig];
            btr[a * 2 + hh]  = enc_bih[orig] + enc_bhh[orig];
        }

    const int rr = lane & 15;
    const int j0 = w * 8 + (lane >> 4) * 4;
    const float pb = pool_b[0];
    float pw[4];
    int   idxf[4];
    #pragma unroll
    for (int m = 0; m < 4; m++) {
        pw[m]   = pool_w[j0 + m];
        idxf[m] = fragidx_(rr, j0 + m);
    }
    unsigned short* ab16 = (unsigned short*)abuf;

    float cst[4]  = {0.f, 0.f, 0.f, 0.f};
    float accj[4] = {0.f, 0.f, 0.f, 0.f};
    float msx = -INFINITY, zsx = 0.f;

    __syncthreads();

    for (int l = 0; l < L_; l++) {
        const int rp = l & 1;
        const int rbase = rp * 1024;        // u32
        const int wbase = (rp ^ 1) * 2048;  // shorts

        // ---- phase 1: gates on tensor cores (1 MMA/tile) ----
        float acc[4][4];
        float xr0 = xs[row0 * 132 + l];
        float xr8 = xs[(row0 + 8) * 132 + l];
        #pragma unroll
        for (int a = 0; a < 4; a++) {
            acc[a][0] = fmaf(xr0, wihr[a*2],   btr[a*2]);
            acc[a][1] = fmaf(xr0, wihr[a*2+1], btr[a*2+1]);
            acc[a][2] = fmaf(xr8, wihr[a*2],   btr[a*2]);
            acc[a][3] = fmaf(xr8, wihr[a*2+1], btr[a*2+1]);
        }
        #pragma unroll
        for (int kt = 0; kt < 8; kt++) {
            uint4 ah = *(const uint4*)&abuf[rbase + (kt * 32 + lane) * 4];
            #pragma unroll
            for (int a = 0; a < 4; a++)
                mma16816h(acc[a], ah.x, ah.y, ah.z, ah.w, whi[a][kt].x, whi[a][kt].y);
        }
        #pragma unroll
        for (int a = 0; a < 4; a++) {
            int cb = (w * 4 + a) * 8 + colq;
            *(float2*)&gsm[row0 * GS_ + cb]       = make_float2(acc[a][0], acc[a][1]);
            *(float2*)&gsm[(row0 + 8) * GS_ + cb] = make_float2(acc[a][2], acc[a][3]);
        }
        __syncwarp();

        // ---- phase 2: cell + fp16 h -> abuf[rp^1] + pool partial ----
        float hv[4], partial = 0.f;
        #pragma unroll
        for (int m = 0; m < 4; m++) {
            float4 g4 = *(const float4*)&gsm[rr * GS_ + 4 * (j0 + m)];  // i,f,g,o
            float si = sig_(g4.x), sf = sig_(g4.y), so = sig_(g4.w);
            float tg = tanh_(g4.z);
            cst[m] = fmaf(sf, cst[m], si * tg);
            float h = so * tanh_(cst[m]);
            hv[m] = h;
            ab16[wbase + idxf[m]] = f2h_(h);
            partial = fmaf(h, pw[m], partial);
        }
        partial += __shfl_xor_sync(0xffffffffu, partial, 16);
        if (lane < 16) red[rp * 256 + rr * 16 + w] = partial;
        __syncthreads();

        // ---- phase 3: replicated online softmax ----
        {
            const float* rr16 = &red[rp * 256 + rr * 16];
            float4 v0 = *(const float4*)&rr16[0];
            float4 v1 = *(const float4*)&rr16[4];
            float4 v2 = *(const float4*)&rr16[8];
            float4 v3 = *(const float4*)&rr16[12];
            float s = ((v0.x+v0.y)+(v0.z+v0.w)) + ((v1.x+v1.y)+(v1.z+v1.w))
                    + ((v2.x+v2.y)+(v2.z+v2.w)) + ((v3.x+v3.y)+(v3.z+v3.w)) + pb;
            float mn = fmaxf(msx, s);
            float f  = __expf(msx - mn);
            float wg = __expf(s - mn);
            zsx = zsx * f + wg;
            msx = mn;
            #pragma unroll
            for (int m = 0; m < 4; m++) accj[m] = fmaf(accj[m], f, wg * hv[m]);
        }
    }

    #pragma unroll
    for (int m = 0; m < 4; m++)
        g_c[(rowbase + rr) * 128 + j0 + m] = __fdividef(accj[m], zsx);
}

// ---------------------------------------------------------------------------
// proj_kernel: Q,K,V projections, full chip. grid 256 x 256 threads.
// ---------------------------------------------------------------------------
__global__ __launch_bounds__(256, 1)
void proj_kernel(const float* __restrict__ bq,
                 const float* __restrict__ bk,
                 const float* __restrict__ bv) {
    int idx = blockIdx.x * 256 + threadIdx.x;   // 0..65535
    int bn = idx >> 5;
    int d4 = idx & 31;
    const float* cr = g_c + bn * 128;

    const float4* WqT4 = reinterpret_cast<const float4*>(g_WqT);
    const float4* WkT4 = reinterpret_cast<const float4*>(g_WkT);
    const float4* WvT4 = reinterpret_cast<const float4*>(g_WvT);

    const float* bq4 = bq + d4 * 4;
    const float* bk4 = bk + d4 * 4;
    const float* bv4 = bv + d4 * 4;
    float4 aq = make_float4(bq4[0], bq4[1], bq4[2], bq4[3]);
    float4 ak = make_float4(bk4[0], bk4[1], bk4[2], bk4[3]);
    float4 av = make_float4(bv4[0], bv4[1], bv4[2], bv4[3]);

    #pragma unroll 4
    for (int kk = 0; kk < 128; kk++) {
        float cv = __ldg(&cr[kk]);
        float4 wq = WqT4[kk * 32 + d4];
        float4 wk = WkT4[kk * 32 + d4];
        float4 wv = WvT4[kk * 32 + d4];
        aq.x = fmaf(cv, wq.x, aq.x); aq.y = fmaf(cv, wq.y, aq.y);
        aq.z = fmaf(cv, wq.z, aq.z); aq.w = fmaf(cv, wq.w, aq.w);
        ak.x = fmaf(cv, wk.x, ak.x); ak.y = fmaf(cv, wk.y, ak.y);
        ak.z = fmaf(cv, wk.z, ak.z); ak.w = fmaf(cv, wk.w, ak.w);
        av.x = fmaf(cv, wv.x, av.x); av.y = fmaf(cv, wv.y, av.y);
        av.z = fmaf(cv, wv.z, av.z); av.w = fmaf(cv, wv.w, av.w);
    }
    *reinterpret_cast<float4*>(&g_q[bn * 128 + d4 * 4]) = aq;
    *reinterpret_cast<float4*>(&g_v[bn * 128 + d4 * 4]) = av;
    int b = bn >> 6, n = bn & 63;
    int dd = d4 * 4;
    g_kT[b * 8192 + (dd + 0) * 64 + n] = ak.x;
    g_kT[b * 8192 + (dd + 1) * 64 + n] = ak.y;
    g_kT[b * 8192 + (dd + 2) * 64 + n] = ak.z;
    g_kT[b * 8192 + (dd + 3) * 64 + n] = ak.w;
}

// ---------------------------------------------------------------------------
// attn2_kernel: scores + softmax + A@V. grid 128 (4 Q-tiles x 32 b), 256 thr.
// smem f-words: q_s 2048 | kTS 8192 | v_s 8192 | sc 1024
// ---------------------------------------------------------------------------
#define ATT_SMEM ((2048 + 8192 + 8192 + 1024) * 4)

__global__ __launch_bounds__(256, 1)
void attn2_kernel(float* __restrict__ out_cstar, float* __restrict__ out_A) {
    extern __shared__ float sm[];
    float* q_s = sm;              // [16][128]
    float* kTS = q_s + 2048;      // [128][64]
    float* v_s = kTS + 8192;      // [64][128]
    float* sc  = v_s + 8192;      // [16][64]
    const int b  = blockIdx.x >> 2;
    const int n0 = (blockIdx.x & 3) * 16;
    const int tid = threadIdx.x;

    {
        const float4* q4 = reinterpret_cast<const float4*>(g_q + b * 8192 + n0 * 128);
        const float4* k4 = reinterpret_cast<const float4*>(g_kT + b * 8192);
        const float4* v4 = reinterpret_cast<const float4*>(g_v + b * 8192);
        for (int i = tid; i < 512;  i += 256) *reinterpret_cast<float4*>(&q_s[i * 4]) = q4[i];
        for (int i = tid; i < 2048; i += 256) *reinterpret_cast<float4*>(&kTS[i * 4]) = k4[i];
        for (int i = tid; i < 2048; i += 256) *reinterpret_cast<float4*>(&v_s[i * 4]) = v4[i];
    }
    __syncthreads();

    const float scale = 0.08838834764831845f;   // 1/sqrt(128)
    for (int o = tid; o < 1024; o += 256) {
        int n = o >> 6, m = o & 63;
        float s = 0.f;
        const float* qr = &q_s[n * 128];
        #pragma unroll 8
        for (int d = 0; d < 128; d++) s = fmaf(qr[d], kTS[d * 64 + m], s);
        sc[o] = s * scale;
    }
    __syncthreads();

    const int warp = tid >> 5, lane = tid & 31;
    for (int n = warp; n < 16; n += 8) {
        float v0 = sc[n * 64 + lane], v1 = sc[n * 64 + 32 + lane];
        float mx = fmaxf(v0, v1);
        #pragma unroll
        for (int o = 16; o; o >>= 1) mx = fmaxf(mx, __shfl_xor_sync(0xffffffffu, mx, o));
        float e0 = __expf(v0 - mx), e1 = __expf(v1 - mx);
        float ss = e0 + e1;
        #pragma unroll
        for (int o = 16; o; o >>= 1) ss += __shfl_xor_sync(0xffffffffu, ss, o);
        float inv = 1.f / ss;
        float a0 = e0 * inv, a1 = e1 * inv;
        sc[n * 64 + lane] = a0;
        sc[n * 64 + 32 + lane] = a1;
        out_A[b * 4096 + (n0 + n) * 64 + lane] = a0;
        out_A[b * 4096 + (n0 + n) * 64 + 32 + lane] = a1;
    }
    __syncthreads();

    for (int o = tid; o < 2048; o += 256) {
        int n = o >> 7, d = o & 127;
        float s = 0.f;
        const float* ar = &sc[n * 64];
        #pragma unroll 8
        for (int m = 0; m < 64; m++) s = fmaf(ar[m], v_s[m * 128 + d], s);
        out_cstar[b * 8192 + (n0 + n) * 128 + d] = s;
        g_cstar[b * 8192 + (n0 + n) * 128 + d]   = s;
    }
}

// ---------------------------------------------------------------------------
// Decoder: tensor-core LSTM + fused readouts; ONE bar/step; dpr in regs.
// smem f-words: gsm 8256 | cs 2048 | red 512 | red2 256 | abuf 2048
// ---------------------------------------------------------------------------
#define DEC_SMEM ((8256 + 2048 + 512 + 256 + 2048) * 4)

__global__ __launch_bounds__(THR_, 1)
void decoder_kernel(const float* __restrict__ dec_bih,
                    const float* __restrict__ dec_bhh,
                    const float* __restrict__ rec_w,  const float* __restrict__ rec_b,
                    const float* __restrict__ pred_w, const float* __restrict__ pred_b,
                    float* __restrict__ out_recon, float* __restrict__ out_pred) {
    extern __shared__ float smf[];
    float*    gsm  = smf;                      // [16][516]
    float*    cs   = gsm + 8256;               // [16][128]
    float*    red  = cs + 2048;                // [2][16][16]
    float*    red2 = red + 512;                // [16][16]
    unsigned* abuf = (unsigned*)(red2 + 256);  // [2][1024] u32

    const int tid = threadIdx.x;
    const int w   = tid >> 5, lane = tid & 31;
    const int rowbase = blockIdx.x * R_;

    for (int i = tid; i < 2048;  i += THR_) abuf[i] = 0u;
    for (int i = tid; i < R_ * 128; i += THR_) cs[i] = g_cstar[rowbase * 128 + i];

    uint2 whi[4][8];
    #pragma unroll
    for (int a = 0; a < 4; a++)
        #pragma unroll
        for (int kt = 0; kt < 8; kt++)
            whi[a][kt] = g_decWF[((w * 4 + a) * 8 + kt) * 32 + lane];

    const int row0 = lane >> 2;
    const int colq = (lane & 3) * 2;

    const int rr = lane & 15;
    const int j0 = w * 8 + (lane >> 4) * 4;
    const float rbv = rec_b[0], pbv = pred_b[0];
    float rw[4], pw2[4];
    int   idxf[4];
    #pragma unroll
    for (int m = 0; m < 4; m++) {
        rw[m]   = rec_w[j0 + m];
        pw2[m]  = pred_w[j0 + m];
        idxf[m] = fragidx_(rr, j0 + m);
    }
    unsigned short* ab16 = (unsigned short*)abuf;

    float cst[4] = {0.f, 0.f, 0.f, 0.f};
    __syncthreads();

    // ---- dpr GEMM (scalar, once): thread = permuted col tid; via gsm ----
    {
        const int orig = colorig_(tid);
        const float bt = dec_bih[orig] + dec_bhh[orig];
        float dpr[R_];
        #pragma unroll
        for (int r = 0; r < R_; r++) dpr[r] = bt;
        #pragma unroll 4
        for (int kb = 0; kb < 32; kb++) {
            float4 wv = g_decWihP[kb * G4_ + tid];
            #pragma unroll
            for (int r = 0; r < R_; r++) {
                float4 h4 = *reinterpret_cast<const float4*>(&cs[r * 128 + kb * 4]);
                dpr[r] = fmaf(wv.x, h4.x, dpr[r]);
                dpr[r] = fmaf(wv.y, h4.y, dpr[r]);
                dpr[r] = fmaf(wv.z, h4.z, dpr[r]);
                dpr[r] = fmaf(wv.w, h4.w, dpr[r]);
            }
        }
        #pragma unroll
        for (int r = 0; r < R_; r++) gsm[r * GS_ + tid] = dpr[r];
    }
    __syncwarp();

    float dfrag[4][4];
    #pragma unroll
    for (int a = 0; a < 4; a++) {
        int cb = (w * 4 + a) * 8 + colq;
        float2 d0 = *(const float2*)&gsm[row0 * GS_ + cb];
        float2 d8 = *(const float2*)&gsm[(row0 + 8) * GS_ + cb];
        dfrag[a][0] = d0.x; dfrag[a][1] = d0.y;
        dfrag[a][2] = d8.x; dfrag[a][3] = d8.y;
    }
    __syncwarp();

    for (int l = 0; l < L_; l++) {
        const int rp = l & 1;
        const int rbase = rp * 1024;
        const int wbase = (rp ^ 1) * 2048;

        // ---- phase 1: gates on tensor cores (1 MMA/tile) ----
        float acc[4][4];
        #pragma unroll
        for (int a = 0; a < 4; a++)
            #pragma unroll
            for (int q = 0; q < 4; q++) acc[a][q] = dfrag[a][q];
        #pragma unroll
        for (int kt = 0; kt < 8; kt++) {
            uint4 ah = *(const uint4*)&abuf[rbase + (kt * 32 + lane) * 4];
            #pragma unroll
            for (int a = 0; a < 4; a++)
                mma16816h(acc[a], ah.x, ah.y, ah.z, ah.w, whi[a][kt].x, whi[a][kt].y);
        }
        #pragma unroll
        for (int a = 0; a < 4; a++) {
            int cb = (w * 4 + a) * 8 + colq;
            *(float2*)&gsm[row0 * GS_ + cb]       = make_float2(acc[a][0], acc[a][1]);
            *(float2*)&gsm[(row0 + 8) * GS_ + cb] = make_float2(acc[a][2], acc[a][3]);
        }
        __syncwarp();

        // ---- phase 2: cell + fp16 h + readout partials ----
        float partial = 0.f, partial2 = 0.f;
        #pragma unroll
        for (int m = 0; m < 4; m++) {
            float4 g4 = *(const float4*)&gsm[rr * GS_ + 4 * (j0 + m)];
            float si = sig_(g4.x), sf = sig_(g4.y), so = sig_(g4.w);
            float tg = tanh_(g4.z);
            cst[m] = fmaf(sf, cst[m], si * tg);
            float h = so * tanh_(cst[m]);
            ab16[wbase + idxf[m]] = f2h_(h);
            partial = fmaf(h, rw[m], partial);
            if (l == L_ - 1) partial2 = fmaf(h, pw2[m], partial2);
        }
        partial += __shfl_xor_sync(0xffffffffu, partial, 16);
        if (lane < 16) red[rp * 256 + rr * 16 + w] = partial;
        if (l == L_ - 1) {
            partial2 += __shfl_xor_sync(0xffffffffu, partial2, 16);
            if (lane < 16) red2[rr * 16 + w] = partial2;
        }
        __syncthreads();

        // ---- phase 3: leaders write recon (and pred last step) ----
        if (tid < 16) {
            const float* r16 = &red[rp * 256 + tid * 16];
            float4 v0 = *(const float4*)&r16[0];
            float4 v1 = *(const float4*)&r16[4];
            float4 v2 = *(const float4*)&r16[8];
            float4 v3 = *(const float4*)&r16[12];
            float s = ((v0.x+v0.y)+(v0.z+v0.w)) + ((v1.x+v1.y)+(v1.z+v1.w))
                    + ((v2.x+v2.y)+(v2.z+v2.w)) + ((v3.x+v3.y)+(v3.z+v3.w)) + rbv;
            out_recon[(rowbase + tid) * 128 + l] = s;
            if (l == L_ - 1) {
                const float* q16 = &red2[tid * 16];
                float4 u0 = *(const float4*)&q16[0];
                float4 u1 = *(const float4*)&q16[4];
                float4 u2 = *(const float4*)&q16[8];
                float4 u3 = *(const float4*)&q16[12];
                float p2 = ((u0.x+u0.y)+(u0.z+u0.w)) + ((u1.x+u1.y)+(u1.z+u1.w))
                         + ((u2.x+u2.y)+(u2.z+u2.w)) + ((u3.x+u3.y)+(u3.z+u3.w)) + pbv;
                out_pred[rowbase + tid] = p2;
            }
        }
    }
}

// ---------------------------------------------------------------------------
extern "C" void kernel_launch(void* const* d_in, const int* in_sizes, int n_in,
                              void* d_out, int out_size) {
    const float* x        = (const float*)d_in[0];
    const float* enc_Wih  = (const float*)d_in[1];
    const float* enc_Whh  = (const float*)d_in[2];
    const float* enc_bih  = (const float*)d_in[3];
    const float* enc_bhh  = (const float*)d_in[4];
    const float* pool_w   = (const float*)d_in[5];
    const float* pool_b   = (const float*)d_in[6];
    const float* Wq       = (const float*)d_in[7];
    const float* bq       = (const float*)d_in[8];
    const float* Wk       = (const float*)d_in[9];
    const float* bk       = (const float*)d_in[10];
    const float* Wv       = (const float*)d_in[11];
    const float* bv       = (const float*)d_in[12];
    const float* dec_Wih  = (const float*)d_in[13];
    const float* dec_Whh  = (const float*)d_in[14];
    const float* dec_bih  = (const float*)d_in[15];
    const float* dec_bhh  = (const float*)d_in[16];
    const float* rec_w    = (const float*)d_in[17];
    const float* rec_b    = (const float*)d_in[18];
    const float* pred_w   = (const float*)d_in[19];
    const float* pred_b   = (const float*)d_in[20];

    float* out = (float*)d_out;
    float* out_recon = out;
    float* out_pred  = out + 262144;
    float* out_cstar = out + 264192;
    float* out_A     = out + 526336;

    cudaFuncSetAttribute(encoder_kernel, cudaFuncAttributeMaxDynamicSharedMemorySize, ENC_SMEM);
    cudaFuncSetAttribute(decoder_kernel, cudaFuncAttributeMaxDynamicSharedMemorySize, DEC_SMEM);
    cudaFuncSetAttribute(attn2_kernel,   cudaFuncAttributeMaxDynamicSharedMemorySize, ATT_SMEM);

    pack_kernel<<<64, 256>>>(enc_Whh, dec_Whh, dec_Wih, Wq, Wk, Wv);
    encoder_kernel<<<NCTA_, THR_, ENC_SMEM>>>(x, enc_Wih, enc_bih, enc_bhh, pool_w, pool_b);
    proj_kernel<<<256, 256>>>(bq, bk, bv);
    attn2_kernel<<<128, 256, ATT_SMEM>>>(out_cstar, out_A);
    decoder_kernel<<<NCTA_, THR_, DEC_SMEM>>>(dec_bih, dec_bhh, rec_w, rec_b,
                                              pred_w, pred_b, out_recon, out_pred);
}

// round 15
// speedup vs baseline: 10.4959x; 1.0201x over previous
#include <cuda_runtime.h>
#include <cuda_fp16.h>
#include <math.h>

// ---------------------------------------------------------------------------
// G_OracleAD: enc-LSTM(+attn pool) -> spatial attention -> dec-LSTM(+readouts)
// B=32 N=64 L=128 H=128  BN=2048  4H=512
// d_out (fp32): recon[262144] | pred[2048] | c_star[262144] | A[131072]
// R15 = R14 resubmitted (infra failure, no measurement):
//      proj fused into encoder epilogue (proj_kernel removed, g_c removed);
//      attn2 at 512 threads. LSTM mainloops unchanged from R13
//      (single-fp16 W, 1 MMA/tile, ownership-aligned warps, 1 bar/step).
// ---------------------------------------------------------------------------

#define BN_   2048
#define L_    128
#define H_    128
#define G4_   512
#define R_    16
#define NCTA_ (BN_ / R_)   // 128
#define THR_  512
#define GS_   516          // padded gsm row stride (floats)

// device scratch
__device__ uint2  g_encWF[16384];      // fp16x2 B-fragments (permuted cols)
__device__ uint2  g_decWF[16384];
__device__ float4 g_decWihP[32 * G4_];
__device__ float  g_WqT[H_ * H_];
__device__ float  g_WkT[H_ * H_];
__device__ float  g_WvT[H_ * H_];
__device__ float  g_cstar[BN_ * H_];
__device__ float  g_q[BN_ * H_];       // Q rows [bn][d]
__device__ float  g_v[BN_ * H_];       // V rows [bn][d]
__device__ float  g_kT[32 * H_ * 64];  // K transposed [b][d][n]

__device__ __forceinline__ int colorig_(int c) { return (c & 3) * 128 + (c >> 2); }

__device__ __forceinline__ float tanh_(float x) {
    float y;
    asm("tanh.approx.f32 %0, %1;" : "=f"(y) : "f"(x));
    return y;
}
__device__ __forceinline__ float sig_(float x) {
    return fmaf(tanh_(0.5f * x), 0.5f, 0.5f);
}
__device__ __forceinline__ void mma16816h(float* c, unsigned a0, unsigned a1,
                                          unsigned a2, unsigned a3,
                                          unsigned b0, unsigned b1) {
    asm("mma.sync.aligned.m16n8k16.row.col.f32.f16.f16.f32 "
        "{%0,%1,%2,%3}, {%4,%5,%6,%7}, {%8,%9}, {%0,%1,%2,%3};"
        : "+f"(c[0]), "+f"(c[1]), "+f"(c[2]), "+f"(c[3])
        : "r"(a0), "r"(a1), "r"(a2), "r"(a3), "r"(b0), "r"(b1));
}
__device__ __forceinline__ unsigned short f2h_(float w) {
    __half b = __float2half_rn(w);
    return *reinterpret_cast<unsigned short*>(&b);
}
__device__ __forceinline__ int fragidx_(int r, int j) {
    int kt = j >> 4, kl = j & 15;
    int lane_w = ((r & 7) << 2) | ((kl >> 1) & 3);
    int reg    = ((kl >> 3) << 1) | (r >> 3);
    return (((kt * 32 + lane_w) * 4 + reg) << 1) | (kl & 1);
}

// ---------------------------------------------------------------------------
__global__ void pack_kernel(const float* __restrict__ encWhh,
                            const float* __restrict__ decWhh,
                            const float* __restrict__ decWih,
                            const float* __restrict__ Wq,
                            const float* __restrict__ Wk,
                            const float* __restrict__ Wv) {
    int idx = blockIdx.x * blockDim.x + threadIdx.x;   // 0..16383
    {
        int kb = idx >> 9, c = idx & 511;
        int orig = (c & 3) * 128 + (c >> 2);
        int s  = orig * 128 + kb * 4;
        g_decWihP[idx] = make_float4(decWih[s], decWih[s+1], decWih[s+2], decWih[s+3]);
    }
    {
        int nt = idx >> 8, kt = (idx >> 5) & 7, l = idx & 31;
        int c  = nt * 8 + (l >> 2);
        int n  = (c & 3) * 128 + (c >> 2);
        int k0 = kt * 16 + (l & 3) * 2;
        unsigned short h0 = f2h_(encWhh[n * 128 + k0]);
        unsigned short h1 = f2h_(encWhh[n * 128 + k0 + 1]);
        unsigned short h2 = f2h_(encWhh[n * 128 + k0 + 8]);
        unsigned short h3 = f2h_(encWhh[n * 128 + k0 + 9]);
        g_encWF[idx] = make_uint2((unsigned)h0 | ((unsigned)h1 << 16),
                                  (unsigned)h2 | ((unsigned)h3 << 16));
        h0 = f2h_(decWhh[n * 128 + k0]);
        h1 = f2h_(decWhh[n * 128 + k0 + 1]);
        h2 = f2h_(decWhh[n * 128 + k0 + 8]);
        h3 = f2h_(decWhh[n * 128 + k0 + 9]);
        g_decWF[idx] = make_uint2((unsigned)h0 | ((unsigned)h1 << 16),
                                  (unsigned)h2 | ((unsigned)h3 << 16));
    }
    {
        int kk = idx >> 7, d = idx & 127;
        g_WqT[idx] = Wq[d * 128 + kk];
        g_WkT[idx] = Wk[d * 128 + kk];
        g_WvT[idx] = Wv[d * 128 + kk];
    }
}

// ---------------------------------------------------------------------------
// Encoder: tensor-core LSTM + fused online-softmax pool + fused QKV proj.
// smem f-words: gsm 8256 | xs 2112 | red 512 | abuf 2048
// ---------------------------------------------------------------------------
#define ENC_SMEM ((8256 + 2112 + 512 + 2048) * 4)

__global__ __launch_bounds__(THR_, 1)
void encoder_kernel(const float* __restrict__ x,
                    const float* __restrict__ enc_Wih,
                    const float* __restrict__ enc_bih,
                    const float* __restrict__ enc_bhh,
                    const float* __restrict__ pool_w,
                    const float* __restrict__ pool_b,
                    const float* __restrict__ bq,
                    const float* __restrict__ bk,
                    const float* __restrict__ bv) {
    extern __shared__ float smf[];
    float*    gsm  = smf;                      // [16][516]
    float*    xs   = gsm + 8256;               // [16][132]
    float*    red  = xs + 2112;                // [2][16][16]
    unsigned* abuf = (unsigned*)(red + 512);   // [2][1024] u32 (fp16 A frags)

    const int tid = threadIdx.x;
    const int w   = tid >> 5, lane = tid & 31;
    const int rowbase = blockIdx.x * R_;

    for (int i = tid; i < 2048;  i += THR_) abuf[i] = 0u;
    for (int i = tid; i < R_ * 128; i += THR_)
        xs[(i >> 7) * 132 + (i & 127)] = x[rowbase * 128 + i];

    uint2 whi[4][8];
    #pragma unroll
    for (int a = 0; a < 4; a++)
        #pragma unroll
        for (int kt = 0; kt < 8; kt++)
            whi[a][kt] = g_encWF[((w * 4 + a) * 8 + kt) * 32 + lane];

    const int row0 = lane >> 2;
    const int colq = (lane & 3) * 2;
    float wihr[8], btr[8];
    #pragma unroll
    for (int a = 0; a < 4; a++)
        #pragma unroll
        for (int hh = 0; hh < 2; hh++) {
            int col  = (w * 4 + a) * 8 + colq + hh;
            int orig = colorig_(col);
            wihr[a * 2 + hh] = enc_Wih[orig];
            btr[a * 2 + hh]  = enc_bih[orig] + enc_bhh[orig];
        }

    const int rr = lane & 15;
    const int j0 = w * 8 + (lane >> 4) * 4;
    const float pb = pool_b[0];
    float pw[4];
    int   idxf[4];
    #pragma unroll
    for (int m = 0; m < 4; m++) {
        pw[m]   = pool_w[j0 + m];
        idxf[m] = fragidx_(rr, j0 + m);
    }
    unsigned short* ab16 = (unsigned short*)abuf;

    float cst[4]  = {0.f, 0.f, 0.f, 0.f};
    float accj[4] = {0.f, 0.f, 0.f, 0.f};
    float msx = -INFINITY, zsx = 0.f;

    __syncthreads();

    for (int l = 0; l < L_; l++) {
        const int rp = l & 1;
        const int rbase = rp * 1024;        // u32
        const int wbase = (rp ^ 1) * 2048;  // shorts

        // ---- phase 1: gates on tensor cores (1 MMA/tile) ----
        float acc[4][4];
        float xr0 = xs[row0 * 132 + l];
        float xr8 = xs[(row0 + 8) * 132 + l];
        #pragma unroll
        for (int a = 0; a < 4; a++) {
            acc[a][0] = fmaf(xr0, wihr[a*2],   btr[a*2]);
            acc[a][1] = fmaf(xr0, wihr[a*2+1], btr[a*2+1]);
            acc[a][2] = fmaf(xr8, wihr[a*2],   btr[a*2]);
            acc[a][3] = fmaf(xr8, wihr[a*2+1], btr[a*2+1]);
        }
        #pragma unroll
        for (int kt = 0; kt < 8; kt++) {
            uint4 ah = *(const uint4*)&abuf[rbase + (kt * 32 + lane) * 4];
            #pragma unroll
            for (int a = 0; a < 4; a++)
                mma16816h(acc[a], ah.x, ah.y, ah.z, ah.w, whi[a][kt].x, whi[a][kt].y);
        }
        #pragma unroll
        for (int a = 0; a < 4; a++) {
            int cb = (w * 4 + a) * 8 + colq;
            *(float2*)&gsm[row0 * GS_ + cb]       = make_float2(acc[a][0], acc[a][1]);
            *(float2*)&gsm[(row0 + 8) * GS_ + cb] = make_float2(acc[a][2], acc[a][3]);
        }
        __syncwarp();

        // ---- phase 2: cell + fp16 h -> abuf[rp^1] + pool partial ----
        float hv[4], partial = 0.f;
        #pragma unroll
        for (int m = 0; m < 4; m++) {
            float4 g4 = *(const float4*)&gsm[rr * GS_ + 4 * (j0 + m)];  // i,f,g,o
            float si = sig_(g4.x), sf = sig_(g4.y), so = sig_(g4.w);
            float tg = tanh_(g4.z);
            cst[m] = fmaf(sf, cst[m], si * tg);
            float h = so * tanh_(cst[m]);
            hv[m] = h;
            ab16[wbase + idxf[m]] = f2h_(h);
            partial = fmaf(h, pw[m], partial);
        }
        partial += __shfl_xor_sync(0xffffffffu, partial, 16);
        if (lane < 16) red[rp * 256 + rr * 16 + w] = partial;
        __syncthreads();

        // ---- phase 3: replicated online softmax ----
        {
            const float* rr16 = &red[rp * 256 + rr * 16];
            float4 v0 = *(const float4*)&rr16[0];
            float4 v1 = *(const float4*)&rr16[4];
            float4 v2 = *(const float4*)&rr16[8];
            float4 v3 = *(const float4*)&rr16[12];
            float s = ((v0.x+v0.y)+(v0.z+v0.w)) + ((v1.x+v1.y)+(v1.z+v1.w))
                    + ((v2.x+v2.y)+(v2.z+v2.w)) + ((v3.x+v3.y)+(v3.z+v3.w)) + pb;
            float mn = fmaxf(msx, s);
            float f  = __expf(msx - mn);
            float wg = __expf(s - mn);
            zsx = zsx * f + wg;
            msx = mn;
            #pragma unroll
            for (int m = 0; m < 4; m++) accj[m] = fmaf(accj[m], f, wg * hv[m]);
        }
    }

    // ---- epilogue A: pooled context c -> smem (reuse gsm as c_s[16][128]) ----
    float* c_s = gsm;
    #pragma unroll
    for (int m = 0; m < 4; m++)
        c_s[rr * 128 + j0 + m] = __fdividef(accj[m], zsx);
    __syncthreads();

    // ---- epilogue B: fused QKV projection (thread = (row, d4)) ----
    {
        const int r  = tid >> 5;    // 0..15
        const int d4 = tid & 31;    // 0..31
        const float4* WqT4 = reinterpret_cast<const float4*>(g_WqT);
        const float4* WkT4 = reinterpret_cast<const float4*>(g_WkT);
        const float4* WvT4 = reinterpret_cast<const float4*>(g_WvT);
        const float* bq4 = bq + d4 * 4;
        const float* bk4 = bk + d4 * 4;
        const float* bv4 = bv + d4 * 4;
        float4 aq = make_float4(bq4[0], bq4[1], bq4[2], bq4[3]);
        float4 ak = make_float4(bk4[0], bk4[1], bk4[2], bk4[3]);
        float4 av = make_float4(bv4[0], bv4[1], bv4[2], bv4[3]);
        const float* cr = &c_s[r * 128];
        #pragma unroll 4
        for (int kk = 0; kk < 128; kk++) {
            float cv = cr[kk];
            float4 wq = WqT4[kk * 32 + d4];
            float4 wk = WkT4[kk * 32 + d4];
            float4 wv = WvT4[kk * 32 + d4];
            aq.x = fmaf(cv, wq.x, aq.x); aq.y = fmaf(cv, wq.y, aq.y);
            aq.z = fmaf(cv, wq.z, aq.z); aq.w = fmaf(cv, wq.w, aq.w);
            ak.x = fmaf(cv, wk.x, ak.x); ak.y = fmaf(cv, wk.y, ak.y);
            ak.z = fmaf(cv, wk.z, ak.z); ak.w = fmaf(cv, wk.w, ak.w);
            av.x = fmaf(cv, wv.x, av.x); av.y = fmaf(cv, wv.y, av.y);
            av.z = fmaf(cv, wv.z, av.z); av.w = fmaf(cv, wv.w, av.w);
        }
        int bn = rowbase + r;
        *reinterpret_cast<float4*>(&g_q[bn * 128 + d4 * 4]) = aq;
        *reinterpret_cast<float4*>(&g_v[bn * 128 + d4 * 4]) = av;
        int b = bn >> 6, n = bn & 63;
        int dd = d4 * 4;
        g_kT[b * 8192 + (dd + 0) * 64 + n] = ak.x;
        g_kT[b * 8192 + (dd + 1) * 64 + n] = ak.y;
        g_kT[b * 8192 + (dd + 2) * 64 + n] = ak.z;
        g_kT[b * 8192 + (dd + 3) * 64 + n] = ak.w;
    }
}

// ---------------------------------------------------------------------------
// attn2_kernel: scores + softmax + A@V. grid 128 (4 Q-tiles x 32 b), 512 thr.
// smem f-words: q_s 2048 | kTS 8192 | v_s 8192 | sc 1024
// ---------------------------------------------------------------------------
#define ATT_SMEM ((2048 + 8192 + 8192 + 1024) * 4)
#define ATHR_ 512

__global__ __launch_bounds__(ATHR_, 1)
void attn2_kernel(float* __restrict__ out_cstar, float* __restrict__ out_A) {
    extern __shared__ float sm[];
    float* q_s = sm;              // [16][128]
    float* kTS = q_s + 2048;      // [128][64]
    float* v_s = kTS + 8192;      // [64][128]
    float* sc  = v_s + 8192;      // [16][64]
    const int b  = blockIdx.x >> 2;
    const int n0 = (blockIdx.x & 3) * 16;
    const int tid = threadIdx.x;

    {
        const float4* q4 = reinterpret_cast<const float4*>(g_q + b * 8192 + n0 * 128);
        const float4* k4 = reinterpret_cast<const float4*>(g_kT + b * 8192);
        const float4* v4 = reinterpret_cast<const float4*>(g_v + b * 8192);
        for (int i = tid; i < 512;  i += ATHR_) *reinterpret_cast<float4*>(&q_s[i * 4]) = q4[i];
        for (int i = tid; i < 2048; i += ATHR_) *reinterpret_cast<float4*>(&kTS[i * 4]) = k4[i];
        for (int i = tid; i < 2048; i += ATHR_) *reinterpret_cast<float4*>(&v_s[i * 4]) = v4[i];
    }
    __syncthreads();

    const float scale = 0.08838834764831845f;   // 1/sqrt(128)
    for (int o = tid; o < 1024; o += ATHR_) {
        int n = o >> 6, m = o & 63;
        float s = 0.f;
        const float* qr = &q_s[n * 128];
        #pragma unroll 8
        for (int d = 0; d < 128; d++) s = fmaf(qr[d], kTS[d * 64 + m], s);
        sc[o] = s * scale;
    }
    __syncthreads();

    const int warp = tid >> 5, lane = tid & 31;
    if (warp < 16) {
        int n = warp;
        float v0 = sc[n * 64 + lane], v1 = sc[n * 64 + 32 + lane];
        float mx = fmaxf(v0, v1);
        #pragma unroll
        for (int o = 16; o; o >>= 1) mx = fmaxf(mx, __shfl_xor_sync(0xffffffffu, mx, o));
        float e0 = __expf(v0 - mx), e1 = __expf(v1 - mx);
        float ss = e0 + e1;
        #pragma unroll
        for (int o = 16; o; o >>= 1) ss += __shfl_xor_sync(0xffffffffu, ss, o);
        float inv = 1.f / ss;
        float a0 = e0 * inv, a1 = e1 * inv;
        sc[n * 64 + lane] = a0;
        sc[n * 64 + 32 + lane] = a1;
        out_A[b * 4096 + (n0 + n) * 64 + lane] = a0;
        out_A[b * 4096 + (n0 + n) * 64 + 32 + lane] = a1;
    }
    __syncthreads();

    for (int o = tid; o < 2048; o += ATHR_) {
        int n = o >> 7, d = o & 127;
        float s = 0.f;
        const float* ar = &sc[n * 64];
        #pragma unroll 8
        for (int m = 0; m < 64; m++) s = fmaf(ar[m], v_s[m * 128 + d], s);
        out_cstar[b * 8192 + (n0 + n) * 128 + d] = s;
        g_cstar[b * 8192 + (n0 + n) * 128 + d]   = s;
    }
}

// ---------------------------------------------------------------------------
// Decoder: tensor-core LSTM + fused readouts; ONE bar/step; dpr in regs.
// smem f-words: gsm 8256 | cs 2048 | red 512 | red2 256 | abuf 2048
// ---------------------------------------------------------------------------
#define DEC_SMEM ((8256 + 2048 + 512 + 256 + 2048) * 4)

__global__ __launch_bounds__(THR_, 1)
void decoder_kernel(const float* __restrict__ dec_bih,
                    const float* __restrict__ dec_bhh,
                    const float* __restrict__ rec_w,  const float* __restrict__ rec_b,
                    const float* __restrict__ pred_w, const float* __restrict__ pred_b,
                    float* __restrict__ out_recon, float* __restrict__ out_pred) {
    extern __shared__ float smf[];
    float*    gsm  = smf;                      // [16][516]
    float*    cs   = gsm + 8256;               // [16][128]
    float*    red  = cs + 2048;                // [2][16][16]
    float*    red2 = red + 512;                // [16][16]
    unsigned* abuf = (unsigned*)(red2 + 256);  // [2][1024] u32

    const int tid = threadIdx.x;
    const int w   = tid >> 5, lane = tid & 31;
    const int rowbase = blockIdx.x * R_;

    for (int i = tid; i < 2048;  i += THR_) abuf[i] = 0u;
    for (int i = tid; i < R_ * 128; i += THR_) cs[i] = g_cstar[rowbase * 128 + i];

    uint2 whi[4][8];
    #pragma unroll
    for (int a = 0; a < 4; a++)
        #pragma unroll
        for (int kt = 0; kt < 8; kt++)
            whi[a][kt] = g_decWF[((w * 4 + a) * 8 + kt) * 32 + lane];

    const int row0 = lane >> 2;
    const int colq = (lane & 3) * 2;

    const int rr = lane & 15;
    const int j0 = w * 8 + (lane >> 4) * 4;
    const float rbv = rec_b[0], pbv = pred_b[0];
    float rw[4], pw2[4];
    int   idxf[4];
    #pragma unroll
    for (int m = 0; m < 4; m++) {
        rw[m]   = rec_w[j0 + m];
        pw2[m]  = pred_w[j0 + m];
        idxf[m] = fragidx_(rr, j0 + m);
    }
    unsigned short* ab16 = (unsigned short*)abuf;

    float cst[4] = {0.f, 0.f, 0.f, 0.f};
    __syncthreads();

    // ---- dpr GEMM (scalar, once): thread = permuted col tid; via gsm ----
    {
        const int orig = colorig_(tid);
        const float bt = dec_bih[orig] + dec_bhh[orig];
        float dpr[R_];
        #pragma unroll
        for (int r = 0; r < R_; r++) dpr[r] = bt;
        #pragma unroll 4
        for (int kb = 0; kb < 32; kb++) {
            float4 wv = g_decWihP[kb * G4_ + tid];
            #pragma unroll
            for (int r = 0; r < R_; r++) {
                float4 h4 = *reinterpret_cast<const float4*>(&cs[r * 128 + kb * 4]);
                dpr[r] = fmaf(wv.x, h4.x, dpr[r]);
                dpr[r] = fmaf(wv.y, h4.y, dpr[r]);
                dpr[r] = fmaf(wv.z, h4.z, dpr[r]);
                dpr[r] = fmaf(wv.w, h4.w, dpr[r]);
            }
        }
        #pragma unroll
        for (int r = 0; r < R_; r++) gsm[r * GS_ + tid] = dpr[r];
    }
    __syncwarp();

    float dfrag[4][4];
    #pragma unroll
    for (int a = 0; a < 4; a++) {
        int cb = (w * 4 + a) * 8 + colq;
        float2 d0 = *(const float2*)&gsm[row0 * GS_ + cb];
        float2 d8 = *(const float2*)&gsm[(row0 + 8) * GS_ + cb];
        dfrag[a][0] = d0.x; dfrag[a][1] = d0.y;
        dfrag[a][2] = d8.x; dfrag[a][3] = d8.y;
    }
    __syncwarp();

    for (int l = 0; l < L_; l++) {
        const int rp = l & 1;
        const int rbase = rp * 1024;
        const int wbase = (rp ^ 1) * 2048;

        // ---- phase 1: gates on tensor cores (1 MMA/tile) ----
        float acc[4][4];
        #pragma unroll
        for (int a = 0; a < 4; a++)
            #pragma unroll
            for (int q = 0; q < 4; q++) acc[a][q] = dfrag[a][q];
        #pragma unroll
        for (int kt = 0; kt < 8; kt++) {
            uint4 ah = *(const uint4*)&abuf[rbase + (kt * 32 + lane) * 4];
            #pragma unroll
            for (int a = 0; a < 4; a++)
                mma16816h(acc[a], ah.x, ah.y, ah.z, ah.w, whi[a][kt].x, whi[a][kt].y);
        }
        #pragma unroll
        for (int a = 0; a < 4; a++) {
            int cb = (w * 4 + a) * 8 + colq;
            *(float2*)&gsm[row0 * GS_ + cb]       = make_float2(acc[a][0], acc[a][1]);
            *(float2*)&gsm[(row0 + 8) * GS_ + cb] = make_float2(acc[a][2], acc[a][3]);
        }
        __syncwarp();

        // ---- phase 2: cell + fp16 h + readout partials ----
        float partial = 0.f, partial2 = 0.f;
        #pragma unroll
        for (int m = 0; m < 4; m++) {
            float4 g4 = *(const float4*)&gsm[rr * GS_ + 4 * (j0 + m)];
            float si = sig_(g4.x), sf = sig_(g4.y), so = sig_(g4.w);
            float tg = tanh_(g4.z);
            cst[m] = fmaf(sf, cst[m], si * tg);
            float h = so * tanh_(cst[m]);
            ab16[wbase + idxf[m]] = f2h_(h);
            partial = fmaf(h, rw[m], partial);
            if (l == L_ - 1) partial2 = fmaf(h, pw2[m], partial2);
        }
        partial += __shfl_xor_sync(0xffffffffu, partial, 16);
        if (lane < 16) red[rp * 256 + rr * 16 + w] = partial;
        if (l == L_ - 1) {
            partial2 += __shfl_xor_sync(0xffffffffu, partial2, 16);
            if (lane < 16) red2[rr * 16 + w] = partial2;
        }
        __syncthreads();

        // ---- phase 3: leaders write recon (and pred last step) ----
        if (tid < 16) {
            const float* r16 = &red[rp * 256 + tid * 16];
            float4 v0 = *(const float4*)&r16[0];
            float4 v1 = *(const float4*)&r16[4];
            float4 v2 = *(const float4*)&r16[8];
            float4 v3 = *(const float4*)&r16[12];
            float s = ((v0.x+v0.y)+(v0.z+v0.w)) + ((v1.x+v1.y)+(v1.z+v1.w))
                    + ((v2.x+v2.y)+(v2.z+v2.w)) + ((v3.x+v3.y)+(v3.z+v3.w)) + rbv;
            out_recon[(rowbase + tid) * 128 + l] = s;
            if (l == L_ - 1) {
                const float* q16 = &red2[tid * 16];
                float4 u0 = *(const float4*)&q16[0];
                float4 u1 = *(const float4*)&q16[4];
                float4 u2 = *(const float4*)&q16[8];
                float4 u3 = *(const float4*)&q16[12];
                float p2 = ((u0.x+u0.y)+(u0.z+u0.w)) + ((u1.x+u1.y)+(u1.z+u1.w))
                         + ((u2.x+u2.y)+(u2.z+u2.w)) + ((u3.x+u3.y)+(u3.z+u3.w)) + pbv;
                out_pred[rowbase + tid] = p2;
            }
        }
    }
}

// ---------------------------------------------------------------------------
extern "C" void kernel_launch(void* const* d_in, const int* in_sizes, int n_in,
                              void* d_out, int out_size) {
    const float* x        = (const float*)d_in[0];
    const float* enc_Wih  = (const float*)d_in[1];
    const float* enc_Whh  = (const float*)d_in[2];
    const float* enc_bih  = (const float*)d_in[3];
    const float* enc_bhh  = (const float*)d_in[4];
    const float* pool_w   = (const float*)d_in[5];
    const float* pool_b   = (const float*)d_in[6];
    const float* Wq       = (const float*)d_in[7];
    const float* bq       = (const float*)d_in[8];
    const float* Wk       = (const float*)d_in[9];
    const float* bk       = (const float*)d_in[10];
    const float* Wv       = (const float*)d_in[11];
    const float* bv       = (const float*)d_in[12];
    const float* dec_Wih  = (const float*)d_in[13];
    const float* dec_Whh  = (const float*)d_in[14];
    const float* dec_bih  = (const float*)d_in[15];
    const float* dec_bhh  = (const float*)d_in[16];
    const float* rec_w    = (const float*)d_in[17];
    const float* rec_b    = (const float*)d_in[18];
    const float* pred_w   = (const float*)d_in[19];
    const float* pred_b   = (const float*)d_in[20];

    float* out = (float*)d_out;
    float* out_recon = out;
    float* out_pred  = out + 262144;
    float* out_cstar = out + 264192;
    float* out_A     = out + 526336;

    cudaFuncSetAttribute(encoder_kernel, cudaFuncAttributeMaxDynamicSharedMemorySize, ENC_SMEM);
    cudaFuncSetAttribute(decoder_kernel, cudaFuncAttributeMaxDynamicSharedMemorySize, DEC_SMEM);
    cudaFuncSetAttribute(attn2_kernel,   cudaFuncAttributeMaxDynamicSharedMemorySize, ATT_SMEM);

    pack_kernel<<<64, 256>>>(enc_Whh, dec_Whh, dec_Wih, Wq, Wk, Wv);
    encoder_kernel<<<NCTA_, THR_, ENC_SMEM>>>(x, enc_Wih, enc_bih, enc_bhh,
                                              pool_w, pool_b, bq, bk, bv);
    attn2_kernel<<<128, ATHR_, ATT_SMEM>>>(out_cstar, out_A);
    decoder_kernel<<<NCTA_, THR_, DEC_SMEM>>>(dec_bih, dec_bhh, rec_w, rec_b,
                                              pred_w, pred_b, out_recon, out_pred);
}

// round 16
// speedup vs baseline: 13.0444x; 1.2428x over previous
#include <cuda_runtime.h>
#include <cuda_fp16.h>
#include <math.h>

// ---------------------------------------------------------------------------
// G_OracleAD: enc-LSTM(+attn pool) -> spatial attention -> dec-LSTM(+readouts)
// B=32 N=64 L=128 H=128  BN=2048  4H=512
// d_out (fp32): recon[262144] | pred[2048] | c_star[262144] | A[131072]
// R16: cell-in-registers — gates consumed directly from MMA accumulators via
//      lane-pair shfl gather (no gsm STS/LDS round trip, no syncwarp).
//      Lane owns row rowl=(lane>>2)|((lane&1)<<3), units j_a=(w*4+a)*2+bit1.
//      Everything else as R15 (fused proj epilogue, single-fp16 W, 1 bar/step).
// ---------------------------------------------------------------------------

#define BN_   2048
#define L_    128
#define H_    128
#define G4_   512
#define R_    16
#define NCTA_ (BN_ / R_)   // 128
#define THR_  512
#define GS_   516          // padded gsm row stride (floats)

// device scratch
__device__ uint2  g_encWF[16384];      // fp16x2 B-fragments (permuted cols)
__device__ uint2  g_decWF[16384];
__device__ float4 g_decWihP[32 * G4_];
__device__ float  g_WqT[H_ * H_];
__device__ float  g_WkT[H_ * H_];
__device__ float  g_WvT[H_ * H_];
__device__ float  g_cstar[BN_ * H_];
__device__ float  g_q[BN_ * H_];       // Q rows [bn][d]
__device__ float  g_v[BN_ * H_];       // V rows [bn][d]
__device__ float  g_kT[32 * H_ * 64];  // K transposed [b][d][n]

__device__ __forceinline__ int colorig_(int c) { return (c & 3) * 128 + (c >> 2); }

__device__ __forceinline__ float tanh_(float x) {
    float y;
    asm("tanh.approx.f32 %0, %1;" : "=f"(y) : "f"(x));
    return y;
}
__device__ __forceinline__ float sig_(float x) {
    return fmaf(tanh_(0.5f * x), 0.5f, 0.5f);
}
__device__ __forceinline__ void mma16816h(float* c, unsigned a0, unsigned a1,
                                          unsigned a2, unsigned a3,
                                          unsigned b0, unsigned b1) {
    asm("mma.sync.aligned.m16n8k16.row.col.f32.f16.f16.f32 "
        "{%0,%1,%2,%3}, {%4,%5,%6,%7}, {%8,%9}, {%0,%1,%2,%3};"
        : "+f"(c[0]), "+f"(c[1]), "+f"(c[2]), "+f"(c[3])
        : "r"(a0), "r"(a1), "r"(a2), "r"(a3), "r"(b0), "r"(b1));
}
__device__ __forceinline__ unsigned short f2h_(float w) {
    __half b = __float2half_rn(w);
    return *reinterpret_cast<unsigned short*>(&b);
}
__device__ __forceinline__ int fragidx_(int r, int j) {
    int kt = j >> 4, kl = j & 15;
    int lane_w = ((r & 7) << 2) | ((kl >> 1) & 3);
    int reg    = ((kl >> 3) << 1) | (r >> 3);
    return (((kt * 32 + lane_w) * 4 + reg) << 1) | (kl & 1);
}

// ---------------------------------------------------------------------------
__global__ void pack_kernel(const float* __restrict__ encWhh,
                            const float* __restrict__ decWhh,
                            const float* __restrict__ decWih,
                            const float* __restrict__ Wq,
                            const float* __restrict__ Wk,
                            const float* __restrict__ Wv) {
    int idx = blockIdx.x * blockDim.x + threadIdx.x;   // 0..16383
    {
        int kb = idx >> 9, c = idx & 511;
        int orig = (c & 3) * 128 + (c >> 2);
        int s  = orig * 128 + kb * 4;
        g_decWihP[idx] = make_float4(decWih[s], decWih[s+1], decWih[s+2], decWih[s+3]);
    }
    {
        int nt = idx >> 8, kt = (idx >> 5) & 7, l = idx & 31;
        int c  = nt * 8 + (l >> 2);
        int n  = (c & 3) * 128 + (c >> 2);
        int k0 = kt * 16 + (l & 3) * 2;
        unsigned short h0 = f2h_(encWhh[n * 128 + k0]);
        unsigned short h1 = f2h_(encWhh[n * 128 + k0 + 1]);
        unsigned short h2 = f2h_(encWhh[n * 128 + k0 + 8]);
        unsigned short h3 = f2h_(encWhh[n * 128 + k0 + 9]);
        g_encWF[idx] = make_uint2((unsigned)h0 | ((unsigned)h1 << 16),
                                  (unsigned)h2 | ((unsigned)h3 << 16));
        h0 = f2h_(decWhh[n * 128 + k0]);
        h1 = f2h_(decWhh[n * 128 + k0 + 1]);
        h2 = f2h_(decWhh[n * 128 + k0 + 8]);
        h3 = f2h_(decWhh[n * 128 + k0 + 9]);
        g_decWF[idx] = make_uint2((unsigned)h0 | ((unsigned)h1 << 16),
                                  (unsigned)h2 | ((unsigned)h3 << 16));
    }
    {
        int kk = idx >> 7, d = idx & 127;
        g_WqT[idx] = Wq[d * 128 + kk];
        g_WkT[idx] = Wk[d * 128 + kk];
        g_WvT[idx] = Wv[d * 128 + kk];
    }
}

// ---------------------------------------------------------------------------
// Encoder: tensor-core LSTM + fused online-softmax pool + fused QKV proj.
// smem f-words: gsm 8256 (epilogue c_s) | xs 2112 | red 512 | abuf 2048
// ---------------------------------------------------------------------------
#define ENC_SMEM ((8256 + 2112 + 512 + 2048) * 4)

__global__ __launch_bounds__(THR_, 1)
void encoder_kernel(const float* __restrict__ x,
                    const float* __restrict__ enc_Wih,
                    const float* __restrict__ enc_bih,
                    const float* __restrict__ enc_bhh,
                    const float* __restrict__ pool_w,
                    const float* __restrict__ pool_b,
                    const float* __restrict__ bq,
                    const float* __restrict__ bk,
                    const float* __restrict__ bv) {
    extern __shared__ float smf[];
    float*    gsm  = smf;                      // epilogue c_s
    float*    xs   = gsm + 8256;               // [16][132]
    float*    red  = xs + 2112;                // [2][16][16]
    unsigned* abuf = (unsigned*)(red + 512);   // [2][1024] u32 (fp16 A frags)

    const int tid = threadIdx.x;
    const int w   = tid >> 5, lane = tid & 31;
    const int rowbase = blockIdx.x * R_;

    for (int i = tid; i < 2048;  i += THR_) abuf[i] = 0u;
    for (int i = tid; i < R_ * 128; i += THR_)
        xs[(i >> 7) * 132 + (i & 127)] = x[rowbase * 128 + i];

    uint2 whi[4][8];
    #pragma unroll
    for (int a = 0; a < 4; a++)
        #pragma unroll
        for (int kt = 0; kt < 8; kt++)
            whi[a][kt] = g_encWF[((w * 4 + a) * 8 + kt) * 32 + lane];

    const int row0 = lane >> 2;
    const int colq = (lane & 3) * 2;
    float wihr[8], btr[8];
    #pragma unroll
    for (int a = 0; a < 4; a++)
        #pragma unroll
        for (int hh = 0; hh < 2; hh++) {
            int col  = (w * 4 + a) * 8 + colq + hh;
            int orig = colorig_(col);
            wihr[a * 2 + hh] = enc_Wih[orig];
            btr[a * 2 + hh]  = enc_bih[orig] + enc_bhh[orig];
        }

    // cell-in-registers mapping
    const bool qe   = (lane & 1) == 0;          // pair-even: holds (i,f)
    const int  rowl = (lane >> 2) | ((lane & 1) << 3);
    const float pb = pool_b[0];
    float pw[4];
    int   idxf[4], jg[4];
    #pragma unroll
    for (int a = 0; a < 4; a++) {
        jg[a]   = (w * 4 + a) * 2 + ((lane >> 1) & 1);
        pw[a]   = pool_w[jg[a]];
        idxf[a] = fragidx_(rowl, jg[a]);
    }
    unsigned short* ab16 = (unsigned short*)abuf;

    float cst[4]  = {0.f, 0.f, 0.f, 0.f};
    float accj[4] = {0.f, 0.f, 0.f, 0.f};
    float msx = -INFINITY, zsx = 0.f;

    __syncthreads();

    for (int l = 0; l < L_; l++) {
        const int rp = l & 1;
        const int rbase = rp * 1024;        // u32
        const int wbase = (rp ^ 1) * 2048;  // shorts

        // ---- phase 1: gates on tensor cores (1 MMA/tile) ----
        float acc[4][4];
        float xr0 = xs[row0 * 132 + l];
        float xr8 = xs[(row0 + 8) * 132 + l];
        #pragma unroll
        for (int a = 0; a < 4; a++) {
            acc[a][0] = fmaf(xr0, wihr[a*2],   btr[a*2]);
            acc[a][1] = fmaf(xr0, wihr[a*2+1], btr[a*2+1]);
            acc[a][2] = fmaf(xr8, wihr[a*2],   btr[a*2]);
            acc[a][3] = fmaf(xr8, wihr[a*2+1], btr[a*2+1]);
        }
        #pragma unroll
        for (int kt = 0; kt < 8; kt++) {
            uint4 ah = *(const uint4*)&abuf[rbase + (kt * 32 + lane) * 4];
            #pragma unroll
            for (int a = 0; a < 4; a++)
                mma16816h(acc[a], ah.x, ah.y, ah.z, ah.w, whi[a][kt].x, whi[a][kt].y);
        }

        // ---- phase 2: cell in registers (lane-pair shfl gather) ----
        float hv[4], partial = 0.f;
        #pragma unroll
        for (int a = 0; a < 4; a++) {
            float s0 = qe ? acc[a][2] : acc[a][0];
            float s1 = qe ? acc[a][3] : acc[a][1];
            float r0 = __shfl_xor_sync(0xffffffffu, s0, 1);
            float r1 = __shfl_xor_sync(0xffffffffu, s1, 1);
            float gi = qe ? acc[a][0] : r0;
            float gf = qe ? acc[a][1] : r1;
            float gg = qe ? r0 : acc[a][2];
            float go = qe ? r1 : acc[a][3];
            float si = sig_(gi), sf = sig_(gf), so = sig_(go);
            float tg = tanh_(gg);
            cst[a] = fmaf(sf, cst[a], si * tg);
            float h = so * tanh_(cst[a]);
            hv[a] = h;
            ab16[wbase + idxf[a]] = f2h_(h);
            partial = fmaf(h, pw[a], partial);
        }
        partial += __shfl_xor_sync(0xffffffffu, partial, 2);
        if ((lane & 2) == 0) red[rp * 256 + rowl * 16 + w] = partial;
        __syncthreads();

        // ---- phase 3: replicated online softmax (row = rowl) ----
        {
            const float* rr16 = &red[rp * 256 + rowl * 16];
            float4 v0 = *(const float4*)&rr16[0];
            float4 v1 = *(const float4*)&rr16[4];
            float4 v2 = *(const float4*)&rr16[8];
            float4 v3 = *(const float4*)&rr16[12];
            float s = ((v0.x+v0.y)+(v0.z+v0.w)) + ((v1.x+v1.y)+(v1.z+v1.w))
                    + ((v2.x+v2.y)+(v2.z+v2.w)) + ((v3.x+v3.y)+(v3.z+v3.w)) + pb;
            float mn = fmaxf(msx, s);
            float f  = __expf(msx - mn);
            float wg = __expf(s - mn);
            zsx = zsx * f + wg;
            msx = mn;
            #pragma unroll
            for (int a = 0; a < 4; a++) accj[a] = fmaf(accj[a], f, wg * hv[a]);
        }
    }

    // ---- epilogue A: pooled context c -> smem (reuse gsm as c_s[16][128]) ----
    float* c_s = gsm;
    #pragma unroll
    for (int a = 0; a < 4; a++)
        c_s[rowl * 128 + jg[a]] = __fdividef(accj[a], zsx);
    __syncthreads();

    // ---- epilogue B: fused QKV projection (thread = (row, d4)) ----
    {
        const int r  = tid >> 5;    // 0..15
        const int d4 = tid & 31;    // 0..31
        const float4* WqT4 = reinterpret_cast<const float4*>(g_WqT);
        const float4* WkT4 = reinterpret_cast<const float4*>(g_WkT);
        const float4* WvT4 = reinterpret_cast<const float4*>(g_WvT);
        const float* bq4 = bq + d4 * 4;
        const float* bk4 = bk + d4 * 4;
        const float* bv4 = bv + d4 * 4;
        float4 aq = make_float4(bq4[0], bq4[1], bq4[2], bq4[3]);
        float4 ak = make_float4(bk4[0], bk4[1], bk4[2], bk4[3]);
        float4 av = make_float4(bv4[0], bv4[1], bv4[2], bv4[3]);
        const float* cr = &c_s[r * 128];
        #pragma unroll 4
        for (int kk = 0; kk < 128; kk++) {
            float cv = cr[kk];
            float4 wq = WqT4[kk * 32 + d4];
            float4 wk = WkT4[kk * 32 + d4];
            float4 wv = WvT4[kk * 32 + d4];
            aq.x = fmaf(cv, wq.x, aq.x); aq.y = fmaf(cv, wq.y, aq.y);
            aq.z = fmaf(cv, wq.z, aq.z); aq.w = fmaf(cv, wq.w, aq.w);
            ak.x = fmaf(cv, wk.x, ak.x); ak.y = fmaf(cv, wk.y, ak.y);
            ak.z = fmaf(cv, wk.z, ak.z); ak.w = fmaf(cv, wk.w, ak.w);
            av.x = fmaf(cv, wv.x, av.x); av.y = fmaf(cv, wv.y, av.y);
            av.z = fmaf(cv, wv.z, av.z); av.w = fmaf(cv, wv.w, av.w);
        }
        int bn = rowbase + r;
        *reinterpret_cast<float4*>(&g_q[bn * 128 + d4 * 4]) = aq;
        *reinterpret_cast<float4*>(&g_v[bn * 128 + d4 * 4]) = av;
        int b = bn >> 6, n = bn & 63;
        int dd = d4 * 4;
        g_kT[b * 8192 + (dd + 0) * 64 + n] = ak.x;
        g_kT[b * 8192 + (dd + 1) * 64 + n] = ak.y;
        g_kT[b * 8192 + (dd + 2) * 64 + n] = ak.z;
        g_kT[b * 8192 + (dd + 3) * 64 + n] = ak.w;
    }
}

// ---------------------------------------------------------------------------
// attn2_kernel: scores + softmax + A@V. grid 128 (4 Q-tiles x 32 b), 512 thr.
// ---------------------------------------------------------------------------
#define ATT_SMEM ((2048 + 8192 + 8192 + 1024) * 4)
#define ATHR_ 512

__global__ __launch_bounds__(ATHR_, 1)
void attn2_kernel(float* __restrict__ out_cstar, float* __restrict__ out_A) {
    extern __shared__ float sm[];
    float* q_s = sm;              // [16][128]
    float* kTS = q_s + 2048;      // [128][64]
    float* v_s = kTS + 8192;      // [64][128]
    float* sc  = v_s + 8192;      // [16][64]
    const int b  = blockIdx.x >> 2;
    const int n0 = (blockIdx.x & 3) * 16;
    const int tid = threadIdx.x;

    {
        const float4* q4 = reinterpret_cast<const float4*>(g_q + b * 8192 + n0 * 128);
        const float4* k4 = reinterpret_cast<const float4*>(g_kT + b * 8192);
        const float4* v4 = reinterpret_cast<const float4*>(g_v + b * 8192);
        for (int i = tid; i < 512;  i += ATHR_) *reinterpret_cast<float4*>(&q_s[i * 4]) = q4[i];
        for (int i = tid; i < 2048; i += ATHR_) *reinterpret_cast<float4*>(&kTS[i * 4]) = k4[i];
        for (int i = tid; i < 2048; i += ATHR_) *reinterpret_cast<float4*>(&v_s[i * 4]) = v4[i];
    }
    __syncthreads();

    const float scale = 0.08838834764831845f;   // 1/sqrt(128)
    for (int o = tid; o < 1024; o += ATHR_) {
        int n = o >> 6, m = o & 63;
        float s = 0.f;
        const float* qr = &q_s[n * 128];
        #pragma unroll 8
        for (int d = 0; d < 128; d++) s = fmaf(qr[d], kTS[d * 64 + m], s);
        sc[o] = s * scale;
    }
    __syncthreads();

    const int warp = tid >> 5, lane = tid & 31;
    if (warp < 16) {
        int n = warp;
        float v0 = sc[n * 64 + lane], v1 = sc[n * 64 + 32 + lane];
        float mx = fmaxf(v0, v1);
        #pragma unroll
        for (int o = 16; o; o >>= 1) mx = fmaxf(mx, __shfl_xor_sync(0xffffffffu, mx, o));
        float e0 = __expf(v0 - mx), e1 = __expf(v1 - mx);
        float ss = e0 + e1;
        #pragma unroll
        for (int o = 16; o; o >>= 1) ss += __shfl_xor_sync(0xffffffffu, ss, o);
        float inv = 1.f / ss;
        float a0 = e0 * inv, a1 = e1 * inv;
        sc[n * 64 + lane] = a0;
        sc[n * 64 + 32 + lane] = a1;
        out_A[b * 4096 + (n0 + n) * 64 + lane] = a0;
        out_A[b * 4096 + (n0 + n) * 64 + 32 + lane] = a1;
    }
    __syncthreads();

    for (int o = tid; o < 2048; o += ATHR_) {
        int n = o >> 7, d = o & 127;
        float s = 0.f;
        const float* ar = &sc[n * 64];
        #pragma unroll 8
        for (int m = 0; m < 64; m++) s = fmaf(ar[m], v_s[m * 128 + d], s);
        out_cstar[b * 8192 + (n0 + n) * 128 + d] = s;
        g_cstar[b * 8192 + (n0 + n) * 128 + d]   = s;
    }
}

// ---------------------------------------------------------------------------
// Decoder: tensor-core LSTM + fused readouts; cell-in-registers; 1 bar/step.
// smem f-words: gsm 8256 (dpr staging) | cs 2048 | red 512 | red2 256 | abuf 2048
// ---------------------------------------------------------------------------
#define DEC_SMEM ((8256 + 2048 + 512 + 256 + 2048) * 4)

__global__ __launch_bounds__(THR_, 1)
void decoder_kernel(const float* __restrict__ dec_bih,
                    const float* __restrict__ dec_bhh,
                    const float* __restrict__ rec_w,  const float* __restrict__ rec_b,
                    const float* __restrict__ pred_w, const float* __restrict__ pred_b,
                    float* __restrict__ out_recon, float* __restrict__ out_pred) {
    extern __shared__ float smf[];
    float*    gsm  = smf;                      // [16][516] (dpr staging only)
    float*    cs   = gsm + 8256;               // [16][128]
    float*    red  = cs + 2048;                // [2][16][16]
    float*    red2 = red + 512;                // [16][16]
    unsigned* abuf = (unsigned*)(red2 + 256);  // [2][1024] u32

    const int tid = threadIdx.x;
    const int w   = tid >> 5, lane = tid & 31;
    const int rowbase = blockIdx.x * R_;

    for (int i = tid; i < 2048;  i += THR_) abuf[i] = 0u;
    for (int i = tid; i < R_ * 128; i += THR_) cs[i] = g_cstar[rowbase * 128 + i];

    uint2 whi[4][8];
    #pragma unroll
    for (int a = 0; a < 4; a++)
        #pragma unroll
        for (int kt = 0; kt < 8; kt++)
            whi[a][kt] = g_decWF[((w * 4 + a) * 8 + kt) * 32 + lane];

    const int row0 = lane >> 2;
    const int colq = (lane & 3) * 2;

    // cell-in-registers mapping
    const bool qe   = (lane & 1) == 0;
    const int  rowl = (lane >> 2) | ((lane & 1) << 3);
    const float rbv = rec_b[0], pbv = pred_b[0];
    float rw[4], pw2[4];
    int   idxf[4];
    #pragma unroll
    for (int a = 0; a < 4; a++) {
        int jga = (w * 4 + a) * 2 + ((lane >> 1) & 1);
        rw[a]   = rec_w[jga];
        pw2[a]  = pred_w[jga];
        idxf[a] = fragidx_(rowl, jga);
    }
    unsigned short* ab16 = (unsigned short*)abuf;

    float cst[4] = {0.f, 0.f, 0.f, 0.f};
    __syncthreads();

    // ---- dpr GEMM (scalar, once): thread = permuted col tid; via gsm ----
    {
        const int orig = colorig_(tid);
        const float bt = dec_bih[orig] + dec_bhh[orig];
        float dpr[R_];
        #pragma unroll
        for (int r = 0; r < R_; r++) dpr[r] = bt;
        #pragma unroll 4
        for (int kb = 0; kb < 32; kb++) {
            float4 wv = g_decWihP[kb * G4_ + tid];
            #pragma unroll
            for (int r = 0; r < R_; r++) {
                float4 h4 = *reinterpret_cast<const float4*>(&cs[r * 128 + kb * 4]);
                dpr[r] = fmaf(wv.x, h4.x, dpr[r]);
                dpr[r] = fmaf(wv.y, h4.y, dpr[r]);
                dpr[r] = fmaf(wv.z, h4.z, dpr[r]);
                dpr[r] = fmaf(wv.w, h4.w, dpr[r]);
            }
        }
        #pragma unroll
        for (int r = 0; r < R_; r++) gsm[r * GS_ + tid] = dpr[r];
    }
    __syncwarp();

    float dfrag[4][4];
    #pragma unroll
    for (int a = 0; a < 4; a++) {
        int cb = (w * 4 + a) * 8 + colq;
        float2 d0 = *(const float2*)&gsm[row0 * GS_ + cb];
        float2 d8 = *(const float2*)&gsm[(row0 + 8) * GS_ + cb];
        dfrag[a][0] = d0.x; dfrag[a][1] = d0.y;
        dfrag[a][2] = d8.x; dfrag[a][3] = d8.y;
    }
    __syncwarp();

    for (int l = 0; l < L_; l++) {
        const int rp = l & 1;
        const int rbase = rp * 1024;
        const int wbase = (rp ^ 1) * 2048;

        // ---- phase 1: gates on tensor cores (1 MMA/tile) ----
        float acc[4][4];
        #pragma unroll
        for (int a = 0; a < 4; a++)
            #pragma unroll
            for (int q = 0; q < 4; q++) acc[a][q] = dfrag[a][q];
        #pragma unroll
        for (int kt = 0; kt < 8; kt++) {
            uint4 ah = *(const uint4*)&abuf[rbase + (kt * 32 + lane) * 4];
            #pragma unroll
            for (int a = 0; a < 4; a++)
                mma16816h(acc[a], ah.x, ah.y, ah.z, ah.w, whi[a][kt].x, whi[a][kt].y);
        }

        // ---- phase 2: cell in registers + readout partials ----
        float partial = 0.f, partial2 = 0.f;
        #pragma unroll
        for (int a = 0; a < 4; a++) {
            float s0 = qe ? acc[a][2] : acc[a][0];
            float s1 = qe ? acc[a][3] : acc[a][1];
            float r0 = __shfl_xor_sync(0xffffffffu, s0, 1);
            float r1 = __shfl_xor_sync(0xffffffffu, s1, 1);
            float gi = qe ? acc[a][0] : r0;
            float gf = qe ? acc[a][1] : r1;
            float gg = qe ? r0 : acc[a][2];
            float go = qe ? r1 : acc[a][3];
            float si = sig_(gi), sf = sig_(gf), so = sig_(go);
            float tg = tanh_(gg);
            cst[a] = fmaf(sf, cst[a], si * tg);
            float h = so * tanh_(cst[a]);
            ab16[wbase + idxf[a]] = f2h_(h);
            partial = fmaf(h, rw[a], partial);
            if (l == L_ - 1) partial2 = fmaf(h, pw2[a], partial2);
        }
        partial += __shfl_xor_sync(0xffffffffu, partial, 2);
        if ((lane & 2) == 0) red[rp * 256 + rowl * 16 + w] = partial;
        if (l == L_ - 1) {
            partial2 += __shfl_xor_sync(0xffffffffu, partial2, 2);
            if ((lane & 2) == 0) red2[rowl * 16 + w] = partial2;
        }
        __syncthreads();

        // ---- phase 3: leaders write recon (and pred last step) ----
        if (tid < 16) {
            const float* r16 = &red[rp * 256 + tid * 16];
            float4 v0 = *(const float4*)&r16[0];
            float4 v1 = *(const float4*)&r16[4];
            float4 v2 = *(const float4*)&r16[8];
            float4 v3 = *(const float4*)&r16[12];
            float s = ((v0.x+v0.y)+(v0.z+v0.w)) + ((v1.x+v1.y)+(v1.z+v1.w))
                    + ((v2.x+v2.y)+(v2.z+v2.w)) + ((v3.x+v3.y)+(v3.z+v3.w)) + rbv;
            out_recon[(rowbase + tid) * 128 + l] = s;
            if (l == L_ - 1) {
                const float* q16 = &red2[tid * 16];
                float4 u0 = *(const float4*)&q16[0];
                float4 u1 = *(const float4*)&q16[4];
                float4 u2 = *(const float4*)&q16[8];
                float4 u3 = *(const float4*)&q16[12];
                float p2 = ((u0.x+u0.y)+(u0.z+u0.w)) + ((u1.x+u1.y)+(u1.z+u1.w))
                         + ((u2.x+u2.y)+(u2.z+u2.w)) + ((u3.x+u3.y)+(u3.z+u3.w)) + pbv;
                out_pred[rowbase + tid] = p2;
            }
        }
    }
}

// ---------------------------------------------------------------------------
extern "C" void kernel_launch(void* const* d_in, const int* in_sizes, int n_in,
                              void* d_out, int out_size) {
    const float* x        = (const float*)d_in[0];
    const float* enc_Wih  = (const float*)d_in[1];
    const float* enc_Whh  = (const float*)d_in[2];
    const float* enc_bih  = (const float*)d_in[3];
    const float* enc_bhh  = (const float*)d_in[4];
    const float* pool_w   = (const float*)d_in[5];
    const float* pool_b   = (const float*)d_in[6];
    const float* Wq       = (const float*)d_in[7];
    const float* bq       = (const float*)d_in[8];
    const float* Wk       = (const float*)d_in[9];
    const float* bk       = (const float*)d_in[10];
    const float* Wv       = (const float*)d_in[11];
    const float* bv       = (const float*)d_in[12];
    const float* dec_Wih  = (const float*)d_in[13];
    const float* dec_Whh  = (const float*)d_in[14];
    const float* dec_bih  = (const float*)d_in[15];
    const float* dec_bhh  = (const float*)d_in[16];
    const float* rec_w    = (const float*)d_in[17];
    const float* rec_b    = (const float*)d_in[18];
    const float* pred_w   = (const float*)d_in[19];
    const float* pred_b   = (const float*)d_in[20];

    float* out = (float*)d_out;
    float* out_recon = out;
    float* out_pred  = out + 262144;
    float* out_cstar = out + 264192;
    float* out_A     = out + 526336;

    cudaFuncSetAttribute(encoder_kernel, cudaFuncAttributeMaxDynamicSharedMemorySize, ENC_SMEM);
    cudaFuncSetAttribute(decoder_kernel, cudaFuncAttributeMaxDynamicSharedMemorySize, DEC_SMEM);
    cudaFuncSetAttribute(attn2_kernel,   cudaFuncAttributeMaxDynamicSharedMemorySize, ATT_SMEM);

    pack_kernel<<<64, 256>>>(enc_Whh, dec_Whh, dec_Wih, Wq, Wk, Wv);
    encoder_kernel<<<NCTA_, THR_, ENC_SMEM>>>(x, enc_Wih, enc_bih, enc_bhh,
                                              pool_w, pool_b, bq, bk, bv);
    attn2_kernel<<<128, ATHR_, ATT_SMEM>>>(out_cstar, out_A);
    decoder_kernel<<<NCTA_, THR_, DEC_SMEM>>>(dec_bih, dec_bhh, rec_w, rec_b,
                                              pred_w, pred_b, out_recon, out_pred);
}